// round 2
// baseline (speedup 1.0000x reference)
#include <cuda_runtime.h>

// Problem constants (shapes fixed by the dataset)
#define NMAX 100000
#define EMAX 800000

// Scratch (no allocation allowed -> __device__ globals)
__device__ float g_xl[NMAX * 128];
__device__ float g_xr[NMAX * 128];
__device__ float g_h [NMAX * 64];
__device__ int   g_cnt[NMAX];
__device__ int   g_rowptr[NMAX + 1];
__device__ int   g_fill[NMAX];
__device__ int   g_adj[EMAX];
__device__ int   g_bsum[128];

// ---------------------------------------------------------------------------
// f32x2 packed-FMA helpers (FFMA2: only reachable via PTX on sm_103a)
// ---------------------------------------------------------------------------
__device__ __forceinline__ unsigned long long pk2(float a, float b) {
    unsigned long long r;
    asm("mov.b64 %0, {%1, %2};" : "=l"(r) : "f"(a), "f"(b));
    return r;
}
__device__ __forceinline__ void ffma2(unsigned long long& d, unsigned long long a,
                                      unsigned long long b) {
    asm("fma.rn.f32x2 %0, %1, %2, %0;" : "+l"(d) : "l"(a), "l"(b));
}
__device__ __forceinline__ float2 upk2(unsigned long long v) {
    float2 f;
    asm("mov.b64 {%0, %1}, %2;" : "=f"(f.x), "=f"(f.y) : "l"(v));
    return f;
}

// ---------------------------------------------------------------------------
// CSR build: histogram over dst, exclusive scan, scatter src
// ---------------------------------------------------------------------------
__global__ void k_zero(int N) {
    int i = blockIdx.x * blockDim.x + threadIdx.x;
    if (i < N) g_cnt[i] = 0;
}

__global__ void k_hist(const int* __restrict__ ei, int E) {
    for (int i = blockIdx.x * blockDim.x + threadIdx.x; i < E; i += gridDim.x * blockDim.x)
        atomicAdd(&g_cnt[ei[E + i]], 1);
}

__device__ __forceinline__ int block_scan_excl_1024(int val, int& total) {
    __shared__ int wsum[32];
    int lane = threadIdx.x & 31;
    int w    = threadIdx.x >> 5;
    int inc  = val;
#pragma unroll
    for (int o = 1; o < 32; o <<= 1) {
        int u = __shfl_up_sync(0xffffffffu, inc, o);
        if (lane >= o) inc += u;
    }
    if (lane == 31) wsum[w] = inc;
    __syncthreads();
    if (w == 0) {
        int v = wsum[lane];
#pragma unroll
        for (int o = 1; o < 32; o <<= 1) {
            int u = __shfl_up_sync(0xffffffffu, v, o);
            if (lane >= o) v += u;
        }
        wsum[lane] = v;
    }
    __syncthreads();
    int off = (w > 0) ? wsum[w - 1] : 0;
    total = wsum[31];
    return off + inc - val;  // exclusive
}

__global__ void k_scan1(int N) {
    int idx = blockIdx.x * 1024 + threadIdx.x;
    int val = (idx < N) ? g_cnt[idx] : 0;
    int total;
    int ex = block_scan_excl_1024(val, total);
    if (idx < N) g_rowptr[idx] = ex;
    if (threadIdx.x == 0) g_bsum[blockIdx.x] = total;
}

__global__ void k_scan2(int NB) {   // NB <= 128
    __shared__ int s[128];
    int t = threadIdx.x;
    s[t] = (t < NB) ? g_bsum[t] : 0;
    __syncthreads();
#pragma unroll
    for (int o = 1; o < 128; o <<= 1) {
        int v = (t >= o) ? s[t - o] : 0;
        __syncthreads();
        s[t] += v;
        __syncthreads();
    }
    if (t < NB) g_bsum[t] = (t > 0) ? s[t - 1] : 0;  // exclusive
}

__global__ void k_scan3(int N, int E) {
    int idx = blockIdx.x * 1024 + threadIdx.x;
    if (idx < N) {
        int r = g_rowptr[idx] + g_bsum[blockIdx.x];
        g_rowptr[idx] = r;
        g_fill[idx]   = r;
    }
    if (idx == 0) g_rowptr[N] = E;
}

__global__ void k_scatter(const int* __restrict__ ei, int E) {
    for (int i = blockIdx.x * blockDim.x + threadIdx.x; i < E; i += gridDim.x * blockDim.x) {
        int d = ei[E + i];
        int p = atomicAdd(&g_fill[d], 1);
        g_adj[p] = ei[i];
    }
}

// ---------------------------------------------------------------------------
// GEMM: Y = X(64-wide rows) @ W using packed f32x2 FMA over k-pairs.
// Lane j holds {x[2j], x[2j+1]} per row; SMEM weights pre-paired so that
// ulonglong2 loads deliver {w[2kp][c], w[2kp+1][c]} ready for FFMA2.
// Accumulators keep even/odd-k partials; merged at the end.
// DUAL computes two 64-col W's in one pass (TOT=128).
// ---------------------------------------------------------------------------
template <int OUTC, bool DUAL>
__global__ void __launch_bounds__(256) k_gemm(const float* __restrict__ X,
                                              const float* __restrict__ W0,
                                              const float* __restrict__ W1,
                                              float* __restrict__ Y0,
                                              float* __restrict__ Y1, int N) {
    constexpr int TOT = DUAL ? 2 * OUTC : OUTC;  // 128 in all uses
    constexpr int RPT = 8;
    // WsA[kp*32+lane] = {w[2kp][c0], w[2kp+1][c0], w[2kp][c0+1], w[2kp+1][c0+1]}, c0=lane*4
    // WsB same for c0+2, c0+3. [kp][lane] layout -> LDS.128 conflict-free.
    __shared__ float4 WsA[1024];
    __shared__ float4 WsB[1024];

    for (int i = threadIdx.x; i < 1024; i += blockDim.x) {
        int kp = i >> 5, ln = i & 31;
        int c0 = ln * 4;
        int k0 = 2 * kp, k1 = 2 * kp + 1;
        float w00, w01, w10, w11, w20, w21, w30, w31;
        if (DUAL) {
            auto f = [&](int k, int c) -> float {
                return (c < OUTC) ? W0[k * OUTC + c] : W1[k * OUTC + (c - OUTC)];
            };
            w00 = f(k0, c0);     w01 = f(k1, c0);
            w10 = f(k0, c0 + 1); w11 = f(k1, c0 + 1);
            w20 = f(k0, c0 + 2); w21 = f(k1, c0 + 2);
            w30 = f(k0, c0 + 3); w31 = f(k1, c0 + 3);
        } else {
            w00 = W0[k0 * TOT + c0];     w01 = W0[k1 * TOT + c0];
            w10 = W0[k0 * TOT + c0 + 1]; w11 = W0[k1 * TOT + c0 + 1];
            w20 = W0[k0 * TOT + c0 + 2]; w21 = W0[k1 * TOT + c0 + 2];
            w30 = W0[k0 * TOT + c0 + 3]; w31 = W0[k1 * TOT + c0 + 3];
        }
        WsA[i] = make_float4(w00, w01, w10, w11);
        WsB[i] = make_float4(w20, w21, w30, w31);
    }
    __syncthreads();

    const int lane = threadIdx.x & 31;
    const int wid  = threadIdx.x >> 5;
    const int nw   = blockDim.x >> 5;

    for (int base = (blockIdx.x * nw + wid) * RPT; base < N; base += gridDim.x * nw * RPT) {
        float2 x2[RPT];
#pragma unroll
        for (int r = 0; r < RPT; r++) {
            int row = base + r;
            x2[r] = (row < N) ? *(const float2*)&X[row * 64 + 2 * lane]
                              : make_float2(0.f, 0.f);
        }
        unsigned long long acc[RPT][4];
#pragma unroll
        for (int r = 0; r < RPT; r++)
#pragma unroll
            for (int j = 0; j < 4; j++) acc[r][j] = 0ull;

#pragma unroll 8
        for (int kp = 0; kp < 32; kp++) {
            ulonglong2 wa = ((const ulonglong2*)WsA)[kp * 32 + lane];
            ulonglong2 wb = ((const ulonglong2*)WsB)[kp * 32 + lane];
#pragma unroll
            for (int r = 0; r < RPT; r++) {
                float sx = __shfl_sync(0xffffffffu, x2[r].x, kp);
                float sy = __shfl_sync(0xffffffffu, x2[r].y, kp);
                unsigned long long xv = pk2(sx, sy);
                ffma2(acc[r][0], xv, wa.x);
                ffma2(acc[r][1], xv, wa.y);
                ffma2(acc[r][2], xv, wb.x);
                ffma2(acc[r][3], xv, wb.y);
            }
        }
#pragma unroll
        for (int r = 0; r < RPT; r++) {
            int row = base + r;
            if (row >= N) break;
            float2 p0 = upk2(acc[r][0]), p1 = upk2(acc[r][1]);
            float2 p2 = upk2(acc[r][2]), p3 = upk2(acc[r][3]);
            float4 o = make_float4(p0.x + p0.y, p1.x + p1.y, p2.x + p2.y, p3.x + p3.y);
            int c = lane * 4;
            if (DUAL) {
                if (c < OUTC) *(float4*)&Y0[row * OUTC + c] = o;
                else          *(float4*)&Y1[row * OUTC + (c - OUTC)] = o;
            } else {
                *(float4*)&Y0[row * TOT + c] = o;
            }
        }
    }
}

// ---------------------------------------------------------------------------
// Fused GATv2 edge phase: one warp per destination node, online softmax.
// Adjacency index prefetched one iteration ahead so the feature gather
// issues at loop top (hides L2 latency on the serial softmax chain).
// ---------------------------------------------------------------------------
__device__ __forceinline__ float leaky(float t) { return t > 0.f ? t : 0.2f * t; }

__global__ void k_edge64(const float* __restrict__ XL, const float* __restrict__ XR,
                         const float* __restrict__ att, const float* __restrict__ bias,
                         float* __restrict__ OUT, int N) {
    int lane = threadIdx.x & 31;
    int n    = (blockIdx.x * blockDim.x + threadIdx.x) >> 5;
    if (n >= N) return;

    float a0 = att[2 * lane], a1 = att[2 * lane + 1];
    float2 xr = *(const float2*)&XR[n * 64 + 2 * lane];
    float2 vs = *(const float2*)&XL[n * 64 + 2 * lane];

    // self edge
    float p = a0 * leaky(vs.x + xr.x) + a1 * leaky(vs.y + xr.y);
    p += __shfl_xor_sync(0xffffffffu, p, 4);
    p += __shfl_xor_sync(0xffffffffu, p, 2);
    p += __shfl_xor_sync(0xffffffffu, p, 1);
    float m = p, d = 1.f, ax = vs.x, ay = vs.y;

    int beg = g_rowptr[n], end = g_rowptr[n + 1];
    int s = (beg < end) ? g_adj[beg] : 0;
    for (int i = beg; i < end; i++) {
        float2 v = *(const float2*)&XL[s * 64 + 2 * lane];
        int sn = (i + 1 < end) ? g_adj[i + 1] : 0;
        p = a0 * leaky(v.x + xr.x) + a1 * leaky(v.y + xr.y);
        p += __shfl_xor_sync(0xffffffffu, p, 4);
        p += __shfl_xor_sync(0xffffffffu, p, 2);
        p += __shfl_xor_sync(0xffffffffu, p, 1);
        if (p <= m) {
            float w = __expf(p - m);
            ax += w * v.x; ay += w * v.y; d += w;
        } else {
            float sc = __expf(m - p);
            ax = ax * sc + v.x; ay = ay * sc + v.y; d = d * sc + 1.f;
            m = p;
        }
        s = sn;
    }
    float inv = 1.f / d;
    float ox = ax * inv + bias[2 * lane];
    float oy = ay * inv + bias[2 * lane + 1];
    ox = ox > 0.f ? ox : (__expf(ox) - 1.f);  // ELU
    oy = oy > 0.f ? oy : (__expf(oy) - 1.f);
    *(float2*)&OUT[n * 64 + 2 * lane] = make_float2(ox, oy);
}

// Layer 3: H=4, C=32 (128 feats, float4 per lane), mean over heads + bias
__global__ void k_edge128_mean(const float* __restrict__ XL, const float* __restrict__ XR,
                               const float* __restrict__ att, const float* __restrict__ bias,
                               float* __restrict__ OUT, int N) {
    int lane = threadIdx.x & 31;
    int n    = (blockIdx.x * blockDim.x + threadIdx.x) >> 5;
    if (n >= N) return;

    float4 a  = *(const float4*)&att[4 * lane];
    float4 xr = *(const float4*)&XR[n * 128 + 4 * lane];
    float4 vs = *(const float4*)&XL[n * 128 + 4 * lane];

    float p = a.x * leaky(vs.x + xr.x) + a.y * leaky(vs.y + xr.y) +
              a.z * leaky(vs.z + xr.z) + a.w * leaky(vs.w + xr.w);
    p += __shfl_xor_sync(0xffffffffu, p, 4);
    p += __shfl_xor_sync(0xffffffffu, p, 2);
    p += __shfl_xor_sync(0xffffffffu, p, 1);
    float m = p, d = 1.f;
    float4 acc = vs;

    int beg = g_rowptr[n], end = g_rowptr[n + 1];
    int s = (beg < end) ? g_adj[beg] : 0;
    for (int i = beg; i < end; i++) {
        float4 v = *(const float4*)&XL[s * 128 + 4 * lane];
        int sn = (i + 1 < end) ? g_adj[i + 1] : 0;
        p = a.x * leaky(v.x + xr.x) + a.y * leaky(v.y + xr.y) +
            a.z * leaky(v.z + xr.z) + a.w * leaky(v.w + xr.w);
        p += __shfl_xor_sync(0xffffffffu, p, 4);
        p += __shfl_xor_sync(0xffffffffu, p, 2);
        p += __shfl_xor_sync(0xffffffffu, p, 1);
        if (p <= m) {
            float w = __expf(p - m);
            acc.x += w * v.x; acc.y += w * v.y; acc.z += w * v.z; acc.w += w * v.w;
            d += w;
        } else {
            float sc = __expf(m - p);
            acc.x = acc.x * sc + v.x; acc.y = acc.y * sc + v.y;
            acc.z = acc.z * sc + v.z; acc.w = acc.w * sc + v.w;
            d = d * sc + 1.f;
            m = p;
        }
        s = sn;
    }
    float inv = 1.f / d;
    float o0 = acc.x * inv, o1 = acc.y * inv, o2 = acc.z * inv, o3 = acc.w * inv;
    // mean over 4 heads: sum lanes {l, l^8, l^16, l^24}
#pragma unroll
    for (int off = 8; off <= 16; off <<= 1) {
        o0 += __shfl_xor_sync(0xffffffffu, o0, off);
        o1 += __shfl_xor_sync(0xffffffffu, o1, off);
        o2 += __shfl_xor_sync(0xffffffffu, o2, off);
        o3 += __shfl_xor_sync(0xffffffffu, o3, off);
    }
    if (lane < 8) {
        int c = 4 * lane;
        float4 o = make_float4(0.25f * o0 + bias[c + 0],
                               0.25f * o1 + bias[c + 1],
                               0.25f * o2 + bias[c + 2],
                               0.25f * o3 + bias[c + 3]);
        *(float4*)&OUT[n * 32 + c] = o;
    }
}

// ---------------------------------------------------------------------------
// Launch
// ---------------------------------------------------------------------------
extern "C" void kernel_launch(void* const* d_in, const int* in_sizes, int n_in,
                              void* d_out, int out_size) {
    const float* x   = (const float*)d_in[0];
    const int*   ei  = (const int*)  d_in[1];
    const float* W1l = (const float*)d_in[2];
    const float* W1r = (const float*)d_in[3];
    const float* a1  = (const float*)d_in[4];
    const float* b1  = (const float*)d_in[5];
    const float* W2l = (const float*)d_in[6];
    const float* W2r = (const float*)d_in[7];
    const float* a2  = (const float*)d_in[8];
    const float* b2  = (const float*)d_in[9];
    const float* W3l = (const float*)d_in[10];
    const float* W3r = (const float*)d_in[11];
    const float* a3  = (const float*)d_in[12];
    const float* b3  = (const float*)d_in[13];
    float* out = (float*)d_out;

    const int N = in_sizes[0] / 64;
    const int E = in_sizes[1] / 2;
    const int NB = (N + 1023) / 1024;

    float *xl, *xr, *h;
    cudaGetSymbolAddress((void**)&xl, g_xl);
    cudaGetSymbolAddress((void**)&xr, g_xr);
    cudaGetSymbolAddress((void**)&h,  g_h);

    // CSR build (per replay: deterministic work)
    k_zero<<<(N + 255) / 256, 256>>>(N);
    k_hist<<<1024, 256>>>(ei, E);
    k_scan1<<<NB, 1024>>>(N);
    k_scan2<<<1, 128>>>(NB);
    k_scan3<<<NB, 1024>>>(N, E);
    k_scatter<<<1024, 256>>>(ei, E);

    const int GB = (N + 63) / 64;        // gemm: 8 warps * 8 rows per block
    const int EB = (N + 7) / 8;          // edge: 8 warps (nodes) per block

    // Layer 1
    k_gemm<64, true><<<GB, 256>>>(x, W1l, W1r, xl, xr, N);
    k_edge64<<<EB, 256>>>(xl, xr, a1, b1, h, N);
    // Layer 2
    k_gemm<64, true><<<GB, 256>>>(h, W2l, W2r, xl, xr, N);
    k_edge64<<<EB, 256>>>(xl, xr, a2, b2, h, N);
    // Layer 3
    k_gemm<128, false><<<GB, 256>>>(h, W3l, nullptr, xl, nullptr, N);
    k_gemm<128, false><<<GB, 256>>>(h, W3r, nullptr, xr, nullptr, N);
    k_edge128_mean<<<EB, 256>>>(xl, xr, a3, b3, out, N);
}

// round 4
// speedup vs baseline: 1.4122x; 1.4122x over previous
#include <cuda_runtime.h>
#include <cuda_bf16.h>
#include <cstdint>

// Problem constants
#define NMAX 100000
#define EMAX 800000

// Scratch (no allocation allowed -> __device__ globals)
__device__ float g_xl[NMAX * 128];
__device__ float g_xr[NMAX * 128];
__device__ float g_h [NMAX * 64];
__device__ int   g_cnt[NMAX];
__device__ int   g_rowptr[NMAX + 1];
__device__ int   g_fill[NMAX];
__device__ int   g_adj[EMAX];
__device__ int   g_bsum[128];
// bf16 [n=128][k=64] images (XOR-swizzled), 4 operand sets:
// 0: [W1l|W1r], 1: [W2l|W2r], 2: W3l, 3: W3r
__device__ __align__(16) unsigned char g_wimg_hi[4][16384];
__device__ __align__(16) unsigned char g_wimg_lo[4][16384];

// ---------------------------------------------------------------------------
// helpers
// ---------------------------------------------------------------------------
__device__ __forceinline__ uint32_t smem_u32(const void* p) {
    uint32_t a;
    asm("{ .reg .u64 t; cvta.to.shared.u64 t, %1; cvt.u32.u64 %0, t; }" : "=r"(a) : "l"(p));
    return a;
}
__device__ __forceinline__ void bf16_split(float v, uint16_t& hi, uint16_t& lo) {
    __nv_bfloat16 h = __float2bfloat16(v);
    float residual = v - __bfloat162float(h);
    __nv_bfloat16 l = __float2bfloat16(residual);
    hi = *(uint16_t*)&h;
    lo = *(uint16_t*)&l;
}
__device__ __forceinline__ void ldm_x4(uint32_t (&r)[4], uint32_t addr) {
    asm volatile("ldmatrix.sync.aligned.m8n8.x4.shared.b16 {%0,%1,%2,%3}, [%4];"
                 : "=r"(r[0]), "=r"(r[1]), "=r"(r[2]), "=r"(r[3]) : "r"(addr));
}
__device__ __forceinline__ void mma_bf16(float (&d)[4], const uint32_t (&a)[4],
                                         uint32_t b0, uint32_t b1) {
    asm volatile(
        "mma.sync.aligned.m16n8k16.row.col.f32.bf16.bf16.f32 "
        "{%0,%1,%2,%3}, {%4,%5,%6,%7}, {%8,%9}, {%0,%1,%2,%3};"
        : "+f"(d[0]), "+f"(d[1]), "+f"(d[2]), "+f"(d[3])
        : "r"(a[0]), "r"(a[1]), "r"(a[2]), "r"(a[3]), "r"(b0), "r"(b1));
}
// XOR swizzle inside a 128B row: chunk (16B) index XORed with (row&7)
__device__ __forceinline__ uint32_t swz_off(int row, int byte_in_row) {
    return (uint32_t)(row * 128 + (byte_in_row ^ ((row & 7) << 4)));
}

// ---------------------------------------------------------------------------
// CSR build
// ---------------------------------------------------------------------------
__global__ void k_zero(int N) {
    int i = blockIdx.x * blockDim.x + threadIdx.x;
    if (i < N) g_cnt[i] = 0;
}
__global__ void k_hist(const int* __restrict__ ei, int E) {
    for (int i = blockIdx.x * blockDim.x + threadIdx.x; i < E; i += gridDim.x * blockDim.x)
        atomicAdd(&g_cnt[ei[E + i]], 1);
}
__device__ __forceinline__ int block_scan_excl_1024(int val, int& total) {
    __shared__ int wsum[32];
    int lane = threadIdx.x & 31, w = threadIdx.x >> 5;
    int inc = val;
#pragma unroll
    for (int o = 1; o < 32; o <<= 1) {
        int u = __shfl_up_sync(0xffffffffu, inc, o);
        if (lane >= o) inc += u;
    }
    if (lane == 31) wsum[w] = inc;
    __syncthreads();
    if (w == 0) {
        int v = wsum[lane];
#pragma unroll
        for (int o = 1; o < 32; o <<= 1) {
            int u = __shfl_up_sync(0xffffffffu, v, o);
            if (lane >= o) v += u;
        }
        wsum[lane] = v;
    }
    __syncthreads();
    int off = (w > 0) ? wsum[w - 1] : 0;
    total = wsum[31];
    return off + inc - val;
}
__global__ void k_scan1(int N) {
    int idx = blockIdx.x * 1024 + threadIdx.x;
    int val = (idx < N) ? g_cnt[idx] : 0;
    int total;
    int ex = block_scan_excl_1024(val, total);
    if (idx < N) g_rowptr[idx] = ex;
    if (threadIdx.x == 0) g_bsum[blockIdx.x] = total;
}
__global__ void k_scan2(int NB) {   // NB <= 128
    __shared__ int s[128];
    int t = threadIdx.x;
    s[t] = (t < NB) ? g_bsum[t] : 0;
    __syncthreads();
#pragma unroll
    for (int o = 1; o < 128; o <<= 1) {
        int v = (t >= o) ? s[t - o] : 0;
        __syncthreads();
        s[t] += v;
        __syncthreads();
    }
    if (t < NB) g_bsum[t] = (t > 0) ? s[t - 1] : 0;
}
__global__ void k_scan3(int N, int E) {
    int idx = blockIdx.x * 1024 + threadIdx.x;
    if (idx < N) {
        int r = g_rowptr[idx] + g_bsum[blockIdx.x];
        g_rowptr[idx] = r;
        g_fill[idx]   = r;
    }
    if (idx == 0) g_rowptr[N] = E;
}
__global__ void k_scatter(const int* __restrict__ ei, int E) {
    for (int i = blockIdx.x * blockDim.x + threadIdx.x; i < E; i += gridDim.x * blockDim.x) {
        int d = ei[E + i];
        int p = atomicAdd(&g_fill[d], 1);
        g_adj[p] = ei[i];
    }
}

// ---------------------------------------------------------------------------
// W -> bf16 hi/lo images, layout B[n][k] (k contiguous), XOR swizzle
// ---------------------------------------------------------------------------
__global__ void k_wconv(const float* __restrict__ W1l, const float* __restrict__ W1r,
                        const float* __restrict__ W2l, const float* __restrict__ W2r,
                        const float* __restrict__ W3l, const float* __restrict__ W3r) {
    int tid = blockIdx.x * blockDim.x + threadIdx.x;
    if (tid >= 4 * 4096) return;
    int img = tid >> 12, idx = tid & 4095;
    int n = idx >> 5, kp = idx & 31;
    int k0 = 2 * kp, k1 = k0 + 1;
    float v0, v1;
    if (img == 0) {
        v0 = (n < 64) ? W1l[k0 * 64 + n] : W1r[k0 * 64 + n - 64];
        v1 = (n < 64) ? W1l[k1 * 64 + n] : W1r[k1 * 64 + n - 64];
    } else if (img == 1) {
        v0 = (n < 64) ? W2l[k0 * 64 + n] : W2r[k0 * 64 + n - 64];
        v1 = (n < 64) ? W2l[k1 * 64 + n] : W2r[k1 * 64 + n - 64];
    } else if (img == 2) {
        v0 = W3l[k0 * 128 + n];
        v1 = W3l[k1 * 128 + n];
    } else {
        v0 = W3r[k0 * 128 + n];
        v1 = W3r[k1 * 128 + n];
    }
    uint16_t h0, l0, h1, l1;
    bf16_split(v0, h0, l0);
    bf16_split(v1, h1, l1);
    uint32_t off = swz_off(n, kp * 4);
    *(uint32_t*)(g_wimg_hi[img] + off) = (uint32_t)h0 | ((uint32_t)h1 << 16);
    *(uint32_t*)(g_wimg_lo[img] + off) = (uint32_t)l0 | ((uint32_t)l1 << 16);
}

// ---------------------------------------------------------------------------
// HMMA GEMM: Y[128-row tile, 128 cols] = X @ W via mma.sync bf16, 3-term split.
// 256 thr = 8 warps: warp (w&3) -> rows (w&3)*32, (w>>2) -> cols (w>>2)*64.
// ---------------------------------------------------------------------------
#define SMA_HI 0
#define SMA_LO 16384
#define SMB_HI 32768
#define SMB_LO 49152
#define SM_TOT 65536

template <bool DUAL>
__global__ void __launch_bounds__(256) k_mma(const float* __restrict__ X,
                                             const unsigned char* __restrict__ Bhi,
                                             const unsigned char* __restrict__ Blo,
                                             float* __restrict__ Y0,
                                             float* __restrict__ Y1, int N) {
    extern __shared__ char smem[];
    const uint32_t sb = smem_u32(smem);
    const int tid = threadIdx.x, wid = tid >> 5, lane = tid & 31;
    const int rowbase = blockIdx.x * 128;

    // Copy W images (16 KB each)
    const uint4* bh = (const uint4*)Bhi;
    const uint4* bl = (const uint4*)Blo;
#pragma unroll
    for (int i = tid; i < 1024; i += 256) {
        ((uint4*)(smem + SMB_HI))[i] = bh[i];
        ((uint4*)(smem + SMB_LO))[i] = bl[i];
    }
    // Convert X tile -> bf16 hi/lo (zero-padded rows past N)
#pragma unroll
    for (int i = tid; i < 4096; i += 256) {
        int r = i >> 5, kp = i & 31;
        int row = rowbase + r;
        float2 v = (row < N) ? *(const float2*)&X[row * 64 + 2 * kp] : make_float2(0.f, 0.f);
        uint16_t h0, l0, h1, l1;
        bf16_split(v.x, h0, l0);
        bf16_split(v.y, h1, l1);
        uint32_t off = swz_off(r, kp * 4);
        *(uint32_t*)(smem + SMA_HI + off) = (uint32_t)h0 | ((uint32_t)h1 << 16);
        *(uint32_t*)(smem + SMA_LO + off) = (uint32_t)l0 | ((uint32_t)l1 << 16);
    }
    __syncthreads();

    const int m0 = (wid & 3) * 32;
    const int n0 = (wid >> 2) * 64;
    const int rl  = lane & 7;      // row within 8-row ldmatrix group
    const int grp = lane >> 3;     // which 8x8 matrix this lane addresses

    float acc[2][8][4];
#pragma unroll
    for (int mt = 0; mt < 2; mt++)
#pragma unroll
        for (int nt = 0; nt < 8; nt++)
#pragma unroll
            for (int j = 0; j < 4; j++) acc[mt][nt][j] = 0.f;

    // terms: (Ahi,Bhi), (Alo,Bhi), (Ahi,Blo)
    const uint32_t aBase[3] = { sb + SMA_HI, sb + SMA_LO, sb + SMA_HI };
    const uint32_t bBase[3] = { sb + SMB_HI, sb + SMB_HI, sb + SMB_LO };

#pragma unroll
    for (int t = 0; t < 3; t++) {
        const uint32_t ab = aBase[t], bb = bBase[t];
#pragma unroll
        for (int ks = 0; ks < 4; ks++) {
            const int cb = ks * 32;  // byte offset of this k16 step (2 x 16B chunks)
            // A frags for 2 m-tiles: lanes0-7:(m,k0) 8-15:(m+8,k0) 16-23:(m,k8) 24-31:(m+8,k8)
            uint32_t a[2][4];
#pragma unroll
            for (int mt = 0; mt < 2; mt++) {
                int arow = m0 + mt * 16 + (grp & 1) * 8 + rl;
                int abyte = cb + (grp >> 1) * 16;
                ldm_x4(a[mt], ab + swz_off(arow, abyte));
            }
            // B frags: 4 x ldmatrix.x4, each covers 2 n-tiles
#pragma unroll
            for (int np = 0; np < 4; np++) {
                int brow = n0 + np * 16 + (grp >> 1) * 8 + rl;
                int bbyte = cb + (grp & 1) * 16;
                uint32_t b[4];
                ldm_x4(b, bb + swz_off(brow, bbyte));
                mma_bf16(acc[0][2 * np],     a[0], b[0], b[1]);
                mma_bf16(acc[1][2 * np],     a[1], b[0], b[1]);
                mma_bf16(acc[0][2 * np + 1], a[0], b[2], b[3]);
                mma_bf16(acc[1][2 * np + 1], a[1], b[2], b[3]);
            }
        }
    }

    // Epilogue: c0,c1 -> (row, col..col+1); c2,c3 -> (row+8, ...)
    const int qr = lane >> 2, qc = (lane & 3) * 2;
#pragma unroll
    for (int mt = 0; mt < 2; mt++) {
#pragma unroll
        for (int nt = 0; nt < 8; nt++) {
            int col = n0 + nt * 8 + qc;
            int row0 = rowbase + m0 + mt * 16 + qr;
#pragma unroll
            for (int h = 0; h < 2; h++) {
                int row = row0 + h * 8;
                if (row < N) {
                    float2 v = make_float2(acc[mt][nt][2 * h], acc[mt][nt][2 * h + 1]);
                    if (DUAL) {
                        if (col < 64) *(float2*)&Y0[row * 64 + col] = v;
                        else          *(float2*)&Y1[row * 64 + col - 64] = v;
                    } else {
                        *(float2*)&Y0[row * 128 + col] = v;
                    }
                }
            }
        }
    }
}

// ---------------------------------------------------------------------------
// Fused GATv2 edge phase: one warp per destination node, online softmax.
// ---------------------------------------------------------------------------
__device__ __forceinline__ float leaky(float t) { return t > 0.f ? t : 0.2f * t; }

__global__ void k_edge64(const float* __restrict__ XL, const float* __restrict__ XR,
                         const float* __restrict__ att, const float* __restrict__ bias,
                         float* __restrict__ OUT, int N) {
    int lane = threadIdx.x & 31;
    int n    = (blockIdx.x * blockDim.x + threadIdx.x) >> 5;
    if (n >= N) return;

    float a0 = att[2 * lane], a1 = att[2 * lane + 1];
    float2 xr = *(const float2*)&XR[n * 64 + 2 * lane];
    float2 vs = *(const float2*)&XL[n * 64 + 2 * lane];

    float p = a0 * leaky(vs.x + xr.x) + a1 * leaky(vs.y + xr.y);
    p += __shfl_xor_sync(0xffffffffu, p, 4);
    p += __shfl_xor_sync(0xffffffffu, p, 2);
    p += __shfl_xor_sync(0xffffffffu, p, 1);
    float m = p, d = 1.f, ax = vs.x, ay = vs.y;

    int beg = g_rowptr[n], end = g_rowptr[n + 1];
    int s = (beg < end) ? g_adj[beg] : 0;
    for (int i = beg; i < end; i++) {
        float2 v = *(const float2*)&XL[s * 64 + 2 * lane];
        int sn = (i + 1 < end) ? g_adj[i + 1] : 0;
        p = a0 * leaky(v.x + xr.x) + a1 * leaky(v.y + xr.y);
        p += __shfl_xor_sync(0xffffffffu, p, 4);
        p += __shfl_xor_sync(0xffffffffu, p, 2);
        p += __shfl_xor_sync(0xffffffffu, p, 1);
        if (p <= m) {
            float w = __expf(p - m);
            ax += w * v.x; ay += w * v.y; d += w;
        } else {
            float sc = __expf(m - p);
            ax = ax * sc + v.x; ay = ay * sc + v.y; d = d * sc + 1.f;
            m = p;
        }
        s = sn;
    }
    float inv = 1.f / d;
    float ox = ax * inv + bias[2 * lane];
    float oy = ay * inv + bias[2 * lane + 1];
    ox = ox > 0.f ? ox : (__expf(ox) - 1.f);
    oy = oy > 0.f ? oy : (__expf(oy) - 1.f);
    *(float2*)&OUT[n * 64 + 2 * lane] = make_float2(ox, oy);
}

__global__ void k_edge128_mean(const float* __restrict__ XL, const float* __restrict__ XR,
                               const float* __restrict__ att, const float* __restrict__ bias,
                               float* __restrict__ OUT, int N) {
    int lane = threadIdx.x & 31;
    int n    = (blockIdx.x * blockDim.x + threadIdx.x) >> 5;
    if (n >= N) return;

    float4 a  = *(const float4*)&att[4 * lane];
    float4 xr = *(const float4*)&XR[n * 128 + 4 * lane];
    float4 vs = *(const float4*)&XL[n * 128 + 4 * lane];

    float p = a.x * leaky(vs.x + xr.x) + a.y * leaky(vs.y + xr.y) +
              a.z * leaky(vs.z + xr.z) + a.w * leaky(vs.w + xr.w);
    p += __shfl_xor_sync(0xffffffffu, p, 4);
    p += __shfl_xor_sync(0xffffffffu, p, 2);
    p += __shfl_xor_sync(0xffffffffu, p, 1);
    float m = p, d = 1.f;
    float4 acc = vs;

    int beg = g_rowptr[n], end = g_rowptr[n + 1];
    int s = (beg < end) ? g_adj[beg] : 0;
    for (int i = beg; i < end; i++) {
        float4 v = *(const float4*)&XL[s * 128 + 4 * lane];
        int sn = (i + 1 < end) ? g_adj[i + 1] : 0;
        p = a.x * leaky(v.x + xr.x) + a.y * leaky(v.y + xr.y) +
            a.z * leaky(v.z + xr.z) + a.w * leaky(v.w + xr.w);
        p += __shfl_xor_sync(0xffffffffu, p, 4);
        p += __shfl_xor_sync(0xffffffffu, p, 2);
        p += __shfl_xor_sync(0xffffffffu, p, 1);
        if (p <= m) {
            float w = __expf(p - m);
            acc.x += w * v.x; acc.y += w * v.y; acc.z += w * v.z; acc.w += w * v.w;
            d += w;
        } else {
            float sc = __expf(m - p);
            acc.x = acc.x * sc + v.x; acc.y = acc.y * sc + v.y;
            acc.z = acc.z * sc + v.z; acc.w = acc.w * sc + v.w;
            d = d * sc + 1.f;
            m = p;
        }
        s = sn;
    }
    float inv = 1.f / d;
    float o0 = acc.x * inv, o1 = acc.y * inv, o2 = acc.z * inv, o3 = acc.w * inv;
#pragma unroll
    for (int off = 8; off <= 16; off <<= 1) {
        o0 += __shfl_xor_sync(0xffffffffu, o0, off);
        o1 += __shfl_xor_sync(0xffffffffu, o1, off);
        o2 += __shfl_xor_sync(0xffffffffu, o2, off);
        o3 += __shfl_xor_sync(0xffffffffu, o3, off);
    }
    if (lane < 8) {
        int c = 4 * lane;
        float4 o = make_float4(0.25f * o0 + bias[c + 0],
                               0.25f * o1 + bias[c + 1],
                               0.25f * o2 + bias[c + 2],
                               0.25f * o3 + bias[c + 3]);
        *(float4*)&OUT[n * 32 + c] = o;
    }
}

// ---------------------------------------------------------------------------
// Launch (ordered so ncu -s 5 -c 1 captures the layer-1 GEMM)
// ---------------------------------------------------------------------------
extern "C" void kernel_launch(void* const* d_in, const int* in_sizes, int n_in,
                              void* d_out, int out_size) {
    const float* x   = (const float*)d_in[0];
    const int*   ei  = (const int*)  d_in[1];
    const float* W1l = (const float*)d_in[2];
    const float* W1r = (const float*)d_in[3];
    const float* a1  = (const float*)d_in[4];
    const float* b1  = (const float*)d_in[5];
    const float* W2l = (const float*)d_in[6];
    const float* W2r = (const float*)d_in[7];
    const float* a2  = (const float*)d_in[8];
    const float* b2  = (const float*)d_in[9];
    const float* W3l = (const float*)d_in[10];
    const float* W3r = (const float*)d_in[11];
    const float* a3  = (const float*)d_in[12];
    const float* b3  = (const float*)d_in[13];
    float* out = (float*)d_out;

    const int N = in_sizes[0] / 64;
    const int E = in_sizes[1] / 2;
    const int NB = (N + 1023) / 1024;

    float *xl, *xr, *h;
    unsigned char (*whi)[16384], (*wlo)[16384];
    cudaGetSymbolAddress((void**)&xl,  g_xl);
    cudaGetSymbolAddress((void**)&xr,  g_xr);
    cudaGetSymbolAddress((void**)&h,   g_h);
    cudaGetSymbolAddress((void**)&whi, g_wimg_hi);
    cudaGetSymbolAddress((void**)&wlo, g_wimg_lo);

    cudaFuncSetAttribute(k_mma<true>,  cudaFuncAttributeMaxDynamicSharedMemorySize, SM_TOT);
    cudaFuncSetAttribute(k_mma<false>, cudaFuncAttributeMaxDynamicSharedMemorySize, SM_TOT);

    const int GT = (N + 127) / 128;
    const int EB = (N + 7) / 8;

    // launches 0-4
    k_wconv<<<64, 256>>>(W1l, W1r, W2l, W2r, W3l, W3r);
    k_zero<<<(N + 255) / 256, 256>>>(N);
    k_hist<<<1024, 256>>>(ei, E);
    k_scan1<<<NB, 1024>>>(N);
    k_scan2<<<1, 128>>>(NB);
    // launch 5: layer-1 GEMM (ncu capture target)
    k_mma<true><<<GT, 256, SM_TOT>>>(x, whi[0], wlo[0], xl, xr, N);
    // finish CSR
    k_scan3<<<NB, 1024>>>(N, E);
    k_scatter<<<1024, 256>>>(ei, E);
    // Layer 1 edge
    k_edge64<<<EB, 256>>>(xl, xr, a1, b1, h, N);
    // Layer 2
    k_mma<true><<<GT, 256, SM_TOT>>>(h, whi[1], wlo[1], xl, xr, N);
    k_edge64<<<EB, 256>>>(xl, xr, a2, b2, h, N);
    // Layer 3
    k_mma<false><<<GT, 256, SM_TOT>>>(h, whi[2], wlo[2], xl, nullptr, N);
    k_mma<false><<<GT, 256, SM_TOT>>>(h, whi[3], wlo[3], xr, nullptr, N);
    k_edge128_mean<<<EB, 256>>>(xl, xr, a3, b3, out, N);
}

// round 5
// speedup vs baseline: 1.4319x; 1.0140x over previous
#include <cuda_runtime.h>
#include <cuda_bf16.h>
#include <cstdint>

// Problem constants
#define NMAX 100000
#define EMAX 800000

// Scratch (no allocation allowed -> __device__ globals)
__device__ float g_xl[NMAX * 128];
__device__ float g_xr[NMAX * 128];
__device__ float g_h [NMAX * 64];
__device__ int   g_cnt[NMAX];
__device__ int   g_rowptr[NMAX + 1];
__device__ int   g_fill[NMAX];
__device__ int   g_adj[EMAX];
__device__ int   g_bsum[128];
// bf16 [n=128][k=64] images (XOR-swizzled), 4 operand sets:
// 0: [W1l|W1r], 1: [W2l|W2r], 2: W3l, 3: W3r
__device__ __align__(16) unsigned char g_wimg_hi[4][16384];
__device__ __align__(16) unsigned char g_wimg_lo[4][16384];

// ---------------------------------------------------------------------------
// helpers
// ---------------------------------------------------------------------------
__device__ __forceinline__ uint32_t smem_u32(const void* p) {
    uint32_t a;
    asm("{ .reg .u64 t; cvta.to.shared.u64 t, %1; cvt.u32.u64 %0, t; }" : "=r"(a) : "l"(p));
    return a;
}
__device__ __forceinline__ void bf16_split(float v, uint16_t& hi, uint16_t& lo) {
    __nv_bfloat16 h = __float2bfloat16(v);
    float residual = v - __bfloat162float(h);
    __nv_bfloat16 l = __float2bfloat16(residual);
    hi = *(uint16_t*)&h;
    lo = *(uint16_t*)&l;
}
__device__ __forceinline__ void ldm_x4(uint32_t (&r)[4], uint32_t addr) {
    asm volatile("ldmatrix.sync.aligned.m8n8.x4.shared.b16 {%0,%1,%2,%3}, [%4];"
                 : "=r"(r[0]), "=r"(r[1]), "=r"(r[2]), "=r"(r[3]) : "r"(addr));
}
__device__ __forceinline__ void mma_bf16(float (&d)[4], const uint32_t (&a)[4],
                                         uint32_t b0, uint32_t b1) {
    asm volatile(
        "mma.sync.aligned.m16n8k16.row.col.f32.bf16.bf16.f32 "
        "{%0,%1,%2,%3}, {%4,%5,%6,%7}, {%8,%9}, {%0,%1,%2,%3};"
        : "+f"(d[0]), "+f"(d[1]), "+f"(d[2]), "+f"(d[3])
        : "r"(a[0]), "r"(a[1]), "r"(a[2]), "r"(a[3]), "r"(b0), "r"(b1));
}
// XOR swizzle inside a 128B row: 16B chunk index XORed with (row&7)
__device__ __forceinline__ uint32_t swz_off(int row, int byte_in_row) {
    return (uint32_t)(row * 128 + (byte_in_row ^ ((row & 7) << 4)));
}

// ---------------------------------------------------------------------------
// k_init: g_cnt zero + W -> bf16 hi/lo images (fused)
// ---------------------------------------------------------------------------
__global__ void k_init(const float* __restrict__ W1l, const float* __restrict__ W1r,
                       const float* __restrict__ W2l, const float* __restrict__ W2r,
                       const float* __restrict__ W3l, const float* __restrict__ W3r,
                       int N) {
    if (blockIdx.x >= 64) {
        int i = (blockIdx.x - 64) * 256 + threadIdx.x;
        if (i < N) g_cnt[i] = 0;
        return;
    }
    int tid = blockIdx.x * 256 + threadIdx.x;   // 0..16383
    int img = tid >> 12, idx = tid & 4095;
    int n = idx >> 5, kp = idx & 31;
    int k0 = 2 * kp, k1 = k0 + 1;
    float v0, v1;
    if (img == 0) {
        v0 = (n < 64) ? W1l[k0 * 64 + n] : W1r[k0 * 64 + n - 64];
        v1 = (n < 64) ? W1l[k1 * 64 + n] : W1r[k1 * 64 + n - 64];
    } else if (img == 1) {
        v0 = (n < 64) ? W2l[k0 * 64 + n] : W2r[k0 * 64 + n - 64];
        v1 = (n < 64) ? W2l[k1 * 64 + n] : W2r[k1 * 64 + n - 64];
    } else if (img == 2) {
        v0 = W3l[k0 * 128 + n];
        v1 = W3l[k1 * 128 + n];
    } else {
        v0 = W3r[k0 * 128 + n];
        v1 = W3r[k1 * 128 + n];
    }
    uint16_t h0, l0, h1, l1;
    bf16_split(v0, h0, l0);
    bf16_split(v1, h1, l1);
    uint32_t off = swz_off(n, kp * 4);
    *(uint32_t*)(g_wimg_hi[img] + off) = (uint32_t)h0 | ((uint32_t)h1 << 16);
    *(uint32_t*)(g_wimg_lo[img] + off) = (uint32_t)l0 | ((uint32_t)l1 << 16);
}

// ---------------------------------------------------------------------------
// CSR build
// ---------------------------------------------------------------------------
__global__ void k_hist(const int* __restrict__ ei, int E) {
    for (int i = blockIdx.x * blockDim.x + threadIdx.x; i < E; i += gridDim.x * blockDim.x)
        atomicAdd(&g_cnt[ei[E + i]], 1);
}
__device__ __forceinline__ int block_scan_excl_1024(int val, int& total) {
    __shared__ int wsum[32];
    int lane = threadIdx.x & 31, w = threadIdx.x >> 5;
    int inc = val;
#pragma unroll
    for (int o = 1; o < 32; o <<= 1) {
        int u = __shfl_up_sync(0xffffffffu, inc, o);
        if (lane >= o) inc += u;
    }
    if (lane == 31) wsum[w] = inc;
    __syncthreads();
    if (w == 0) {
        int v = wsum[lane];
#pragma unroll
        for (int o = 1; o < 32; o <<= 1) {
            int u = __shfl_up_sync(0xffffffffu, v, o);
            if (lane >= o) v += u;
        }
        wsum[lane] = v;
    }
    __syncthreads();
    int off = (w > 0) ? wsum[w - 1] : 0;
    total = wsum[31];
    return off + inc - val;
}
__global__ void k_scan1(int N) {
    int idx = blockIdx.x * 1024 + threadIdx.x;
    int val = (idx < N) ? g_cnt[idx] : 0;
    int total;
    int ex = block_scan_excl_1024(val, total);
    if (idx < N) g_rowptr[idx] = ex;
    if (threadIdx.x == 0) g_bsum[blockIdx.x] = total;
}
// scan3 with inline reduction of preceding block totals (NB <= 128)
__global__ void k_scan3(int N, int E) {
    __shared__ int ws[4];
    __shared__ int s_off;
    int t = threadIdx.x;
    if (t < 128) {
        int v = (t < blockIdx.x) ? g_bsum[t] : 0;
#pragma unroll
        for (int o = 16; o > 0; o >>= 1) v += __shfl_xor_sync(0xffffffffu, v, o);
        if ((t & 31) == 0) ws[t >> 5] = v;
    }
    __syncthreads();
    if (t == 0) s_off = ws[0] + ws[1] + ws[2] + ws[3];
    __syncthreads();
    int idx = blockIdx.x * 1024 + t;
    if (idx < N) {
        int r = g_rowptr[idx] + s_off;
        g_rowptr[idx] = r;
        g_fill[idx]   = r;
    }
    if (idx == 0) g_rowptr[N] = E;
}
__global__ void k_scatter(const int* __restrict__ ei, int E) {
    for (int i = blockIdx.x * blockDim.x + threadIdx.x; i < E; i += gridDim.x * blockDim.x) {
        int d = ei[E + i];
        int p = atomicAdd(&g_fill[d], 1);
        g_adj[p] = ei[i];
    }
}

// ---------------------------------------------------------------------------
// HMMA GEMM (layers 1/2): Y[128 x 128] tile = X @ [Wl|Wr], 3-term bf16 split.
// 256 thr = 8 warps: warp -> rows (w&3)*32, cols (w>>2)*64.
// ---------------------------------------------------------------------------
#define SMA_HI 0
#define SMA_LO 16384
#define SMB_HI 32768
#define SMB_LO 49152
#define SM_TOT 65536

__global__ void __launch_bounds__(256) k_mma(const float* __restrict__ X,
                                             const unsigned char* __restrict__ Bhi,
                                             const unsigned char* __restrict__ Blo,
                                             float* __restrict__ Y0,
                                             float* __restrict__ Y1, int N) {
    extern __shared__ char smem[];
    const uint32_t sb = smem_u32(smem);
    const int tid = threadIdx.x, wid = tid >> 5, lane = tid & 31;
    const int rowbase = blockIdx.x * 128;

    const uint4* bh = (const uint4*)Bhi;
    const uint4* bl = (const uint4*)Blo;
#pragma unroll
    for (int i = tid; i < 1024; i += 256) {
        ((uint4*)(smem + SMB_HI))[i] = bh[i];
        ((uint4*)(smem + SMB_LO))[i] = bl[i];
    }
#pragma unroll
    for (int i = tid; i < 4096; i += 256) {
        int r = i >> 5, kp = i & 31;
        int row = rowbase + r;
        float2 v = (row < N) ? *(const float2*)&X[row * 64 + 2 * kp] : make_float2(0.f, 0.f);
        uint16_t h0, l0, h1, l1;
        bf16_split(v.x, h0, l0);
        bf16_split(v.y, h1, l1);
        uint32_t off = swz_off(r, kp * 4);
        *(uint32_t*)(smem + SMA_HI + off) = (uint32_t)h0 | ((uint32_t)h1 << 16);
        *(uint32_t*)(smem + SMA_LO + off) = (uint32_t)l0 | ((uint32_t)l1 << 16);
    }
    __syncthreads();

    const int m0 = (wid & 3) * 32;
    const int n0 = (wid >> 2) * 64;
    const int rl  = lane & 7;
    const int grp = lane >> 3;

    float acc[2][8][4];
#pragma unroll
    for (int mt = 0; mt < 2; mt++)
#pragma unroll
        for (int nt = 0; nt < 8; nt++)
#pragma unroll
            for (int j = 0; j < 4; j++) acc[mt][nt][j] = 0.f;

    const uint32_t aBase[3] = { sb + SMA_HI, sb + SMA_LO, sb + SMA_HI };
    const uint32_t bBase[3] = { sb + SMB_HI, sb + SMB_HI, sb + SMB_LO };

#pragma unroll
    for (int t = 0; t < 3; t++) {
        const uint32_t ab = aBase[t], bb = bBase[t];
#pragma unroll
        for (int ks = 0; ks < 4; ks++) {
            const int cb = ks * 32;
            uint32_t a[2][4];
#pragma unroll
            for (int mt = 0; mt < 2; mt++) {
                int arow = m0 + mt * 16 + (grp & 1) * 8 + rl;
                int abyte = cb + (grp >> 1) * 16;
                ldm_x4(a[mt], ab + swz_off(arow, abyte));
            }
#pragma unroll
            for (int np = 0; np < 4; np++) {
                int brow = n0 + np * 16 + (grp >> 1) * 8 + rl;
                int bbyte = cb + (grp & 1) * 16;
                uint32_t b[4];
                ldm_x4(b, bb + swz_off(brow, bbyte));
                mma_bf16(acc[0][2 * np],     a[0], b[0], b[1]);
                mma_bf16(acc[1][2 * np],     a[1], b[0], b[1]);
                mma_bf16(acc[0][2 * np + 1], a[0], b[2], b[3]);
                mma_bf16(acc[1][2 * np + 1], a[1], b[2], b[3]);
            }
        }
    }

    const int qr = lane >> 2, qc = (lane & 3) * 2;
#pragma unroll
    for (int mt = 0; mt < 2; mt++) {
#pragma unroll
        for (int nt = 0; nt < 8; nt++) {
            int col = n0 + nt * 8 + qc;
            int row0 = rowbase + m0 + mt * 16 + qr;
#pragma unroll
            for (int h = 0; h < 2; h++) {
                int row = row0 + h * 8;
                if (row < N) {
                    float2 v = make_float2(acc[mt][nt][2 * h], acc[mt][nt][2 * h + 1]);
                    if (col < 64) *(float2*)&Y0[row * 64 + col] = v;
                    else          *(float2*)&Y1[row * 64 + col - 64] = v;
                }
            }
        }
    }
}

// ---------------------------------------------------------------------------
// Layer-3 fused GEMM: Y[128 x 256] = X @ [W3l | W3r] in ONE pass.
// 512 thr = 16 warps; warp -> rows (w&3)*32, cols (w>>2)*64 (0..255).
// cols 0-127 -> xl, 128-255 -> xr. X converted once.
// ---------------------------------------------------------------------------
#define SM3_AHI 0
#define SM3_ALO 16384
#define SM3_BHI 32768
#define SM3_BLO 65536
#define SM3_TOT 98304

__global__ void __launch_bounds__(512) k_mma3(const float* __restrict__ X,
                                              const unsigned char* __restrict__ Bhi2,
                                              const unsigned char* __restrict__ Blo2,
                                              const unsigned char* __restrict__ Bhi3,
                                              const unsigned char* __restrict__ Blo3,
                                              float* __restrict__ Y0,
                                              float* __restrict__ Y1, int N) {
    extern __shared__ char smem[];
    const uint32_t sb = smem_u32(smem);
    const int tid = threadIdx.x, wid = tid >> 5, lane = tid & 31;
    const int rowbase = blockIdx.x * 128;

    // B images: rows 0-127 = W3l, rows 128-255 = W3r
#pragma unroll
    for (int i = tid; i < 2048; i += 512) {
        ((uint4*)(smem + SM3_BHI))[i] = (i < 1024) ? ((const uint4*)Bhi2)[i]
                                                   : ((const uint4*)Bhi3)[i - 1024];
        ((uint4*)(smem + SM3_BLO))[i] = (i < 1024) ? ((const uint4*)Blo2)[i]
                                                   : ((const uint4*)Blo3)[i - 1024];
    }
#pragma unroll
    for (int i = tid; i < 4096; i += 512) {
        int r = i >> 5, kp = i & 31;
        int row = rowbase + r;
        float2 v = (row < N) ? *(const float2*)&X[row * 64 + 2 * kp] : make_float2(0.f, 0.f);
        uint16_t h0, l0, h1, l1;
        bf16_split(v.x, h0, l0);
        bf16_split(v.y, h1, l1);
        uint32_t off = swz_off(r, kp * 4);
        *(uint32_t*)(smem + SM3_AHI + off) = (uint32_t)h0 | ((uint32_t)h1 << 16);
        *(uint32_t*)(smem + SM3_ALO + off) = (uint32_t)l0 | ((uint32_t)l1 << 16);
    }
    __syncthreads();

    const int m0 = (wid & 3) * 32;
    const int n0 = (wid >> 2) * 64;  // 0,64,128,192
    const int rl  = lane & 7;
    const int grp = lane >> 3;

    float acc[2][8][4];
#pragma unroll
    for (int mt = 0; mt < 2; mt++)
#pragma unroll
        for (int nt = 0; nt < 8; nt++)
#pragma unroll
            for (int j = 0; j < 4; j++) acc[mt][nt][j] = 0.f;

    const uint32_t aBase[3] = { sb + SM3_AHI, sb + SM3_ALO, sb + SM3_AHI };
    const uint32_t bBase[3] = { sb + SM3_BHI, sb + SM3_BHI, sb + SM3_BLO };

#pragma unroll
    for (int t = 0; t < 3; t++) {
        const uint32_t ab = aBase[t], bb = bBase[t];
#pragma unroll
        for (int ks = 0; ks < 4; ks++) {
            const int cb = ks * 32;
            uint32_t a[2][4];
#pragma unroll
            for (int mt = 0; mt < 2; mt++) {
                int arow = m0 + mt * 16 + (grp & 1) * 8 + rl;
                int abyte = cb + (grp >> 1) * 16;
                ldm_x4(a[mt], ab + swz_off(arow, abyte));
            }
#pragma unroll
            for (int np = 0; np < 4; np++) {
                int brow = n0 + np * 16 + (grp >> 1) * 8 + rl;
                int bbyte = cb + (grp & 1) * 16;
                uint32_t b[4];
                ldm_x4(b, bb + swz_off(brow, bbyte));
                mma_bf16(acc[0][2 * np],     a[0], b[0], b[1]);
                mma_bf16(acc[1][2 * np],     a[1], b[0], b[1]);
                mma_bf16(acc[0][2 * np + 1], a[0], b[2], b[3]);
                mma_bf16(acc[1][2 * np + 1], a[1], b[2], b[3]);
            }
        }
    }

    const int qr = lane >> 2, qc = (lane & 3) * 2;
#pragma unroll
    for (int mt = 0; mt < 2; mt++) {
#pragma unroll
        for (int nt = 0; nt < 8; nt++) {
            int col = n0 + nt * 8 + qc;
            int row0 = rowbase + m0 + mt * 16 + qr;
#pragma unroll
            for (int h = 0; h < 2; h++) {
                int row = row0 + h * 8;
                if (row < N) {
                    float2 v = make_float2(acc[mt][nt][2 * h], acc[mt][nt][2 * h + 1]);
                    if (col < 128) *(float2*)&Y0[row * 128 + col] = v;
                    else           *(float2*)&Y1[row * 128 + col - 128] = v;
                }
            }
        }
    }
}

// ---------------------------------------------------------------------------
// Fused GATv2 edge phase: one warp per destination node, online softmax.
// ---------------------------------------------------------------------------
__device__ __forceinline__ float leaky(float t) { return t > 0.f ? t : 0.2f * t; }

__global__ void k_edge64(const float* __restrict__ XL, const float* __restrict__ XR,
                         const float* __restrict__ att, const float* __restrict__ bias,
                         float* __restrict__ OUT, int N) {
    int lane = threadIdx.x & 31;
    int n    = (blockIdx.x * blockDim.x + threadIdx.x) >> 5;
    if (n >= N) return;

    float a0 = att[2 * lane], a1 = att[2 * lane + 1];
    float2 xr = *(const float2*)&XR[n * 64 + 2 * lane];
    float2 vs = *(const float2*)&XL[n * 64 + 2 * lane];

    float p = a0 * leaky(vs.x + xr.x) + a1 * leaky(vs.y + xr.y);
    p += __shfl_xor_sync(0xffffffffu, p, 4);
    p += __shfl_xor_sync(0xffffffffu, p, 2);
    p += __shfl_xor_sync(0xffffffffu, p, 1);
    float m = p, d = 1.f, ax = vs.x, ay = vs.y;

    int beg = g_rowptr[n], end = g_rowptr[n + 1];
    int s = (beg < end) ? g_adj[beg] : 0;
    for (int i = beg; i < end; i++) {
        float2 v = *(const float2*)&XL[s * 64 + 2 * lane];
        int sn = (i + 1 < end) ? g_adj[i + 1] : 0;
        p = a0 * leaky(v.x + xr.x) + a1 * leaky(v.y + xr.y);
        p += __shfl_xor_sync(0xffffffffu, p, 4);
        p += __shfl_xor_sync(0xffffffffu, p, 2);
        p += __shfl_xor_sync(0xffffffffu, p, 1);
        if (p <= m) {
            float w = __expf(p - m);
            ax += w * v.x; ay += w * v.y; d += w;
        } else {
            float sc = __expf(m - p);
            ax = ax * sc + v.x; ay = ay * sc + v.y; d = d * sc + 1.f;
            m = p;
        }
        s = sn;
    }
    float inv = 1.f / d;
    float ox = ax * inv + bias[2 * lane];
    float oy = ay * inv + bias[2 * lane + 1];
    ox = ox > 0.f ? ox : (__expf(ox) - 1.f);
    oy = oy > 0.f ? oy : (__expf(oy) - 1.f);
    *(float2*)&OUT[n * 64 + 2 * lane] = make_float2(ox, oy);
}

__global__ void k_edge128_mean(const float* __restrict__ XL, const float* __restrict__ XR,
                               const float* __restrict__ att, const float* __restrict__ bias,
                               float* __restrict__ OUT, int N) {
    int lane = threadIdx.x & 31;
    int n    = (blockIdx.x * blockDim.x + threadIdx.x) >> 5;
    if (n >= N) return;

    float4 a  = *(const float4*)&att[4 * lane];
    float4 xr = *(const float4*)&XR[n * 128 + 4 * lane];
    float4 vs = *(const float4*)&XL[n * 128 + 4 * lane];

    float p = a.x * leaky(vs.x + xr.x) + a.y * leaky(vs.y + xr.y) +
              a.z * leaky(vs.z + xr.z) + a.w * leaky(vs.w + xr.w);
    p += __shfl_xor_sync(0xffffffffu, p, 4);
    p += __shfl_xor_sync(0xffffffffu, p, 2);
    p += __shfl_xor_sync(0xffffffffu, p, 1);
    float m = p, d = 1.f;
    float4 acc = vs;

    int beg = g_rowptr[n], end = g_rowptr[n + 1];
    int s = (beg < end) ? g_adj[beg] : 0;
    for (int i = beg; i < end; i++) {
        float4 v = *(const float4*)&XL[s * 128 + 4 * lane];
        int sn = (i + 1 < end) ? g_adj[i + 1] : 0;
        p = a.x * leaky(v.x + xr.x) + a.y * leaky(v.y + xr.y) +
            a.z * leaky(v.z + xr.z) + a.w * leaky(v.w + xr.w);
        p += __shfl_xor_sync(0xffffffffu, p, 4);
        p += __shfl_xor_sync(0xffffffffu, p, 2);
        p += __shfl_xor_sync(0xffffffffu, p, 1);
        if (p <= m) {
            float w = __expf(p - m);
            acc.x += w * v.x; acc.y += w * v.y; acc.z += w * v.z; acc.w += w * v.w;
            d += w;
        } else {
            float sc = __expf(m - p);
            acc.x = acc.x * sc + v.x; acc.y = acc.y * sc + v.y;
            acc.z = acc.z * sc + v.z; acc.w = acc.w * sc + v.w;
            d = d * sc + 1.f;
            m = p;
        }
        s = sn;
    }
    float inv = 1.f / d;
    float o0 = acc.x * inv, o1 = acc.y * inv, o2 = acc.z * inv, o3 = acc.w * inv;
#pragma unroll
    for (int off = 8; off <= 16; off <<= 1) {
        o0 += __shfl_xor_sync(0xffffffffu, o0, off);
        o1 += __shfl_xor_sync(0xffffffffu, o1, off);
        o2 += __shfl_xor_sync(0xffffffffu, o2, off);
        o3 += __shfl_xor_sync(0xffffffffu, o3, off);
    }
    if (lane < 8) {
        int c = 4 * lane;
        float4 o = make_float4(0.25f * o0 + bias[c + 0],
                               0.25f * o1 + bias[c + 1],
                               0.25f * o2 + bias[c + 2],
                               0.25f * o3 + bias[c + 3]);
        *(float4*)&OUT[n * 32 + c] = o;
    }
}

// ---------------------------------------------------------------------------
// Launch (layer-1 GEMM at index 3 -> ncu capture target)
// ---------------------------------------------------------------------------
extern "C" void kernel_launch(void* const* d_in, const int* in_sizes, int n_in,
                              void* d_out, int out_size) {
    const float* x   = (const float*)d_in[0];
    const int*   ei  = (const int*)  d_in[1];
    const float* W1l = (const float*)d_in[2];
    const float* W1r = (const float*)d_in[3];
    const float* a1  = (const float*)d_in[4];
    const float* b1  = (const float*)d_in[5];
    const float* W2l = (const float*)d_in[6];
    const float* W2r = (const float*)d_in[7];
    const float* a2  = (const float*)d_in[8];
    const float* b2  = (const float*)d_in[9];
    const float* W3l = (const float*)d_in[10];
    const float* W3r = (const float*)d_in[11];
    const float* a3  = (const float*)d_in[12];
    const float* b3  = (const float*)d_in[13];
    float* out = (float*)d_out;

    const int N = in_sizes[0] / 64;
    const int E = in_sizes[1] / 2;
    const int NB = (N + 1023) / 1024;

    float *xl, *xr, *h;
    unsigned char (*whi)[16384], (*wlo)[16384];
    cudaGetSymbolAddress((void**)&xl,  g_xl);
    cudaGetSymbolAddress((void**)&xr,  g_xr);
    cudaGetSymbolAddress((void**)&h,   g_h);
    cudaGetSymbolAddress((void**)&whi, g_wimg_hi);
    cudaGetSymbolAddress((void**)&wlo, g_wimg_lo);

    cudaFuncSetAttribute(k_mma,  cudaFuncAttributeMaxDynamicSharedMemorySize, SM_TOT);
    cudaFuncSetAttribute(k_mma3, cudaFuncAttributeMaxDynamicSharedMemorySize, SM3_TOT);

    const int GT = (N + 127) / 128;
    const int EB = (N + 7) / 8;
    const int ZB = (N + 255) / 256;

    // 0: init (zero cnt + W images)
    k_init<<<64 + ZB, 256>>>(W1l, W1r, W2l, W2r, W3l, W3r, N);
    // 1-2: CSR part 1
    k_hist<<<1024, 256>>>(ei, E);
    k_scan1<<<NB, 1024>>>(N);
    // 3: layer-1 GEMM (ncu capture target)
    k_mma<<<GT, 256, SM_TOT>>>(x, whi[0], wlo[0], xl, xr, N);
    // 4-5: CSR part 2
    k_scan3<<<NB, 1024>>>(N, E);
    k_scatter<<<1024, 256>>>(ei, E);
    // Layer 1 edge
    k_edge64<<<EB, 256>>>(xl, xr, a1, b1, h, N);
    // Layer 2
    k_mma<<<GT, 256, SM_TOT>>>(h, whi[1], wlo[1], xl, xr, N);
    k_edge64<<<EB, 256>>>(xl, xr, a2, b2, h, N);
    // Layer 3 (fused dual-N GEMM)
    k_mma3<<<GT, 512, SM3_TOT>>>(h, whi[2], wlo[2], whi[3], wlo[3], xl, xr, N);
    k_edge128_mean<<<EB, 256>>>(xl, xr, a3, b3, out, N);
}

// round 6
// speedup vs baseline: 1.5423x; 1.0770x over previous
#include <cuda_runtime.h>
#include <cuda_bf16.h>
#include <cstdint>

// Problem constants
#define NMAX 100000
#define EMAX 800000

// Scratch (no allocation allowed -> __device__ globals)
__device__ float g_xl[NMAX * 128];
__device__ float g_xr[NMAX * 128];
__device__ float g_h [NMAX * 64];
__device__ int   g_cnt[NMAX];
__device__ int   g_rowptr[NMAX + 1];
__device__ int   g_fill[NMAX];
__device__ int   g_adj[EMAX];
__device__ int   g_bsum[128];
// bf16 [n=128][k=64] images (XOR-swizzled), 4 operand sets:
// 0: [W1l|W1r], 1: [W2l|W2r], 2: W3l, 3: W3r
__device__ __align__(16) unsigned char g_wimg_hi[4][16384];
__device__ __align__(16) unsigned char g_wimg_lo[4][16384];

// ---------------------------------------------------------------------------
// helpers
// ---------------------------------------------------------------------------
__device__ __forceinline__ uint32_t smem_u32(const void* p) {
    uint32_t a;
    asm("{ .reg .u64 t; cvta.to.shared.u64 t, %1; cvt.u32.u64 %0, t; }" : "=r"(a) : "l"(p));
    return a;
}
__device__ __forceinline__ void bf16_split(float v, uint16_t& hi, uint16_t& lo) {
    __nv_bfloat16 h = __float2bfloat16(v);
    float residual = v - __bfloat162float(h);
    __nv_bfloat16 l = __float2bfloat16(residual);
    hi = *(uint16_t*)&h;
    lo = *(uint16_t*)&l;
}
__device__ __forceinline__ void ldm_x4(uint32_t (&r)[4], uint32_t addr) {
    asm volatile("ldmatrix.sync.aligned.m8n8.x4.shared.b16 {%0,%1,%2,%3}, [%4];"
                 : "=r"(r[0]), "=r"(r[1]), "=r"(r[2]), "=r"(r[3]) : "r"(addr));
}
__device__ __forceinline__ void mma_bf16(float (&d)[4], const uint32_t (&a)[4],
                                         uint32_t b0, uint32_t b1) {
    asm volatile(
        "mma.sync.aligned.m16n8k16.row.col.f32.bf16.bf16.f32 "
        "{%0,%1,%2,%3}, {%4,%5,%6,%7}, {%8,%9}, {%0,%1,%2,%3};"
        : "+f"(d[0]), "+f"(d[1]), "+f"(d[2]), "+f"(d[3])
        : "r"(a[0]), "r"(a[1]), "r"(a[2]), "r"(a[3]), "r"(b0), "r"(b1));
}
// XOR swizzle inside a 128B row: 16B chunk index XORed with (row&7)
__device__ __forceinline__ uint32_t swz_off(int row, int byte_in_row) {
    return (uint32_t)(row * 128 + (byte_in_row ^ ((row & 7) << 4)));
}

// ---------------------------------------------------------------------------
// k_init: g_cnt zero + W -> bf16 hi/lo images (fused)
// ---------------------------------------------------------------------------
__global__ void k_init(const float* __restrict__ W1l, const float* __restrict__ W1r,
                       const float* __restrict__ W2l, const float* __restrict__ W2r,
                       const float* __restrict__ W3l, const float* __restrict__ W3r,
                       int N) {
    if (blockIdx.x >= 64) {
        int i = (blockIdx.x - 64) * 256 + threadIdx.x;
        if (i < N) g_cnt[i] = 0;
        return;
    }
    int tid = blockIdx.x * 256 + threadIdx.x;   // 0..16383
    int img = tid >> 12, idx = tid & 4095;
    int n = idx >> 5, kp = idx & 31;
    int k0 = 2 * kp, k1 = k0 + 1;
    float v0, v1;
    if (img == 0) {
        v0 = (n < 64) ? W1l[k0 * 64 + n] : W1r[k0 * 64 + n - 64];
        v1 = (n < 64) ? W1l[k1 * 64 + n] : W1r[k1 * 64 + n - 64];
    } else if (img == 1) {
        v0 = (n < 64) ? W2l[k0 * 64 + n] : W2r[k0 * 64 + n - 64];
        v1 = (n < 64) ? W2l[k1 * 64 + n] : W2r[k1 * 64 + n - 64];
    } else if (img == 2) {
        v0 = W3l[k0 * 128 + n];
        v1 = W3l[k1 * 128 + n];
    } else {
        v0 = W3r[k0 * 128 + n];
        v1 = W3r[k1 * 128 + n];
    }
    uint16_t h0, l0, h1, l1;
    bf16_split(v0, h0, l0);
    bf16_split(v1, h1, l1);
    uint32_t off = swz_off(n, kp * 4);
    *(uint32_t*)(g_wimg_hi[img] + off) = (uint32_t)h0 | ((uint32_t)h1 << 16);
    *(uint32_t*)(g_wimg_lo[img] + off) = (uint32_t)l0 | ((uint32_t)l1 << 16);
}

// ---------------------------------------------------------------------------
// CSR build
// ---------------------------------------------------------------------------
__global__ void k_hist(const int* __restrict__ ei, int E) {
    for (int i = blockIdx.x * blockDim.x + threadIdx.x; i < E; i += gridDim.x * blockDim.x)
        atomicAdd(&g_cnt[ei[E + i]], 1);
}
__device__ __forceinline__ int block_scan_excl_1024(int val, int& total) {
    __shared__ int wsum[32];
    int lane = threadIdx.x & 31, w = threadIdx.x >> 5;
    int inc = val;
#pragma unroll
    for (int o = 1; o < 32; o <<= 1) {
        int u = __shfl_up_sync(0xffffffffu, inc, o);
        if (lane >= o) inc += u;
    }
    if (lane == 31) wsum[w] = inc;
    __syncthreads();
    if (w == 0) {
        int v = wsum[lane];
#pragma unroll
        for (int o = 1; o < 32; o <<= 1) {
            int u = __shfl_up_sync(0xffffffffu, v, o);
            if (lane >= o) v += u;
        }
        wsum[lane] = v;
    }
    __syncthreads();
    int off = (w > 0) ? wsum[w - 1] : 0;
    total = wsum[31];
    return off + inc - val;
}
__global__ void k_scan1(int N) {
    int idx = blockIdx.x * 1024 + threadIdx.x;
    int val = (idx < N) ? g_cnt[idx] : 0;
    int total;
    int ex = block_scan_excl_1024(val, total);
    if (idx < N) g_rowptr[idx] = ex;
    if (threadIdx.x == 0) g_bsum[blockIdx.x] = total;
}
// scan3 with inline reduction of preceding block totals (NB <= 128)
__global__ void k_scan3(int N, int E) {
    __shared__ int ws[4];
    __shared__ int s_off;
    int t = threadIdx.x;
    if (t < 128) {
        int v = (t < blockIdx.x) ? g_bsum[t] : 0;
#pragma unroll
        for (int o = 16; o > 0; o >>= 1) v += __shfl_xor_sync(0xffffffffu, v, o);
        if ((t & 31) == 0) ws[t >> 5] = v;
    }
    __syncthreads();
    if (t == 0) s_off = ws[0] + ws[1] + ws[2] + ws[3];
    __syncthreads();
    int idx = blockIdx.x * 1024 + t;
    if (idx < N) {
        int r = g_rowptr[idx] + s_off;
        g_rowptr[idx] = r;
        g_fill[idx]   = r;
    }
    if (idx == 0) g_rowptr[N] = E;
}
__global__ void k_scatter(const int* __restrict__ ei, int E) {
    for (int i = blockIdx.x * blockDim.x + threadIdx.x; i < E; i += gridDim.x * blockDim.x) {
        int d = ei[E + i];
        int p = atomicAdd(&g_fill[d], 1);
        g_adj[p] = ei[i];
    }
}

// ---------------------------------------------------------------------------
// HMMA GEMM (layers 1/2): Y[128 x 128] tile = X @ [Wl|Wr], 3-term bf16 split.
// __launch_bounds__(256,2): cap at 128 regs -> 2 CTAs/SM (occupancy fix).
// ---------------------------------------------------------------------------
#define SMA_HI 0
#define SMA_LO 16384
#define SMB_HI 32768
#define SMB_LO 49152
#define SM_TOT 65536

__global__ void __launch_bounds__(256, 2) k_mma(const float* __restrict__ X,
                                                const unsigned char* __restrict__ Bhi,
                                                const unsigned char* __restrict__ Blo,
                                                float* __restrict__ Y0,
                                                float* __restrict__ Y1, int N) {
    extern __shared__ char smem[];
    const uint32_t sb = smem_u32(smem);
    const int tid = threadIdx.x, wid = tid >> 5, lane = tid & 31;
    const int rowbase = blockIdx.x * 128;

    const uint4* bh = (const uint4*)Bhi;
    const uint4* bl = (const uint4*)Blo;
#pragma unroll
    for (int i = tid; i < 1024; i += 256) {
        ((uint4*)(smem + SMB_HI))[i] = bh[i];
        ((uint4*)(smem + SMB_LO))[i] = bl[i];
    }
#pragma unroll
    for (int i = tid; i < 4096; i += 256) {
        int r = i >> 5, kp = i & 31;
        int row = rowbase + r;
        float2 v = (row < N) ? *(const float2*)&X[row * 64 + 2 * kp] : make_float2(0.f, 0.f);
        uint16_t h0, l0, h1, l1;
        bf16_split(v.x, h0, l0);
        bf16_split(v.y, h1, l1);
        uint32_t off = swz_off(r, kp * 4);
        *(uint32_t*)(smem + SMA_HI + off) = (uint32_t)h0 | ((uint32_t)h1 << 16);
        *(uint32_t*)(smem + SMA_LO + off) = (uint32_t)l0 | ((uint32_t)l1 << 16);
    }
    __syncthreads();

    const int m0 = (wid & 3) * 32;
    const int n0 = (wid >> 2) * 64;
    const int rl  = lane & 7;
    const int grp = lane >> 3;

    float acc[2][8][4];
#pragma unroll
    for (int mt = 0; mt < 2; mt++)
#pragma unroll
        for (int nt = 0; nt < 8; nt++)
#pragma unroll
            for (int j = 0; j < 4; j++) acc[mt][nt][j] = 0.f;

    const uint32_t aBase[3] = { sb + SMA_HI, sb + SMA_LO, sb + SMA_HI };
    const uint32_t bBase[3] = { sb + SMB_HI, sb + SMB_HI, sb + SMB_LO };

#pragma unroll
    for (int t = 0; t < 3; t++) {
        const uint32_t ab = aBase[t], bb = bBase[t];
#pragma unroll
        for (int ks = 0; ks < 4; ks++) {
            const int cb = ks * 32;
            uint32_t a[2][4];
#pragma unroll
            for (int mt = 0; mt < 2; mt++) {
                int arow = m0 + mt * 16 + (grp & 1) * 8 + rl;
                int abyte = cb + (grp >> 1) * 16;
                ldm_x4(a[mt], ab + swz_off(arow, abyte));
            }
#pragma unroll
            for (int np = 0; np < 4; np++) {
                int brow = n0 + np * 16 + (grp >> 1) * 8 + rl;
                int bbyte = cb + (grp & 1) * 16;
                uint32_t b[4];
                ldm_x4(b, bb + swz_off(brow, bbyte));
                mma_bf16(acc[0][2 * np],     a[0], b[0], b[1]);
                mma_bf16(acc[1][2 * np],     a[1], b[0], b[1]);
                mma_bf16(acc[0][2 * np + 1], a[0], b[2], b[3]);
                mma_bf16(acc[1][2 * np + 1], a[1], b[2], b[3]);
            }
        }
    }

    const int qr = lane >> 2, qc = (lane & 3) * 2;
#pragma unroll
    for (int mt = 0; mt < 2; mt++) {
#pragma unroll
        for (int nt = 0; nt < 8; nt++) {
            int col = n0 + nt * 8 + qc;
            int row0 = rowbase + m0 + mt * 16 + qr;
#pragma unroll
            for (int h = 0; h < 2; h++) {
                int row = row0 + h * 8;
                if (row < N) {
                    float2 v = make_float2(acc[mt][nt][2 * h], acc[mt][nt][2 * h + 1]);
                    if (col < 64) *(float2*)&Y0[row * 64 + col] = v;
                    else          *(float2*)&Y1[row * 64 + col - 64] = v;
                }
            }
        }
    }
}

// ---------------------------------------------------------------------------
// Layer-3 fused GEMM: Y[128 x 256] = X @ [W3l | W3r] in ONE pass (512 thr).
// ---------------------------------------------------------------------------
#define SM3_AHI 0
#define SM3_ALO 16384
#define SM3_BHI 32768
#define SM3_BLO 65536
#define SM3_TOT 98304

__global__ void __launch_bounds__(512) k_mma3(const float* __restrict__ X,
                                              const unsigned char* __restrict__ Bhi2,
                                              const unsigned char* __restrict__ Blo2,
                                              const unsigned char* __restrict__ Bhi3,
                                              const unsigned char* __restrict__ Blo3,
                                              float* __restrict__ Y0,
                                              float* __restrict__ Y1, int N) {
    extern __shared__ char smem[];
    const uint32_t sb = smem_u32(smem);
    const int tid = threadIdx.x, wid = tid >> 5, lane = tid & 31;
    const int rowbase = blockIdx.x * 128;

#pragma unroll
    for (int i = tid; i < 2048; i += 512) {
        ((uint4*)(smem + SM3_BHI))[i] = (i < 1024) ? ((const uint4*)Bhi2)[i]
                                                   : ((const uint4*)Bhi3)[i - 1024];
        ((uint4*)(smem + SM3_BLO))[i] = (i < 1024) ? ((const uint4*)Blo2)[i]
                                                   : ((const uint4*)Blo3)[i - 1024];
    }
#pragma unroll
    for (int i = tid; i < 4096; i += 512) {
        int r = i >> 5, kp = i & 31;
        int row = rowbase + r;
        float2 v = (row < N) ? *(const float2*)&X[row * 64 + 2 * kp] : make_float2(0.f, 0.f);
        uint16_t h0, l0, h1, l1;
        bf16_split(v.x, h0, l0);
        bf16_split(v.y, h1, l1);
        uint32_t off = swz_off(r, kp * 4);
        *(uint32_t*)(smem + SM3_AHI + off) = (uint32_t)h0 | ((uint32_t)h1 << 16);
        *(uint32_t*)(smem + SM3_ALO + off) = (uint32_t)l0 | ((uint32_t)l1 << 16);
    }
    __syncthreads();

    const int m0 = (wid & 3) * 32;
    const int n0 = (wid >> 2) * 64;  // 0,64,128,192
    const int rl  = lane & 7;
    const int grp = lane >> 3;

    float acc[2][8][4];
#pragma unroll
    for (int mt = 0; mt < 2; mt++)
#pragma unroll
        for (int nt = 0; nt < 8; nt++)
#pragma unroll
            for (int j = 0; j < 4; j++) acc[mt][nt][j] = 0.f;

    const uint32_t aBase[3] = { sb + SM3_AHI, sb + SM3_ALO, sb + SM3_AHI };
    const uint32_t bBase[3] = { sb + SM3_BHI, sb + SM3_BHI, sb + SM3_BLO };

#pragma unroll
    for (int t = 0; t < 3; t++) {
        const uint32_t ab = aBase[t], bb = bBase[t];
#pragma unroll
        for (int ks = 0; ks < 4; ks++) {
            const int cb = ks * 32;
            uint32_t a[2][4];
#pragma unroll
            for (int mt = 0; mt < 2; mt++) {
                int arow = m0 + mt * 16 + (grp & 1) * 8 + rl;
                int abyte = cb + (grp >> 1) * 16;
                ldm_x4(a[mt], ab + swz_off(arow, abyte));
            }
#pragma unroll
            for (int np = 0; np < 4; np++) {
                int brow = n0 + np * 16 + (grp >> 1) * 8 + rl;
                int bbyte = cb + (grp & 1) * 16;
                uint32_t b[4];
                ldm_x4(b, bb + swz_off(brow, bbyte));
                mma_bf16(acc[0][2 * np],     a[0], b[0], b[1]);
                mma_bf16(acc[1][2 * np],     a[1], b[0], b[1]);
                mma_bf16(acc[0][2 * np + 1], a[0], b[2], b[3]);
                mma_bf16(acc[1][2 * np + 1], a[1], b[2], b[3]);
            }
        }
    }

    const int qr = lane >> 2, qc = (lane & 3) * 2;
#pragma unroll
    for (int mt = 0; mt < 2; mt++) {
#pragma unroll
        for (int nt = 0; nt < 8; nt++) {
            int col = n0 + nt * 8 + qc;
            int row0 = rowbase + m0 + mt * 16 + qr;
#pragma unroll
            for (int h = 0; h < 2; h++) {
                int row = row0 + h * 8;
                if (row < N) {
                    float2 v = make_float2(acc[mt][nt][2 * h], acc[mt][nt][2 * h + 1]);
                    if (col < 128) *(float2*)&Y0[row * 128 + col] = v;
                    else           *(float2*)&Y1[row * 128 + col - 128] = v;
                }
            }
        }
    }
}

// ---------------------------------------------------------------------------
// Fused GATv2 edge phase: warp per node; 4-edge software pipeline;
// branchless single-exp online-softmax update (no inter-head divergence).
// ---------------------------------------------------------------------------
__device__ __forceinline__ float leaky(float t) { return fmaxf(t, 0.2f * t); }

__device__ __forceinline__ float red8(float p) {
    p += __shfl_xor_sync(0xffffffffu, p, 4);
    p += __shfl_xor_sync(0xffffffffu, p, 2);
    p += __shfl_xor_sync(0xffffffffu, p, 1);
    return p;
}

__global__ void k_edge64(const float* __restrict__ XL, const float* __restrict__ XR,
                         const float* __restrict__ att, const float* __restrict__ bias,
                         float* __restrict__ OUT, int N) {
    int lane = threadIdx.x & 31;
    int n    = (blockIdx.x * blockDim.x + threadIdx.x) >> 5;
    if (n >= N) return;

    float a0 = att[2 * lane], a1 = att[2 * lane + 1];
    float2 xr = *(const float2*)&XR[n * 64 + 2 * lane];
    float2 vs = *(const float2*)&XL[n * 64 + 2 * lane];

    float m = red8(a0 * leaky(vs.x + xr.x) + a1 * leaky(vs.y + xr.y));
    float d = 1.f, ax = vs.x, ay = vs.y;

    auto upd = [&](float p, float2 v) {
        float mn = fmaxf(m, p);
        float e  = __expf(fminf(m, p) - mn);
        bool  gt = p > m;
        float wo = gt ? e : 1.f;
        float wn = gt ? 1.f : e;
        ax = ax * wo + wn * v.x;
        ay = ay * wo + wn * v.y;
        d  = d  * wo + wn;
        m  = mn;
    };

    int beg = g_rowptr[n], end = g_rowptr[n + 1];
    int i = beg;
    int s0 = 0, s1 = 0, s2 = 0, s3 = 0;
    if (i + 4 <= end) { s0 = g_adj[i]; s1 = g_adj[i+1]; s2 = g_adj[i+2]; s3 = g_adj[i+3]; }
    while (i + 4 <= end) {
        float2 v0 = *(const float2*)&XL[s0 * 64 + 2 * lane];
        float2 v1 = *(const float2*)&XL[s1 * 64 + 2 * lane];
        float2 v2 = *(const float2*)&XL[s2 * 64 + 2 * lane];
        float2 v3 = *(const float2*)&XL[s3 * 64 + 2 * lane];
        i += 4;
        if (i + 4 <= end) { s0 = g_adj[i]; s1 = g_adj[i+1]; s2 = g_adj[i+2]; s3 = g_adj[i+3]; }
        float p0 = a0 * leaky(v0.x + xr.x) + a1 * leaky(v0.y + xr.y);
        float p1 = a0 * leaky(v1.x + xr.x) + a1 * leaky(v1.y + xr.y);
        float p2 = a0 * leaky(v2.x + xr.x) + a1 * leaky(v2.y + xr.y);
        float p3 = a0 * leaky(v3.x + xr.x) + a1 * leaky(v3.y + xr.y);
#pragma unroll
        for (int o = 4; o > 0; o >>= 1) {
            p0 += __shfl_xor_sync(0xffffffffu, p0, o);
            p1 += __shfl_xor_sync(0xffffffffu, p1, o);
            p2 += __shfl_xor_sync(0xffffffffu, p2, o);
            p3 += __shfl_xor_sync(0xffffffffu, p3, o);
        }
        upd(p0, v0); upd(p1, v1); upd(p2, v2); upd(p3, v3);
    }
    for (; i < end; i++) {
        int s = g_adj[i];
        float2 v = *(const float2*)&XL[s * 64 + 2 * lane];
        float p = red8(a0 * leaky(v.x + xr.x) + a1 * leaky(v.y + xr.y));
        upd(p, v);
    }
    float inv = 1.f / d;
    float ox = ax * inv + bias[2 * lane];
    float oy = ay * inv + bias[2 * lane + 1];
    ox = ox > 0.f ? ox : (__expf(ox) - 1.f);
    oy = oy > 0.f ? oy : (__expf(oy) - 1.f);
    *(float2*)&OUT[n * 64 + 2 * lane] = make_float2(ox, oy);
}

__global__ void k_edge128_mean(const float* __restrict__ XL, const float* __restrict__ XR,
                               const float* __restrict__ att, const float* __restrict__ bias,
                               float* __restrict__ OUT, int N) {
    int lane = threadIdx.x & 31;
    int n    = (blockIdx.x * blockDim.x + threadIdx.x) >> 5;
    if (n >= N) return;

    float4 a  = *(const float4*)&att[4 * lane];
    float4 xr = *(const float4*)&XR[n * 128 + 4 * lane];
    float4 vs = *(const float4*)&XL[n * 128 + 4 * lane];

    auto score = [&](const float4& v) {
        return a.x * leaky(v.x + xr.x) + a.y * leaky(v.y + xr.y) +
               a.z * leaky(v.z + xr.z) + a.w * leaky(v.w + xr.w);
    };

    float m = red8(score(vs));
    float d = 1.f;
    float4 acc = vs;

    auto upd = [&](float p, const float4& v) {
        float mn = fmaxf(m, p);
        float e  = __expf(fminf(m, p) - mn);
        bool  gt = p > m;
        float wo = gt ? e : 1.f;
        float wn = gt ? 1.f : e;
        acc.x = acc.x * wo + wn * v.x;
        acc.y = acc.y * wo + wn * v.y;
        acc.z = acc.z * wo + wn * v.z;
        acc.w = acc.w * wo + wn * v.w;
        d = d * wo + wn;
        m = mn;
    };

    int beg = g_rowptr[n], end = g_rowptr[n + 1];
    int i = beg;
    int s0 = 0, s1 = 0, s2 = 0, s3 = 0;
    if (i + 4 <= end) { s0 = g_adj[i]; s1 = g_adj[i+1]; s2 = g_adj[i+2]; s3 = g_adj[i+3]; }
    while (i + 4 <= end) {
        float4 v0 = *(const float4*)&XL[s0 * 128 + 4 * lane];
        float4 v1 = *(const float4*)&XL[s1 * 128 + 4 * lane];
        float4 v2 = *(const float4*)&XL[s2 * 128 + 4 * lane];
        float4 v3 = *(const float4*)&XL[s3 * 128 + 4 * lane];
        i += 4;
        if (i + 4 <= end) { s0 = g_adj[i]; s1 = g_adj[i+1]; s2 = g_adj[i+2]; s3 = g_adj[i+3]; }
        float p0 = score(v0), p1 = score(v1), p2 = score(v2), p3 = score(v3);
#pragma unroll
        for (int o = 4; o > 0; o >>= 1) {
            p0 += __shfl_xor_sync(0xffffffffu, p0, o);
            p1 += __shfl_xor_sync(0xffffffffu, p1, o);
            p2 += __shfl_xor_sync(0xffffffffu, p2, o);
            p3 += __shfl_xor_sync(0xffffffffu, p3, o);
        }
        upd(p0, v0); upd(p1, v1); upd(p2, v2); upd(p3, v3);
    }
    for (; i < end; i++) {
        int s = g_adj[i];
        float4 v = *(const float4*)&XL[s * 128 + 4 * lane];
        float p = red8(score(v));
        upd(p, v);
    }
    float inv = 1.f / d;
    float o0 = acc.x * inv, o1 = acc.y * inv, o2 = acc.z * inv, o3 = acc.w * inv;
#pragma unroll
    for (int off = 8; off <= 16; off <<= 1) {
        o0 += __shfl_xor_sync(0xffffffffu, o0, off);
        o1 += __shfl_xor_sync(0xffffffffu, o1, off);
        o2 += __shfl_xor_sync(0xffffffffu, o2, off);
        o3 += __shfl_xor_sync(0xffffffffu, o3, off);
    }
    if (lane < 8) {
        int c = 4 * lane;
        float4 o = make_float4(0.25f * o0 + bias[c + 0],
                               0.25f * o1 + bias[c + 1],
                               0.25f * o2 + bias[c + 2],
                               0.25f * o3 + bias[c + 3]);
        *(float4*)&OUT[n * 32 + c] = o;
    }
}

// ---------------------------------------------------------------------------
// Launch (layer-1 GEMM at index 3 -> ncu capture target)
// ---------------------------------------------------------------------------
extern "C" void kernel_launch(void* const* d_in, const int* in_sizes, int n_in,
                              void* d_out, int out_size) {
    const float* x   = (const float*)d_in[0];
    const int*   ei  = (const int*)  d_in[1];
    const float* W1l = (const float*)d_in[2];
    const float* W1r = (const float*)d_in[3];
    const float* a1  = (const float*)d_in[4];
    const float* b1  = (const float*)d_in[5];
    const float* W2l = (const float*)d_in[6];
    const float* W2r = (const float*)d_in[7];
    const float* a2  = (const float*)d_in[8];
    const float* b2  = (const float*)d_in[9];
    const float* W3l = (const float*)d_in[10];
    const float* W3r = (const float*)d_in[11];
    const float* a3  = (const float*)d_in[12];
    const float* b3  = (const float*)d_in[13];
    float* out = (float*)d_out;

    const int N = in_sizes[0] / 64;
    const int E = in_sizes[1] / 2;
    const int NB = (N + 1023) / 1024;

    float *xl, *xr, *h;
    unsigned char (*whi)[16384], (*wlo)[16384];
    cudaGetSymbolAddress((void**)&xl,  g_xl);
    cudaGetSymbolAddress((void**)&xr,  g_xr);
    cudaGetSymbolAddress((void**)&h,   g_h);
    cudaGetSymbolAddress((void**)&whi, g_wimg_hi);
    cudaGetSymbolAddress((void**)&wlo, g_wimg_lo);

    cudaFuncSetAttribute(k_mma,  cudaFuncAttributeMaxDynamicSharedMemorySize, SM_TOT);
    cudaFuncSetAttribute(k_mma3, cudaFuncAttributeMaxDynamicSharedMemorySize, SM3_TOT);

    const int GT = (N + 127) / 128;
    const int EB = (N + 7) / 8;
    const int ZB = (N + 255) / 256;

    // 0: init (zero cnt + W images)
    k_init<<<64 + ZB, 256>>>(W1l, W1r, W2l, W2r, W3l, W3r, N);
    // 1-2: CSR part 1
    k_hist<<<1024, 256>>>(ei, E);
    k_scan1<<<NB, 1024>>>(N);
    // 3: layer-1 GEMM (ncu capture target)
    k_mma<<<GT, 256, SM_TOT>>>(x, whi[0], wlo[0], xl, xr, N);
    // 4-5: CSR part 2
    k_scan3<<<NB, 1024>>>(N, E);
    k_scatter<<<1024, 256>>>(ei, E);
    // Layer 1 edge
    k_edge64<<<EB, 256>>>(xl, xr, a1, b1, h, N);
    // Layer 2
    k_mma<<<GT, 256, SM_TOT>>>(h, whi[1], wlo[1], xl, xr, N);
    k_edge64<<<EB, 256>>>(xl, xr, a2, b2, h, N);
    // Layer 3 (fused dual-N GEMM)
    k_mma3<<<GT, 512, SM3_TOT>>>(h, whi[2], wlo[2], whi[3], wlo[3], xl, xr, N);
    k_edge128_mean<<<EB, 256>>>(xl, xr, a3, b3, out, N);
}

// round 7
// speedup vs baseline: 1.5575x; 1.0099x over previous
#include <cuda_runtime.h>
#include <cuda_bf16.h>
#include <cstdint>

// Problem constants
#define NMAX 100000
#define EMAX 800000

// Scratch (no allocation allowed -> __device__ globals)
__device__ float g_xl[NMAX * 128];
__device__ float g_xr[NMAX * 128];
__device__ float g_h [NMAX * 64];
__device__ int   g_cnt[NMAX];
__device__ int   g_rowptr[NMAX + 1];
__device__ int   g_fill[NMAX];
__device__ int   g_adj[EMAX];
__device__ int   g_bsum[128];
// bf16 [n=128][k=64] images (XOR-swizzled), 4 operand sets:
// 0: [W1l|W1r], 1: [W2l|W2r], 2: W3l, 3: W3r
__device__ __align__(16) unsigned char g_wimg_hi[4][16384];
__device__ __align__(16) unsigned char g_wimg_lo[4][16384];

// ---------------------------------------------------------------------------
// helpers
// ---------------------------------------------------------------------------
__device__ __forceinline__ uint32_t smem_u32(const void* p) {
    uint32_t a;
    asm("{ .reg .u64 t; cvta.to.shared.u64 t, %1; cvt.u32.u64 %0, t; }" : "=r"(a) : "l"(p));
    return a;
}
__device__ __forceinline__ void bf16_split(float v, uint16_t& hi, uint16_t& lo) {
    __nv_bfloat16 h = __float2bfloat16(v);
    float residual = v - __bfloat162float(h);
    __nv_bfloat16 l = __float2bfloat16(residual);
    hi = *(uint16_t*)&h;
    lo = *(uint16_t*)&l;
}
__device__ __forceinline__ void ldm_x4(uint32_t (&r)[4], uint32_t addr) {
    asm volatile("ldmatrix.sync.aligned.m8n8.x4.shared.b16 {%0,%1,%2,%3}, [%4];"
                 : "=r"(r[0]), "=r"(r[1]), "=r"(r[2]), "=r"(r[3]) : "r"(addr));
}
__device__ __forceinline__ void mma_bf16(float (&d)[4], const uint32_t (&a)[4],
                                         uint32_t b0, uint32_t b1) {
    asm volatile(
        "mma.sync.aligned.m16n8k16.row.col.f32.bf16.bf16.f32 "
        "{%0,%1,%2,%3}, {%4,%5,%6,%7}, {%8,%9}, {%0,%1,%2,%3};"
        : "+f"(d[0]), "+f"(d[1]), "+f"(d[2]), "+f"(d[3])
        : "r"(a[0]), "r"(a[1]), "r"(a[2]), "r"(a[3]), "r"(b0), "r"(b1));
}
// XOR swizzle inside a 128B row: 16B chunk index XORed with (row&7)
__device__ __forceinline__ uint32_t swz_off(int row, int byte_in_row) {
    return (uint32_t)(row * 128 + (byte_in_row ^ ((row & 7) << 4)));
}

// ---------------------------------------------------------------------------
// k_init: g_cnt zero + W -> bf16 hi/lo images (fused)
// ---------------------------------------------------------------------------
__global__ void k_init(const float* __restrict__ W1l, const float* __restrict__ W1r,
                       const float* __restrict__ W2l, const float* __restrict__ W2r,
                       const float* __restrict__ W3l, const float* __restrict__ W3r,
                       int N) {
    if (blockIdx.x >= 64) {
        int i = (blockIdx.x - 64) * 256 + threadIdx.x;
        if (i < N) g_cnt[i] = 0;
        return;
    }
    int tid = blockIdx.x * 256 + threadIdx.x;   // 0..16383
    int img = tid >> 12, idx = tid & 4095;
    int n = idx >> 5, kp = idx & 31;
    int k0 = 2 * kp, k1 = k0 + 1;
    float v0, v1;
    if (img == 0) {
        v0 = (n < 64) ? W1l[k0 * 64 + n] : W1r[k0 * 64 + n - 64];
        v1 = (n < 64) ? W1l[k1 * 64 + n] : W1r[k1 * 64 + n - 64];
    } else if (img == 1) {
        v0 = (n < 64) ? W2l[k0 * 64 + n] : W2r[k0 * 64 + n - 64];
        v1 = (n < 64) ? W2l[k1 * 64 + n] : W2r[k1 * 64 + n - 64];
    } else if (img == 2) {
        v0 = W3l[k0 * 128 + n];
        v1 = W3l[k1 * 128 + n];
    } else {
        v0 = W3r[k0 * 128 + n];
        v1 = W3r[k1 * 128 + n];
    }
    uint16_t h0, l0, h1, l1;
    bf16_split(v0, h0, l0);
    bf16_split(v1, h1, l1);
    uint32_t off = swz_off(n, kp * 4);
    *(uint32_t*)(g_wimg_hi[img] + off) = (uint32_t)h0 | ((uint32_t)h1 << 16);
    *(uint32_t*)(g_wimg_lo[img] + off) = (uint32_t)l0 | ((uint32_t)l1 << 16);
}

// ---------------------------------------------------------------------------
// CSR build
// ---------------------------------------------------------------------------
__global__ void k_hist(const int* __restrict__ ei, int E) {
    for (int i = blockIdx.x * blockDim.x + threadIdx.x; i < E; i += gridDim.x * blockDim.x)
        atomicAdd(&g_cnt[ei[E + i]], 1);
}
__device__ __forceinline__ int block_scan_excl_1024(int val, int& total) {
    __shared__ int wsum[32];
    int lane = threadIdx.x & 31, w = threadIdx.x >> 5;
    int inc = val;
#pragma unroll
    for (int o = 1; o < 32; o <<= 1) {
        int u = __shfl_up_sync(0xffffffffu, inc, o);
        if (lane >= o) inc += u;
    }
    if (lane == 31) wsum[w] = inc;
    __syncthreads();
    if (w == 0) {
        int v = wsum[lane];
#pragma unroll
        for (int o = 1; o < 32; o <<= 1) {
            int u = __shfl_up_sync(0xffffffffu, v, o);
            if (lane >= o) v += u;
        }
        wsum[lane] = v;
    }
    __syncthreads();
    int off = (w > 0) ? wsum[w - 1] : 0;
    total = wsum[31];
    return off + inc - val;
}
__global__ void k_scan1(int N) {
    int idx = blockIdx.x * 1024 + threadIdx.x;
    int val = (idx < N) ? g_cnt[idx] : 0;
    int total;
    int ex = block_scan_excl_1024(val, total);
    if (idx < N) g_rowptr[idx] = ex;
    if (threadIdx.x == 0) g_bsum[blockIdx.x] = total;
}
// scan3 with inline reduction of preceding block totals (NB <= 128)
__global__ void k_scan3(int N, int E) {
    __shared__ int ws[4];
    __shared__ int s_off;
    int t = threadIdx.x;
    if (t < 128) {
        int v = (t < blockIdx.x) ? g_bsum[t] : 0;
#pragma unroll
        for (int o = 16; o > 0; o >>= 1) v += __shfl_xor_sync(0xffffffffu, v, o);
        if ((t & 31) == 0) ws[t >> 5] = v;
    }
    __syncthreads();
    if (t == 0) s_off = ws[0] + ws[1] + ws[2] + ws[3];
    __syncthreads();
    int idx = blockIdx.x * 1024 + t;
    if (idx < N) {
        int r = g_rowptr[idx] + s_off;
        g_rowptr[idx] = r;
        g_fill[idx]   = r;
    }
    if (idx == 0) g_rowptr[N] = E;
}
__global__ void k_scatter(const int* __restrict__ ei, int E) {
    for (int i = blockIdx.x * blockDim.x + threadIdx.x; i < E; i += gridDim.x * blockDim.x) {
        int d = ei[E + i];
        int p = atomicAdd(&g_fill[d], 1);
        g_adj[p] = ei[i];
    }
}

// ---------------------------------------------------------------------------
// HMMA GEMM (layers 1/2): Y[128 x 128] tile = X @ [Wl|Wr], 3-term bf16 split.
// ---------------------------------------------------------------------------
#define SMA_HI 0
#define SMA_LO 16384
#define SMB_HI 32768
#define SMB_LO 49152
#define SM_TOT 65536

__global__ void __launch_bounds__(256, 2) k_mma(const float* __restrict__ X,
                                                const unsigned char* __restrict__ Bhi,
                                                const unsigned char* __restrict__ Blo,
                                                float* __restrict__ Y0,
                                                float* __restrict__ Y1, int N) {
    extern __shared__ char smem[];
    const uint32_t sb = smem_u32(smem);
    const int tid = threadIdx.x, wid = tid >> 5, lane = tid & 31;
    const int rowbase = blockIdx.x * 128;

    const uint4* bh = (const uint4*)Bhi;
    const uint4* bl = (const uint4*)Blo;
#pragma unroll
    for (int i = tid; i < 1024; i += 256) {
        ((uint4*)(smem + SMB_HI))[i] = bh[i];
        ((uint4*)(smem + SMB_LO))[i] = bl[i];
    }
#pragma unroll
    for (int i = tid; i < 4096; i += 256) {
        int r = i >> 5, kp = i & 31;
        int row = rowbase + r;
        float2 v = (row < N) ? *(const float2*)&X[row * 64 + 2 * kp] : make_float2(0.f, 0.f);
        uint16_t h0, l0, h1, l1;
        bf16_split(v.x, h0, l0);
        bf16_split(v.y, h1, l1);
        uint32_t off = swz_off(r, kp * 4);
        *(uint32_t*)(smem + SMA_HI + off) = (uint32_t)h0 | ((uint32_t)h1 << 16);
        *(uint32_t*)(smem + SMA_LO + off) = (uint32_t)l0 | ((uint32_t)l1 << 16);
    }
    __syncthreads();

    const int m0 = (wid & 3) * 32;
    const int n0 = (wid >> 2) * 64;
    const int rl  = lane & 7;
    const int grp = lane >> 3;

    float acc[2][8][4];
#pragma unroll
    for (int mt = 0; mt < 2; mt++)
#pragma unroll
        for (int nt = 0; nt < 8; nt++)
#pragma unroll
            for (int j = 0; j < 4; j++) acc[mt][nt][j] = 0.f;

    const uint32_t aBase[3] = { sb + SMA_HI, sb + SMA_LO, sb + SMA_HI };
    const uint32_t bBase[3] = { sb + SMB_HI, sb + SMB_HI, sb + SMB_LO };

#pragma unroll
    for (int t = 0; t < 3; t++) {
        const uint32_t ab = aBase[t], bb = bBase[t];
#pragma unroll
        for (int ks = 0; ks < 4; ks++) {
            const int cb = ks * 32;
            uint32_t a[2][4];
#pragma unroll
            for (int mt = 0; mt < 2; mt++) {
                int arow = m0 + mt * 16 + (grp & 1) * 8 + rl;
                int abyte = cb + (grp >> 1) * 16;
                ldm_x4(a[mt], ab + swz_off(arow, abyte));
            }
#pragma unroll
            for (int np = 0; np < 4; np++) {
                int brow = n0 + np * 16 + (grp >> 1) * 8 + rl;
                int bbyte = cb + (grp & 1) * 16;
                uint32_t b[4];
                ldm_x4(b, bb + swz_off(brow, bbyte));
                mma_bf16(acc[0][2 * np],     a[0], b[0], b[1]);
                mma_bf16(acc[1][2 * np],     a[1], b[0], b[1]);
                mma_bf16(acc[0][2 * np + 1], a[0], b[2], b[3]);
                mma_bf16(acc[1][2 * np + 1], a[1], b[2], b[3]);
            }
        }
    }

    const int qr = lane >> 2, qc = (lane & 3) * 2;
#pragma unroll
    for (int mt = 0; mt < 2; mt++) {
#pragma unroll
        for (int nt = 0; nt < 8; nt++) {
            int col = n0 + nt * 8 + qc;
            int row0 = rowbase + m0 + mt * 16 + qr;
#pragma unroll
            for (int h = 0; h < 2; h++) {
                int row = row0 + h * 8;
                if (row < N) {
                    float2 v = make_float2(acc[mt][nt][2 * h], acc[mt][nt][2 * h + 1]);
                    if (col < 64) *(float2*)&Y0[row * 64 + col] = v;
                    else          *(float2*)&Y1[row * 64 + col - 64] = v;
                }
            }
        }
    }
}

// ---------------------------------------------------------------------------
// Layer-3 fused GEMM: Y[128 x 256] = X @ [W3l | W3r] in ONE pass (512 thr).
// ---------------------------------------------------------------------------
#define SM3_AHI 0
#define SM3_ALO 16384
#define SM3_BHI 32768
#define SM3_BLO 65536
#define SM3_TOT 98304

__global__ void __launch_bounds__(512) k_mma3(const float* __restrict__ X,
                                              const unsigned char* __restrict__ Bhi2,
                                              const unsigned char* __restrict__ Blo2,
                                              const unsigned char* __restrict__ Bhi3,
                                              const unsigned char* __restrict__ Blo3,
                                              float* __restrict__ Y0,
                                              float* __restrict__ Y1, int N) {
    extern __shared__ char smem[];
    const uint32_t sb = smem_u32(smem);
    const int tid = threadIdx.x, wid = tid >> 5, lane = tid & 31;
    const int rowbase = blockIdx.x * 128;

#pragma unroll
    for (int i = tid; i < 2048; i += 512) {
        ((uint4*)(smem + SM3_BHI))[i] = (i < 1024) ? ((const uint4*)Bhi2)[i]
                                                   : ((const uint4*)Bhi3)[i - 1024];
        ((uint4*)(smem + SM3_BLO))[i] = (i < 1024) ? ((const uint4*)Blo2)[i]
                                                   : ((const uint4*)Blo3)[i - 1024];
    }
#pragma unroll
    for (int i = tid; i < 4096; i += 512) {
        int r = i >> 5, kp = i & 31;
        int row = rowbase + r;
        float2 v = (row < N) ? *(const float2*)&X[row * 64 + 2 * kp] : make_float2(0.f, 0.f);
        uint16_t h0, l0, h1, l1;
        bf16_split(v.x, h0, l0);
        bf16_split(v.y, h1, l1);
        uint32_t off = swz_off(r, kp * 4);
        *(uint32_t*)(smem + SM3_AHI + off) = (uint32_t)h0 | ((uint32_t)h1 << 16);
        *(uint32_t*)(smem + SM3_ALO + off) = (uint32_t)l0 | ((uint32_t)l1 << 16);
    }
    __syncthreads();

    const int m0 = (wid & 3) * 32;
    const int n0 = (wid >> 2) * 64;  // 0,64,128,192
    const int rl  = lane & 7;
    const int grp = lane >> 3;

    float acc[2][8][4];
#pragma unroll
    for (int mt = 0; mt < 2; mt++)
#pragma unroll
        for (int nt = 0; nt < 8; nt++)
#pragma unroll
            for (int j = 0; j < 4; j++) acc[mt][nt][j] = 0.f;

    const uint32_t aBase[3] = { sb + SM3_AHI, sb + SM3_ALO, sb + SM3_AHI };
    const uint32_t bBase[3] = { sb + SM3_BHI, sb + SM3_BHI, sb + SM3_BLO };

#pragma unroll
    for (int t = 0; t < 3; t++) {
        const uint32_t ab = aBase[t], bb = bBase[t];
#pragma unroll
        for (int ks = 0; ks < 4; ks++) {
            const int cb = ks * 32;
            uint32_t a[2][4];
#pragma unroll
            for (int mt = 0; mt < 2; mt++) {
                int arow = m0 + mt * 16 + (grp & 1) * 8 + rl;
                int abyte = cb + (grp >> 1) * 16;
                ldm_x4(a[mt], ab + swz_off(arow, abyte));
            }
#pragma unroll
            for (int np = 0; np < 4; np++) {
                int brow = n0 + np * 16 + (grp >> 1) * 8 + rl;
                int bbyte = cb + (grp & 1) * 16;
                uint32_t b[4];
                ldm_x4(b, bb + swz_off(brow, bbyte));
                mma_bf16(acc[0][2 * np],     a[0], b[0], b[1]);
                mma_bf16(acc[1][2 * np],     a[1], b[0], b[1]);
                mma_bf16(acc[0][2 * np + 1], a[0], b[2], b[3]);
                mma_bf16(acc[1][2 * np + 1], a[1], b[2], b[3]);
            }
        }
    }

    const int qr = lane >> 2, qc = (lane & 3) * 2;
#pragma unroll
    for (int mt = 0; mt < 2; mt++) {
#pragma unroll
        for (int nt = 0; nt < 8; nt++) {
            int col = n0 + nt * 8 + qc;
            int row0 = rowbase + m0 + mt * 16 + qr;
#pragma unroll
            for (int h = 0; h < 2; h++) {
                int row = row0 + h * 8;
                if (row < N) {
                    float2 v = make_float2(acc[mt][nt][2 * h], acc[mt][nt][2 * h + 1]);
                    if (col < 128) *(float2*)&Y0[row * 128 + col] = v;
                    else           *(float2*)&Y1[row * 128 + col - 128] = v;
                }
            }
        }
    }
}

// ---------------------------------------------------------------------------
// Fused GATv2 edge phase: warp per node; 4-edge pipeline with BLOCK-MERGED
// online softmax (one accumulator rescale per quad, flash-attention style).
// ---------------------------------------------------------------------------
__device__ __forceinline__ float leaky(float t) { return fmaxf(t, 0.2f * t); }

__device__ __forceinline__ float red8(float p) {
    p += __shfl_xor_sync(0xffffffffu, p, 4);
    p += __shfl_xor_sync(0xffffffffu, p, 2);
    p += __shfl_xor_sync(0xffffffffu, p, 1);
    return p;
}

__global__ void k_edge64(const float* __restrict__ XL, const float* __restrict__ XR,
                         const float* __restrict__ att, const float* __restrict__ bias,
                         float* __restrict__ OUT, int N) {
    int lane = threadIdx.x & 31;
    int n    = (blockIdx.x * blockDim.x + threadIdx.x) >> 5;
    if (n >= N) return;

    float a0 = att[2 * lane], a1 = att[2 * lane + 1];
    float2 xr = *(const float2*)&XR[n * 64 + 2 * lane];
    float2 vs = *(const float2*)&XL[n * 64 + 2 * lane];

    float m = red8(a0 * leaky(vs.x + xr.x) + a1 * leaky(vs.y + xr.y));
    float d = 1.f, ax = vs.x, ay = vs.y;

    int beg = g_rowptr[n], end = g_rowptr[n + 1];
    int i = beg;
    int s0 = 0, s1 = 0, s2 = 0, s3 = 0;
    if (i + 4 <= end) { s0 = g_adj[i]; s1 = g_adj[i+1]; s2 = g_adj[i+2]; s3 = g_adj[i+3]; }
    while (i + 4 <= end) {
        float2 v0 = *(const float2*)&XL[s0 * 64 + 2 * lane];
        float2 v1 = *(const float2*)&XL[s1 * 64 + 2 * lane];
        float2 v2 = *(const float2*)&XL[s2 * 64 + 2 * lane];
        float2 v3 = *(const float2*)&XL[s3 * 64 + 2 * lane];
        i += 4;
        if (i + 4 <= end) { s0 = g_adj[i]; s1 = g_adj[i+1]; s2 = g_adj[i+2]; s3 = g_adj[i+3]; }
        float p0 = a0 * leaky(v0.x + xr.x) + a1 * leaky(v0.y + xr.y);
        float p1 = a0 * leaky(v1.x + xr.x) + a1 * leaky(v1.y + xr.y);
        float p2 = a0 * leaky(v2.x + xr.x) + a1 * leaky(v2.y + xr.y);
        float p3 = a0 * leaky(v3.x + xr.x) + a1 * leaky(v3.y + xr.y);
#pragma unroll
        for (int o = 4; o > 0; o >>= 1) {
            p0 += __shfl_xor_sync(0xffffffffu, p0, o);
            p1 += __shfl_xor_sync(0xffffffffu, p1, o);
            p2 += __shfl_xor_sync(0xffffffffu, p2, o);
            p3 += __shfl_xor_sync(0xffffffffu, p3, o);
        }
        // block-merged online softmax: one rescale per quad
        float mq = fmaxf(fmaxf(p0, p1), fmaxf(p2, p3));
        float mn = fmaxf(m, mq);
        float w  = __expf(m - mn);
        float e0 = __expf(p0 - mn), e1 = __expf(p1 - mn);
        float e2 = __expf(p2 - mn), e3 = __expf(p3 - mn);
        float sx = (e0 * v0.x + e1 * v1.x) + (e2 * v2.x + e3 * v3.x);
        float sy = (e0 * v0.y + e1 * v1.y) + (e2 * v2.y + e3 * v3.y);
        ax = ax * w + sx;
        ay = ay * w + sy;
        d  = d  * w + ((e0 + e1) + (e2 + e3));
        m  = mn;
    }
    for (; i < end; i++) {
        int s = g_adj[i];
        float2 v = *(const float2*)&XL[s * 64 + 2 * lane];
        float p = red8(a0 * leaky(v.x + xr.x) + a1 * leaky(v.y + xr.y));
        float mn = fmaxf(m, p);
        float w  = __expf(m - mn);
        float e  = __expf(p - mn);
        ax = ax * w + e * v.x;
        ay = ay * w + e * v.y;
        d  = d  * w + e;
        m  = mn;
    }
    float inv = 1.f / d;
    float ox = ax * inv + bias[2 * lane];
    float oy = ay * inv + bias[2 * lane + 1];
    ox = ox > 0.f ? ox : (__expf(ox) - 1.f);
    oy = oy > 0.f ? oy : (__expf(oy) - 1.f);
    *(float2*)&OUT[n * 64 + 2 * lane] = make_float2(ox, oy);
}

__global__ void k_edge128_mean(const float* __restrict__ XL, const float* __restrict__ XR,
                               const float* __restrict__ att, const float* __restrict__ bias,
                               float* __restrict__ OUT, int N) {
    int lane = threadIdx.x & 31;
    int n    = (blockIdx.x * blockDim.x + threadIdx.x) >> 5;
    if (n >= N) return;

    float4 a  = *(const float4*)&att[4 * lane];
    float4 xr = *(const float4*)&XR[n * 128 + 4 * lane];
    float4 vs = *(const float4*)&XL[n * 128 + 4 * lane];

    auto score = [&](const float4& v) {
        return a.x * leaky(v.x + xr.x) + a.y * leaky(v.y + xr.y) +
               a.z * leaky(v.z + xr.z) + a.w * leaky(v.w + xr.w);
    };

    float m = red8(score(vs));
    float d = 1.f;
    float4 acc = vs;

    int beg = g_rowptr[n], end = g_rowptr[n + 1];
    int i = beg;
    int s0 = 0, s1 = 0, s2 = 0, s3 = 0;
    if (i + 4 <= end) { s0 = g_adj[i]; s1 = g_adj[i+1]; s2 = g_adj[i+2]; s3 = g_adj[i+3]; }
    while (i + 4 <= end) {
        float4 v0 = *(const float4*)&XL[s0 * 128 + 4 * lane];
        float4 v1 = *(const float4*)&XL[s1 * 128 + 4 * lane];
        float4 v2 = *(const float4*)&XL[s2 * 128 + 4 * lane];
        float4 v3 = *(const float4*)&XL[s3 * 128 + 4 * lane];
        i += 4;
        if (i + 4 <= end) { s0 = g_adj[i]; s1 = g_adj[i+1]; s2 = g_adj[i+2]; s3 = g_adj[i+3]; }
        float p0 = score(v0), p1 = score(v1), p2 = score(v2), p3 = score(v3);
#pragma unroll
        for (int o = 4; o > 0; o >>= 1) {
            p0 += __shfl_xor_sync(0xffffffffu, p0, o);
            p1 += __shfl_xor_sync(0xffffffffu, p1, o);
            p2 += __shfl_xor_sync(0xffffffffu, p2, o);
            p3 += __shfl_xor_sync(0xffffffffu, p3, o);
        }
        float mq = fmaxf(fmaxf(p0, p1), fmaxf(p2, p3));
        float mn = fmaxf(m, mq);
        float w  = __expf(m - mn);
        float e0 = __expf(p0 - mn), e1 = __expf(p1 - mn);
        float e2 = __expf(p2 - mn), e3 = __expf(p3 - mn);
        acc.x = acc.x * w + (e0 * v0.x + e1 * v1.x) + (e2 * v2.x + e3 * v3.x);
        acc.y = acc.y * w + (e0 * v0.y + e1 * v1.y) + (e2 * v2.y + e3 * v3.y);
        acc.z = acc.z * w + (e0 * v0.z + e1 * v1.z) + (e2 * v2.z + e3 * v3.z);
        acc.w = acc.w * w + (e0 * v0.w + e1 * v1.w) + (e2 * v2.w + e3 * v3.w);
        d = d * w + ((e0 + e1) + (e2 + e3));
        m = mn;
    }
    for (; i < end; i++) {
        int s = g_adj[i];
        float4 v = *(const float4*)&XL[s * 128 + 4 * lane];
        float p = red8(score(v));
        float mn = fmaxf(m, p);
        float w  = __expf(m - mn);
        float e  = __expf(p - mn);
        acc.x = acc.x * w + e * v.x;
        acc.y = acc.y * w + e * v.y;
        acc.z = acc.z * w + e * v.z;
        acc.w = acc.w * w + e * v.w;
        d = d * w + e;
        m = mn;
    }
    float inv = 1.f / d;
    float o0 = acc.x * inv, o1 = acc.y * inv, o2 = acc.z * inv, o3 = acc.w * inv;
#pragma unroll
    for (int off = 8; off <= 16; off <<= 1) {
        o0 += __shfl_xor_sync(0xffffffffu, o0, off);
        o1 += __shfl_xor_sync(0xffffffffu, o1, off);
        o2 += __shfl_xor_sync(0xffffffffu, o2, off);
        o3 += __shfl_xor_sync(0xffffffffu, o3, off);
    }
    if (lane < 8) {
        int c = 4 * lane;
        float4 o = make_float4(0.25f * o0 + bias[c + 0],
                               0.25f * o1 + bias[c + 1],
                               0.25f * o2 + bias[c + 2],
                               0.25f * o3 + bias[c + 3]);
        *(float4*)&OUT[n * 32 + c] = o;
    }
}

// ---------------------------------------------------------------------------
// Launch (layer-1 GEMM at index 3 -> ncu capture target)
// ---------------------------------------------------------------------------
extern "C" void kernel_launch(void* const* d_in, const int* in_sizes, int n_in,
                              void* d_out, int out_size) {
    const float* x   = (const float*)d_in[0];
    const int*   ei  = (const int*)  d_in[1];
    const float* W1l = (const float*)d_in[2];
    const float* W1r = (const float*)d_in[3];
    const float* a1  = (const float*)d_in[4];
    const float* b1  = (const float*)d_in[5];
    const float* W2l = (const float*)d_in[6];
    const float* W2r = (const float*)d_in[7];
    const float* a2  = (const float*)d_in[8];
    const float* b2  = (const float*)d_in[9];
    const float* W3l = (const float*)d_in[10];
    const float* W3r = (const float*)d_in[11];
    const float* a3  = (const float*)d_in[12];
    const float* b3  = (const float*)d_in[13];
    float* out = (float*)d_out;

    const int N = in_sizes[0] / 64;
    const int E = in_sizes[1] / 2;
    const int NB = (N + 1023) / 1024;

    float *xl, *xr, *h;
    unsigned char (*whi)[16384], (*wlo)[16384];
    cudaGetSymbolAddress((void**)&xl,  g_xl);
    cudaGetSymbolAddress((void**)&xr,  g_xr);
    cudaGetSymbolAddress((void**)&h,   g_h);
    cudaGetSymbolAddress((void**)&whi, g_wimg_hi);
    cudaGetSymbolAddress((void**)&wlo, g_wimg_lo);

    cudaFuncSetAttribute(k_mma,  cudaFuncAttributeMaxDynamicSharedMemorySize, SM_TOT);
    cudaFuncSetAttribute(k_mma3, cudaFuncAttributeMaxDynamicSharedMemorySize, SM3_TOT);

    const int GT = (N + 127) / 128;
    const int EB = (N + 7) / 8;
    const int ZB = (N + 255) / 256;

    // 0: init (zero cnt + W images)
    k_init<<<64 + ZB, 256>>>(W1l, W1r, W2l, W2r, W3l, W3r, N);
    // 1-2: CSR part 1
    k_hist<<<1024, 256>>>(ei, E);
    k_scan1<<<NB, 1024>>>(N);
    // 3: layer-1 GEMM (ncu capture target)
    k_mma<<<GT, 256, SM_TOT>>>(x, whi[0], wlo[0], xl, xr, N);
    // 4-5: CSR part 2
    k_scan3<<<NB, 1024>>>(N, E);
    k_scatter<<<1024, 256>>>(ei, E);
    // Layer 1 edge
    k_edge64<<<EB, 256>>>(xl, xr, a1, b1, h, N);
    // Layer 2
    k_mma<<<GT, 256, SM_TOT>>>(h, whi[1], wlo[1], xl, xr, N);
    k_edge64<<<EB, 256>>>(xl, xr, a2, b2, h, N);
    // Layer 3 (fused dual-N GEMM)
    k_mma3<<<GT, 512, SM3_TOT>>>(h, whi[2], wlo[2], whi[3], wlo[3], xl, xr, N);
    k_edge128_mean<<<EB, 256>>>(xl, xr, a3, b3, out, N);
}

// round 8
// speedup vs baseline: 1.7316x; 1.1118x over previous
#include <cuda_runtime.h>
#include <cuda_bf16.h>
#include <cuda_fp16.h>
#include <cstdint>

// Problem constants
#define NMAX 100000
#define EMAX 800000

// Scratch (no allocation allowed -> __device__ globals)
__device__ float g_xl[NMAX * 128];     // reused as fp16 xl (half2) buffers
__device__ float g_xr[NMAX * 128];     // fp32 xr
__device__ float g_h [NMAX * 64];
__device__ int   g_cnt[NMAX];
__device__ int   g_rowptr[NMAX + 1];
__device__ int   g_fill[NMAX];
__device__ int   g_adj[EMAX];
__device__ int   g_bsum[128];
// bf16 [n=128][k=64] images (XOR-swizzled), 4 operand sets:
// 0: [W1l|W1r], 1: [W2l|W2r], 2: W3l, 3: W3r
__device__ __align__(16) unsigned char g_wimg_hi[4][16384];
__device__ __align__(16) unsigned char g_wimg_lo[4][16384];

// ---------------------------------------------------------------------------
// helpers
// ---------------------------------------------------------------------------
__device__ __forceinline__ uint32_t smem_u32(const void* p) {
    uint32_t a;
    asm("{ .reg .u64 t; cvta.to.shared.u64 t, %1; cvt.u32.u64 %0, t; }" : "=r"(a) : "l"(p));
    return a;
}
__device__ __forceinline__ void bf16_split(float v, uint16_t& hi, uint16_t& lo) {
    __nv_bfloat16 h = __float2bfloat16(v);
    float residual = v - __bfloat162float(h);
    __nv_bfloat16 l = __float2bfloat16(residual);
    hi = *(uint16_t*)&h;
    lo = *(uint16_t*)&l;
}
__device__ __forceinline__ void ldm_x4(uint32_t (&r)[4], uint32_t addr) {
    asm volatile("ldmatrix.sync.aligned.m8n8.x4.shared.b16 {%0,%1,%2,%3}, [%4];"
                 : "=r"(r[0]), "=r"(r[1]), "=r"(r[2]), "=r"(r[3]) : "r"(addr));
}
__device__ __forceinline__ void mma_bf16(float (&d)[4], const uint32_t (&a)[4],
                                         uint32_t b0, uint32_t b1) {
    asm volatile(
        "mma.sync.aligned.m16n8k16.row.col.f32.bf16.bf16.f32 "
        "{%0,%1,%2,%3}, {%4,%5,%6,%7}, {%8,%9}, {%0,%1,%2,%3};"
        : "+f"(d[0]), "+f"(d[1]), "+f"(d[2]), "+f"(d[3])
        : "r"(a[0]), "r"(a[1]), "r"(a[2]), "r"(a[3]), "r"(b0), "r"(b1));
}
// XOR swizzle inside a 128B row: 16B chunk index XORed with (row&7)
__device__ __forceinline__ uint32_t swz_off(int row, int byte_in_row) {
    return (uint32_t)(row * 128 + (byte_in_row ^ ((row & 7) << 4)));
}

// ---------------------------------------------------------------------------
// k_init: g_cnt zero + W -> bf16 hi/lo images (fused)
// ---------------------------------------------------------------------------
__global__ void k_init(const float* __restrict__ W1l, const float* __restrict__ W1r,
                       const float* __restrict__ W2l, const float* __restrict__ W2r,
                       const float* __restrict__ W3l, const float* __restrict__ W3r,
                       int N) {
    if (blockIdx.x >= 64) {
        int i = (blockIdx.x - 64) * 256 + threadIdx.x;
        if (i < N) g_cnt[i] = 0;
        return;
    }
    int tid = blockIdx.x * 256 + threadIdx.x;   // 0..16383
    int img = tid >> 12, idx = tid & 4095;
    int n = idx >> 5, kp = idx & 31;
    int k0 = 2 * kp, k1 = k0 + 1;
    float v0, v1;
    if (img == 0) {
        v0 = (n < 64) ? W1l[k0 * 64 + n] : W1r[k0 * 64 + n - 64];
        v1 = (n < 64) ? W1l[k1 * 64 + n] : W1r[k1 * 64 + n - 64];
    } else if (img == 1) {
        v0 = (n < 64) ? W2l[k0 * 64 + n] : W2r[k0 * 64 + n - 64];
        v1 = (n < 64) ? W2l[k1 * 64 + n] : W2r[k1 * 64 + n - 64];
    } else if (img == 2) {
        v0 = W3l[k0 * 128 + n];
        v1 = W3l[k1 * 128 + n];
    } else {
        v0 = W3r[k0 * 128 + n];
        v1 = W3r[k1 * 128 + n];
    }
    uint16_t h0, l0, h1, l1;
    bf16_split(v0, h0, l0);
    bf16_split(v1, h1, l1);
    uint32_t off = swz_off(n, kp * 4);
    *(uint32_t*)(g_wimg_hi[img] + off) = (uint32_t)h0 | ((uint32_t)h1 << 16);
    *(uint32_t*)(g_wimg_lo[img] + off) = (uint32_t)l0 | ((uint32_t)l1 << 16);
}

// ---------------------------------------------------------------------------
// CSR build
// ---------------------------------------------------------------------------
__global__ void k_hist(const int* __restrict__ ei, int E) {
    for (int i = blockIdx.x * blockDim.x + threadIdx.x; i < E; i += gridDim.x * blockDim.x)
        atomicAdd(&g_cnt[ei[E + i]], 1);
}
__device__ __forceinline__ int block_scan_excl_1024(int val, int& total) {
    __shared__ int wsum[32];
    int lane = threadIdx.x & 31, w = threadIdx.x >> 5;
    int inc = val;
#pragma unroll
    for (int o = 1; o < 32; o <<= 1) {
        int u = __shfl_up_sync(0xffffffffu, inc, o);
        if (lane >= o) inc += u;
    }
    if (lane == 31) wsum[w] = inc;
    __syncthreads();
    if (w == 0) {
        int v = wsum[lane];
#pragma unroll
        for (int o = 1; o < 32; o <<= 1) {
            int u = __shfl_up_sync(0xffffffffu, v, o);
            if (lane >= o) v += u;
        }
        wsum[lane] = v;
    }
    __syncthreads();
    int off = (w > 0) ? wsum[w - 1] : 0;
    total = wsum[31];
    return off + inc - val;
}
__global__ void k_scan1(int N) {
    int idx = blockIdx.x * 1024 + threadIdx.x;
    int val = (idx < N) ? g_cnt[idx] : 0;
    int total;
    int ex = block_scan_excl_1024(val, total);
    if (idx < N) g_rowptr[idx] = ex;
    if (threadIdx.x == 0) g_bsum[blockIdx.x] = total;
}
// scan3 with inline reduction of preceding block totals (NB <= 128)
__global__ void k_scan3(int N, int E) {
    __shared__ int ws[4];
    __shared__ int s_off;
    int t = threadIdx.x;
    if (t < 128) {
        int v = (t < blockIdx.x) ? g_bsum[t] : 0;
#pragma unroll
        for (int o = 16; o > 0; o >>= 1) v += __shfl_xor_sync(0xffffffffu, v, o);
        if ((t & 31) == 0) ws[t >> 5] = v;
    }
    __syncthreads();
    if (t == 0) s_off = ws[0] + ws[1] + ws[2] + ws[3];
    __syncthreads();
    int idx = blockIdx.x * 1024 + t;
    if (idx < N) {
        int r = g_rowptr[idx] + s_off;
        g_rowptr[idx] = r;
        g_fill[idx]   = r;
    }
    if (idx == 0) g_rowptr[N] = E;
}
__global__ void k_scatter(const int* __restrict__ ei, int E) {
    for (int i = blockIdx.x * blockDim.x + threadIdx.x; i < E; i += gridDim.x * blockDim.x) {
        int d = ei[E + i];
        int p = atomicAdd(&g_fill[d], 1);
        g_adj[p] = ei[i];
    }
}

// ---------------------------------------------------------------------------
// HMMA GEMM (layers 1/2): Y[128 x 128] tile = X @ [Wl|Wr], 3-term bf16 split.
// Restructured mainloop: Ahi/Alo frags hoisted per k-step, all 3 terms issued
// from one load set (ldmatrix count 72 -> 48 per warp).
// Epilogue: cols<64 -> fp16 xl (half2), cols>=64 -> fp32 xr.
// ---------------------------------------------------------------------------
#define SMA_HI 0
#define SMA_LO 16384
#define SMB_HI 32768
#define SMB_LO 49152
#define SM_TOT 65536

__global__ void __launch_bounds__(256, 2) k_mma(const float* __restrict__ X,
                                                const unsigned char* __restrict__ Bhi,
                                                const unsigned char* __restrict__ Blo,
                                                __half2* __restrict__ Y0h,
                                                float* __restrict__ Y1, int N) {
    extern __shared__ char smem[];
    const uint32_t sb = smem_u32(smem);
    const int tid = threadIdx.x, wid = tid >> 5, lane = tid & 31;
    const int rowbase = blockIdx.x * 128;

    const uint4* bh = (const uint4*)Bhi;
    const uint4* bl = (const uint4*)Blo;
#pragma unroll
    for (int i = tid; i < 1024; i += 256) {
        ((uint4*)(smem + SMB_HI))[i] = bh[i];
        ((uint4*)(smem + SMB_LO))[i] = bl[i];
    }
#pragma unroll
    for (int i = tid; i < 4096; i += 256) {
        int r = i >> 5, kp = i & 31;
        int row = rowbase + r;
        float2 v = (row < N) ? *(const float2*)&X[row * 64 + 2 * kp] : make_float2(0.f, 0.f);
        uint16_t h0, l0, h1, l1;
        bf16_split(v.x, h0, l0);
        bf16_split(v.y, h1, l1);
        uint32_t off = swz_off(r, kp * 4);
        *(uint32_t*)(smem + SMA_HI + off) = (uint32_t)h0 | ((uint32_t)h1 << 16);
        *(uint32_t*)(smem + SMA_LO + off) = (uint32_t)l0 | ((uint32_t)l1 << 16);
    }
    __syncthreads();

    const int m0 = (wid & 3) * 32;
    const int n0 = (wid >> 2) * 64;
    const int rl  = lane & 7;
    const int grp = lane >> 3;

    float acc[2][8][4];
#pragma unroll
    for (int mt = 0; mt < 2; mt++)
#pragma unroll
        for (int nt = 0; nt < 8; nt++)
#pragma unroll
            for (int j = 0; j < 4; j++) acc[mt][nt][j] = 0.f;

#pragma unroll
    for (int ks = 0; ks < 4; ks++) {
        const int cb = ks * 32;
        uint32_t ahi[2][4], alo[2][4];
#pragma unroll
        for (int mt = 0; mt < 2; mt++) {
            int arow = m0 + mt * 16 + (grp & 1) * 8 + rl;
            int abyte = cb + (grp >> 1) * 16;
            ldm_x4(ahi[mt], sb + SMA_HI + swz_off(arow, abyte));
            ldm_x4(alo[mt], sb + SMA_LO + swz_off(arow, abyte));
        }
#pragma unroll
        for (int np = 0; np < 4; np++) {
            int brow = n0 + np * 16 + (grp >> 1) * 8 + rl;
            int bbyte = cb + (grp & 1) * 16;
            uint32_t bhi[4], blo[4];
            ldm_x4(bhi, sb + SMB_HI + swz_off(brow, bbyte));
            ldm_x4(blo, sb + SMB_LO + swz_off(brow, bbyte));
            // term 0: Ahi * Bhi
            mma_bf16(acc[0][2 * np],     ahi[0], bhi[0], bhi[1]);
            mma_bf16(acc[1][2 * np],     ahi[1], bhi[0], bhi[1]);
            mma_bf16(acc[0][2 * np + 1], ahi[0], bhi[2], bhi[3]);
            mma_bf16(acc[1][2 * np + 1], ahi[1], bhi[2], bhi[3]);
            // term 1: Alo * Bhi
            mma_bf16(acc[0][2 * np],     alo[0], bhi[0], bhi[1]);
            mma_bf16(acc[1][2 * np],     alo[1], bhi[0], bhi[1]);
            mma_bf16(acc[0][2 * np + 1], alo[0], bhi[2], bhi[3]);
            mma_bf16(acc[1][2 * np + 1], alo[1], bhi[2], bhi[3]);
            // term 2: Ahi * Blo
            mma_bf16(acc[0][2 * np],     ahi[0], blo[0], blo[1]);
            mma_bf16(acc[1][2 * np],     ahi[1], blo[0], blo[1]);
            mma_bf16(acc[0][2 * np + 1], ahi[0], blo[2], blo[3]);
            mma_bf16(acc[1][2 * np + 1], ahi[1], blo[2], blo[3]);
        }
    }

    const int qr = lane >> 2, qc = (lane & 3) * 2;
#pragma unroll
    for (int mt = 0; mt < 2; mt++) {
#pragma unroll
        for (int nt = 0; nt < 8; nt++) {
            int col = n0 + nt * 8 + qc;
            int row0 = rowbase + m0 + mt * 16 + qr;
#pragma unroll
            for (int h = 0; h < 2; h++) {
                int row = row0 + h * 8;
                if (row < N) {
                    float vx = acc[mt][nt][2 * h], vy = acc[mt][nt][2 * h + 1];
                    if (col < 64) Y0h[row * 32 + (col >> 1)] = __floats2half2_rn(vx, vy);
                    else          *(float2*)&Y1[row * 64 + col - 64] = make_float2(vx, vy);
                }
            }
        }
    }
}

// ---------------------------------------------------------------------------
// Layer-3 fused GEMM: Y[128 x 256] = X @ [W3l | W3r] in ONE pass (512 thr).
// Epilogue: cols<128 -> fp16 xl, cols>=128 -> fp32 xr.
// ---------------------------------------------------------------------------
#define SM3_AHI 0
#define SM3_ALO 16384
#define SM3_BHI 32768
#define SM3_BLO 65536
#define SM3_TOT 98304

__global__ void __launch_bounds__(512) k_mma3(const float* __restrict__ X,
                                              const unsigned char* __restrict__ Bhi2,
                                              const unsigned char* __restrict__ Blo2,
                                              const unsigned char* __restrict__ Bhi3,
                                              const unsigned char* __restrict__ Blo3,
                                              __half2* __restrict__ Y0h,
                                              float* __restrict__ Y1, int N) {
    extern __shared__ char smem[];
    const uint32_t sb = smem_u32(smem);
    const int tid = threadIdx.x, wid = tid >> 5, lane = tid & 31;
    const int rowbase = blockIdx.x * 128;

#pragma unroll
    for (int i = tid; i < 2048; i += 512) {
        ((uint4*)(smem + SM3_BHI))[i] = (i < 1024) ? ((const uint4*)Bhi2)[i]
                                                   : ((const uint4*)Bhi3)[i - 1024];
        ((uint4*)(smem + SM3_BLO))[i] = (i < 1024) ? ((const uint4*)Blo2)[i]
                                                   : ((const uint4*)Blo3)[i - 1024];
    }
#pragma unroll
    for (int i = tid; i < 4096; i += 512) {
        int r = i >> 5, kp = i & 31;
        int row = rowbase + r;
        float2 v = (row < N) ? *(const float2*)&X[row * 64 + 2 * kp] : make_float2(0.f, 0.f);
        uint16_t h0, l0, h1, l1;
        bf16_split(v.x, h0, l0);
        bf16_split(v.y, h1, l1);
        uint32_t off = swz_off(r, kp * 4);
        *(uint32_t*)(smem + SM3_AHI + off) = (uint32_t)h0 | ((uint32_t)h1 << 16);
        *(uint32_t*)(smem + SM3_ALO + off) = (uint32_t)l0 | ((uint32_t)l1 << 16);
    }
    __syncthreads();

    const int m0 = (wid & 3) * 32;
    const int n0 = (wid >> 2) * 64;  // 0,64,128,192
    const int rl  = lane & 7;
    const int grp = lane >> 3;

    float acc[2][8][4];
#pragma unroll
    for (int mt = 0; mt < 2; mt++)
#pragma unroll
        for (int nt = 0; nt < 8; nt++)
#pragma unroll
            for (int j = 0; j < 4; j++) acc[mt][nt][j] = 0.f;

#pragma unroll
    for (int ks = 0; ks < 4; ks++) {
        const int cb = ks * 32;
        uint32_t ahi[2][4], alo[2][4];
#pragma unroll
        for (int mt = 0; mt < 2; mt++) {
            int arow = m0 + mt * 16 + (grp & 1) * 8 + rl;
            int abyte = cb + (grp >> 1) * 16;
            ldm_x4(ahi[mt], sb + SM3_AHI + swz_off(arow, abyte));
            ldm_x4(alo[mt], sb + SM3_ALO + swz_off(arow, abyte));
        }
#pragma unroll
        for (int np = 0; np < 4; np++) {
            int brow = n0 + np * 16 + (grp >> 1) * 8 + rl;
            int bbyte = cb + (grp & 1) * 16;
            uint32_t bhi[4], blo[4];
            ldm_x4(bhi, sb + SM3_BHI + swz_off(brow, bbyte));
            ldm_x4(blo, sb + SM3_BLO + swz_off(brow, bbyte));
            mma_bf16(acc[0][2 * np],     ahi[0], bhi[0], bhi[1]);
            mma_bf16(acc[1][2 * np],     ahi[1], bhi[0], bhi[1]);
            mma_bf16(acc[0][2 * np + 1], ahi[0], bhi[2], bhi[3]);
            mma_bf16(acc[1][2 * np + 1], ahi[1], bhi[2], bhi[3]);
            mma_bf16(acc[0][2 * np],     alo[0], bhi[0], bhi[1]);
            mma_bf16(acc[1][2 * np],     alo[1], bhi[0], bhi[1]);
            mma_bf16(acc[0][2 * np + 1], alo[0], bhi[2], bhi[3]);
            mma_bf16(acc[1][2 * np + 1], alo[1], bhi[2], bhi[3]);
            mma_bf16(acc[0][2 * np],     ahi[0], blo[0], blo[1]);
            mma_bf16(acc[1][2 * np],     ahi[1], blo[0], blo[1]);
            mma_bf16(acc[0][2 * np + 1], ahi[0], blo[2], blo[3]);
            mma_bf16(acc[1][2 * np + 1], ahi[1], blo[2], blo[3]);
        }
    }

    const int qr = lane >> 2, qc = (lane & 3) * 2;
#pragma unroll
    for (int mt = 0; mt < 2; mt++) {
#pragma unroll
        for (int nt = 0; nt < 8; nt++) {
            int col = n0 + nt * 8 + qc;
            int row0 = rowbase + m0 + mt * 16 + qr;
#pragma unroll
            for (int h = 0; h < 2; h++) {
                int row = row0 + h * 8;
                if (row < N) {
                    float vx = acc[mt][nt][2 * h], vy = acc[mt][nt][2 * h + 1];
                    if (col < 128) Y0h[row * 64 + (col >> 1)] = __floats2half2_rn(vx, vy);
                    else           *(float2*)&Y1[row * 128 + col - 128] = make_float2(vx, vy);
                }
            }
        }
    }
}

// ---------------------------------------------------------------------------
// Fused GATv2 edge phase: warp per node; 4-edge pipeline; fp16 gathers;
// block-merged online softmax.
// ---------------------------------------------------------------------------
__device__ __forceinline__ float leaky(float t) { return fmaxf(t, 0.2f * t); }

__device__ __forceinline__ float red8(float p) {
    p += __shfl_xor_sync(0xffffffffu, p, 4);
    p += __shfl_xor_sync(0xffffffffu, p, 2);
    p += __shfl_xor_sync(0xffffffffu, p, 1);
    return p;
}

__global__ void k_edge64(const __half2* __restrict__ XLH, const float* __restrict__ XR,
                         const float* __restrict__ att, const float* __restrict__ bias,
                         float* __restrict__ OUT, int N) {
    int lane = threadIdx.x & 31;
    int n    = (blockIdx.x * blockDim.x + threadIdx.x) >> 5;
    if (n >= N) return;

    float a0 = att[2 * lane], a1 = att[2 * lane + 1];
    float2 xr = *(const float2*)&XR[n * 64 + 2 * lane];
    float2 vs = __half22float2(XLH[n * 32 + lane]);

    float m = red8(a0 * leaky(vs.x + xr.x) + a1 * leaky(vs.y + xr.y));
    float d = 1.f, ax = vs.x, ay = vs.y;

    int beg = g_rowptr[n], end = g_rowptr[n + 1];
    int i = beg;
    int s0 = 0, s1 = 0, s2 = 0, s3 = 0;
    if (i + 4 <= end) { s0 = g_adj[i]; s1 = g_adj[i+1]; s2 = g_adj[i+2]; s3 = g_adj[i+3]; }
    while (i + 4 <= end) {
        float2 v0 = __half22float2(XLH[s0 * 32 + lane]);
        float2 v1 = __half22float2(XLH[s1 * 32 + lane]);
        float2 v2 = __half22float2(XLH[s2 * 32 + lane]);
        float2 v3 = __half22float2(XLH[s3 * 32 + lane]);
        i += 4;
        if (i + 4 <= end) { s0 = g_adj[i]; s1 = g_adj[i+1]; s2 = g_adj[i+2]; s3 = g_adj[i+3]; }
        float p0 = a0 * leaky(v0.x + xr.x) + a1 * leaky(v0.y + xr.y);
        float p1 = a0 * leaky(v1.x + xr.x) + a1 * leaky(v1.y + xr.y);
        float p2 = a0 * leaky(v2.x + xr.x) + a1 * leaky(v2.y + xr.y);
        float p3 = a0 * leaky(v3.x + xr.x) + a1 * leaky(v3.y + xr.y);
#pragma unroll
        for (int o = 4; o > 0; o >>= 1) {
            p0 += __shfl_xor_sync(0xffffffffu, p0, o);
            p1 += __shfl_xor_sync(0xffffffffu, p1, o);
            p2 += __shfl_xor_sync(0xffffffffu, p2, o);
            p3 += __shfl_xor_sync(0xffffffffu, p3, o);
        }
        float mq = fmaxf(fmaxf(p0, p1), fmaxf(p2, p3));
        float mn = fmaxf(m, mq);
        float w  = __expf(m - mn);
        float e0 = __expf(p0 - mn), e1 = __expf(p1 - mn);
        float e2 = __expf(p2 - mn), e3 = __expf(p3 - mn);
        ax = ax * w + (e0 * v0.x + e1 * v1.x) + (e2 * v2.x + e3 * v3.x);
        ay = ay * w + (e0 * v0.y + e1 * v1.y) + (e2 * v2.y + e3 * v3.y);
        d  = d  * w + ((e0 + e1) + (e2 + e3));
        m  = mn;
    }
    for (; i < end; i++) {
        int s = g_adj[i];
        float2 v = __half22float2(XLH[s * 32 + lane]);
        float p = red8(a0 * leaky(v.x + xr.x) + a1 * leaky(v.y + xr.y));
        float mn = fmaxf(m, p);
        float w  = __expf(m - mn);
        float e  = __expf(p - mn);
        ax = ax * w + e * v.x;
        ay = ay * w + e * v.y;
        d  = d  * w + e;
        m  = mn;
    }
    float inv = 1.f / d;
    float ox = ax * inv + bias[2 * lane];
    float oy = ay * inv + bias[2 * lane + 1];
    ox = ox > 0.f ? ox : (__expf(ox) - 1.f);
    oy = oy > 0.f ? oy : (__expf(oy) - 1.f);
    *(float2*)&OUT[n * 64 + 2 * lane] = make_float2(ox, oy);
}

__device__ __forceinline__ float4 h2f4(uint2 u) {
    float2 lohalf = __half22float2(*(__half2*)&u.x);
    float2 hihalf = __half22float2(*(__half2*)&u.y);
    return make_float4(lohalf.x, lohalf.y, hihalf.x, hihalf.y);
}

__global__ void k_edge128_mean(const __half2* __restrict__ XLH, const float* __restrict__ XR,
                               const float* __restrict__ att, const float* __restrict__ bias,
                               float* __restrict__ OUT, int N) {
    int lane = threadIdx.x & 31;
    int n    = (blockIdx.x * blockDim.x + threadIdx.x) >> 5;
    if (n >= N) return;

    float4 a  = *(const float4*)&att[4 * lane];
    float4 xr = *(const float4*)&XR[n * 128 + 4 * lane];
    float4 vs = h2f4(*(const uint2*)&XLH[n * 64 + 2 * lane]);

    auto score = [&](const float4& v) {
        return a.x * leaky(v.x + xr.x) + a.y * leaky(v.y + xr.y) +
               a.z * leaky(v.z + xr.z) + a.w * leaky(v.w + xr.w);
    };

    float m = red8(score(vs));
    float d = 1.f;
    float4 acc = vs;

    int beg = g_rowptr[n], end = g_rowptr[n + 1];
    int i = beg;
    int s0 = 0, s1 = 0, s2 = 0, s3 = 0;
    if (i + 4 <= end) { s0 = g_adj[i]; s1 = g_adj[i+1]; s2 = g_adj[i+2]; s3 = g_adj[i+3]; }
    while (i + 4 <= end) {
        float4 v0 = h2f4(*(const uint2*)&XLH[s0 * 64 + 2 * lane]);
        float4 v1 = h2f4(*(const uint2*)&XLH[s1 * 64 + 2 * lane]);
        float4 v2 = h2f4(*(const uint2*)&XLH[s2 * 64 + 2 * lane]);
        float4 v3 = h2f4(*(const uint2*)&XLH[s3 * 64 + 2 * lane]);
        i += 4;
        if (i + 4 <= end) { s0 = g_adj[i]; s1 = g_adj[i+1]; s2 = g_adj[i+2]; s3 = g_adj[i+3]; }
        float p0 = score(v0), p1 = score(v1), p2 = score(v2), p3 = score(v3);
#pragma unroll
        for (int o = 4; o > 0; o >>= 1) {
            p0 += __shfl_xor_sync(0xffffffffu, p0, o);
            p1 += __shfl_xor_sync(0xffffffffu, p1, o);
            p2 += __shfl_xor_sync(0xffffffffu, p2, o);
            p3 += __shfl_xor_sync(0xffffffffu, p3, o);
        }
        float mq = fmaxf(fmaxf(p0, p1), fmaxf(p2, p3));
        float mn = fmaxf(m, mq);
        float w  = __expf(m - mn);
        float e0 = __expf(p0 - mn), e1 = __expf(p1 - mn);
        float e2 = __expf(p2 - mn), e3 = __expf(p3 - mn);
        acc.x = acc.x * w + (e0 * v0.x + e1 * v1.x) + (e2 * v2.x + e3 * v3.x);
        acc.y = acc.y * w + (e0 * v0.y + e1 * v1.y) + (e2 * v2.y + e3 * v3.y);
        acc.z = acc.z * w + (e0 * v0.z + e1 * v1.z) + (e2 * v2.z + e3 * v3.z);
        acc.w = acc.w * w + (e0 * v0.w + e1 * v1.w) + (e2 * v2.w + e3 * v3.w);
        d = d * w + ((e0 + e1) + (e2 + e3));
        m = mn;
    }
    for (; i < end; i++) {
        int s = g_adj[i];
        float4 v = h2f4(*(const uint2*)&XLH[s * 64 + 2 * lane]);
        float p = red8(score(v));
        float mn = fmaxf(m, p);
        float w  = __expf(m - mn);
        float e  = __expf(p - mn);
        acc.x = acc.x * w + e * v.x;
        acc.y = acc.y * w + e * v.y;
        acc.z = acc.z * w + e * v.z;
        acc.w = acc.w * w + e * v.w;
        d = d * w + e;
        m = mn;
    }
    float inv = 1.f / d;
    float o0 = acc.x * inv, o1 = acc.y * inv, o2 = acc.z * inv, o3 = acc.w * inv;
#pragma unroll
    for (int off = 8; off <= 16; off <<= 1) {
        o0 += __shfl_xor_sync(0xffffffffu, o0, off);
        o1 += __shfl_xor_sync(0xffffffffu, o1, off);
        o2 += __shfl_xor_sync(0xffffffffu, o2, off);
        o3 += __shfl_xor_sync(0xffffffffu, o3, off);
    }
    if (lane < 8) {
        int c = 4 * lane;
        float4 o = make_float4(0.25f * o0 + bias[c + 0],
                               0.25f * o1 + bias[c + 1],
                               0.25f * o2 + bias[c + 2],
                               0.25f * o3 + bias[c + 3]);
        *(float4*)&OUT[n * 32 + c] = o;
    }
}

// ---------------------------------------------------------------------------
// Launch (layer-1 GEMM at index 3 -> ncu capture target)
// ---------------------------------------------------------------------------
extern "C" void kernel_launch(void* const* d_in, const int* in_sizes, int n_in,
                              void* d_out, int out_size) {
    const float* x   = (const float*)d_in[0];
    const int*   ei  = (const int*)  d_in[1];
    const float* W1l = (const float*)d_in[2];
    const float* W1r = (const float*)d_in[3];
    const float* a1  = (const float*)d_in[4];
    const float* b1  = (const float*)d_in[5];
    const float* W2l = (const float*)d_in[6];
    const float* W2r = (const float*)d_in[7];
    const float* a2  = (const float*)d_in[8];
    const float* b2  = (const float*)d_in[9];
    const float* W3l = (const float*)d_in[10];
    const float* W3r = (const float*)d_in[11];
    const float* a3  = (const float*)d_in[12];
    const float* b3  = (const float*)d_in[13];
    float* out = (float*)d_out;

    const int N = in_sizes[0] / 64;
    const int E = in_sizes[1] / 2;
    const int NB = (N + 1023) / 1024;

    float *xlf, *xr, *h;
    unsigned char (*whi)[16384], (*wlo)[16384];
    cudaGetSymbolAddress((void**)&xlf, g_xl);
    cudaGetSymbolAddress((void**)&xr,  g_xr);
    cudaGetSymbolAddress((void**)&h,   g_h);
    cudaGetSymbolAddress((void**)&whi, g_wimg_hi);
    cudaGetSymbolAddress((void**)&wlo, g_wimg_lo);
    __half2* xlh = (__half2*)xlf;

    cudaFuncSetAttribute(k_mma,  cudaFuncAttributeMaxDynamicSharedMemorySize, SM_TOT);
    cudaFuncSetAttribute(k_mma3, cudaFuncAttributeMaxDynamicSharedMemorySize, SM3_TOT);

    const int GT = (N + 127) / 128;
    const int EB = (N + 7) / 8;
    const int ZB = (N + 255) / 256;

    // 0: init (zero cnt + W images)
    k_init<<<64 + ZB, 256>>>(W1l, W1r, W2l, W2r, W3l, W3r, N);
    // 1-2: CSR part 1
    k_hist<<<1024, 256>>>(ei, E);
    k_scan1<<<NB, 1024>>>(N);
    // 3: layer-1 GEMM (ncu capture target)
    k_mma<<<GT, 256, SM_TOT>>>(x, whi[0], wlo[0], xlh, xr, N);
    // 4-5: CSR part 2
    k_scan3<<<NB, 1024>>>(N, E);
    k_scatter<<<1024, 256>>>(ei, E);
    // Layer 1 edge
    k_edge64<<<EB, 256>>>(xlh, xr, a1, b1, h, N);
    // Layer 2
    k_mma<<<GT, 256, SM_TOT>>>(h, whi[1], wlo[1], xlh, xr, N);
    k_edge64<<<EB, 256>>>(xlh, xr, a2, b2, h, N);
    // Layer 3 (fused dual-N GEMM)
    k_mma3<<<GT, 512, SM3_TOT>>>(h, whi[2], wlo[2], whi[3], wlo[3], xlh, xr, N);
    k_edge128_mean<<<EB, 256>>>(xlh, xr, a3, b3, out, N);
}

// round 9
// speedup vs baseline: 1.7867x; 1.0319x over previous
#include <cuda_runtime.h>
#include <cuda_bf16.h>
#include <cuda_fp16.h>
#include <cstdint>

// Problem constants
#define NMAX 100000
#define EMAX 800000

// Scratch (no allocation allowed -> __device__ globals)
__device__ float g_xl[NMAX * 128];     // reused as fp16 xl (half2) buffers
__device__ float g_xr[NMAX * 128];     // fp32 xr
__device__ float g_h [NMAX * 64];
__device__ int   g_cnt[NMAX];
__device__ int   g_rowptr[NMAX + 1];
__device__ int   g_fill[NMAX];
__device__ int   g_adj[EMAX];
__device__ int   g_bsum[128];
// bf16 [n=128][k=64] images (XOR-swizzled), 4 operand sets:
// 0: [W1l|W1r], 1: [W2l|W2r], 2: W3l, 3: W3r
__device__ __align__(16) unsigned char g_wimg_hi[4][16384];
__device__ __align__(16) unsigned char g_wimg_lo[4][16384];

// ---------------------------------------------------------------------------
// helpers
// ---------------------------------------------------------------------------
__device__ __forceinline__ uint32_t smem_u32(const void* p) {
    uint32_t a;
    asm("{ .reg .u64 t; cvta.to.shared.u64 t, %1; cvt.u32.u64 %0, t; }" : "=r"(a) : "l"(p));
    return a;
}
__device__ __forceinline__ void bf16_split(float v, uint16_t& hi, uint16_t& lo) {
    __nv_bfloat16 h = __float2bfloat16(v);
    float residual = v - __bfloat162float(h);
    __nv_bfloat16 l = __float2bfloat16(residual);
    hi = *(uint16_t*)&h;
    lo = *(uint16_t*)&l;
}
__device__ __forceinline__ void ldm_x4(uint32_t (&r)[4], uint32_t addr) {
    asm volatile("ldmatrix.sync.aligned.m8n8.x4.shared.b16 {%0,%1,%2,%3}, [%4];"
                 : "=r"(r[0]), "=r"(r[1]), "=r"(r[2]), "=r"(r[3]) : "r"(addr));
}
__device__ __forceinline__ void mma_bf16(float (&d)[4], const uint32_t (&a)[4],
                                         uint32_t b0, uint32_t b1) {
    asm volatile(
        "mma.sync.aligned.m16n8k16.row.col.f32.bf16.bf16.f32 "
        "{%0,%1,%2,%3}, {%4,%5,%6,%7}, {%8,%9}, {%0,%1,%2,%3};"
        : "+f"(d[0]), "+f"(d[1]), "+f"(d[2]), "+f"(d[3])
        : "r"(a[0]), "r"(a[1]), "r"(a[2]), "r"(a[3]), "r"(b0), "r"(b1));
}
// XOR swizzle inside a 128B row: 16B chunk index XORed with (row&7)
__device__ __forceinline__ uint32_t swz_off(int row, int byte_in_row) {
    return (uint32_t)(row * 128 + (byte_in_row ^ ((row & 7) << 4)));
}

// ---------------------------------------------------------------------------
// k_init: g_cnt zero + W -> bf16 hi/lo images (fused)
// ---------------------------------------------------------------------------
__global__ void k_init(const float* __restrict__ W1l, const float* __restrict__ W1r,
                       const float* __restrict__ W2l, const float* __restrict__ W2r,
                       const float* __restrict__ W3l, const float* __restrict__ W3r,
                       int N) {
    if (blockIdx.x >= 64) {
        int i = (blockIdx.x - 64) * 256 + threadIdx.x;
        if (i < N) g_cnt[i] = 0;
        return;
    }
    int tid = blockIdx.x * 256 + threadIdx.x;   // 0..16383
    int img = tid >> 12, idx = tid & 4095;
    int n = idx >> 5, kp = idx & 31;
    int k0 = 2 * kp, k1 = k0 + 1;
    float v0, v1;
    if (img == 0) {
        v0 = (n < 64) ? W1l[k0 * 64 + n] : W1r[k0 * 64 + n - 64];
        v1 = (n < 64) ? W1l[k1 * 64 + n] : W1r[k1 * 64 + n - 64];
    } else if (img == 1) {
        v0 = (n < 64) ? W2l[k0 * 64 + n] : W2r[k0 * 64 + n - 64];
        v1 = (n < 64) ? W2l[k1 * 64 + n] : W2r[k1 * 64 + n - 64];
    } else if (img == 2) {
        v0 = W3l[k0 * 128 + n];
        v1 = W3l[k1 * 128 + n];
    } else {
        v0 = W3r[k0 * 128 + n];
        v1 = W3r[k1 * 128 + n];
    }
    uint16_t h0, l0, h1, l1;
    bf16_split(v0, h0, l0);
    bf16_split(v1, h1, l1);
    uint32_t off = swz_off(n, kp * 4);
    *(uint32_t*)(g_wimg_hi[img] + off) = (uint32_t)h0 | ((uint32_t)h1 << 16);
    *(uint32_t*)(g_wimg_lo[img] + off) = (uint32_t)l0 | ((uint32_t)l1 << 16);
}

// ---------------------------------------------------------------------------
// CSR build
// ---------------------------------------------------------------------------
__global__ void k_hist(const int* __restrict__ ei, int E) {
    for (int i = blockIdx.x * blockDim.x + threadIdx.x; i < E; i += gridDim.x * blockDim.x)
        atomicAdd(&g_cnt[ei[E + i]], 1);
}
__device__ __forceinline__ int block_scan_excl_1024(int val, int& total) {
    __shared__ int wsum[32];
    int lane = threadIdx.x & 31, w = threadIdx.x >> 5;
    int inc = val;
#pragma unroll
    for (int o = 1; o < 32; o <<= 1) {
        int u = __shfl_up_sync(0xffffffffu, inc, o);
        if (lane >= o) inc += u;
    }
    if (lane == 31) wsum[w] = inc;
    __syncthreads();
    if (w == 0) {
        int v = wsum[lane];
#pragma unroll
        for (int o = 1; o < 32; o <<= 1) {
            int u = __shfl_up_sync(0xffffffffu, v, o);
            if (lane >= o) v += u;
        }
        wsum[lane] = v;
    }
    __syncthreads();
    int off = (w > 0) ? wsum[w - 1] : 0;
    total = wsum[31];
    return off + inc - val;
}
__global__ void k_scan1(int N) {
    int idx = blockIdx.x * 1024 + threadIdx.x;
    int val = (idx < N) ? g_cnt[idx] : 0;
    int total;
    int ex = block_scan_excl_1024(val, total);
    if (idx < N) g_rowptr[idx] = ex;
    if (threadIdx.x == 0) g_bsum[blockIdx.x] = total;
}
// scan3 with inline reduction of preceding block totals (NB <= 128)
__global__ void k_scan3(int N, int E) {
    __shared__ int ws[4];
    __shared__ int s_off;
    int t = threadIdx.x;
    if (t < 128) {
        int v = (t < blockIdx.x) ? g_bsum[t] : 0;
#pragma unroll
        for (int o = 16; o > 0; o >>= 1) v += __shfl_xor_sync(0xffffffffu, v, o);
        if ((t & 31) == 0) ws[t >> 5] = v;
    }
    __syncthreads();
    if (t == 0) s_off = ws[0] + ws[1] + ws[2] + ws[3];
    __syncthreads();
    int idx = blockIdx.x * 1024 + t;
    if (idx < N) {
        int r = g_rowptr[idx] + s_off;
        g_rowptr[idx] = r;
        g_fill[idx]   = r;
    }
    if (idx == 0) g_rowptr[N] = E;
}
__global__ void k_scatter(const int* __restrict__ ei, int E) {
    for (int i = blockIdx.x * blockDim.x + threadIdx.x; i < E; i += gridDim.x * blockDim.x) {
        int d = ei[E + i];
        int p = atomicAdd(&g_fill[d], 1);
        g_adj[p] = ei[i];
    }
}

// ---------------------------------------------------------------------------
// HMMA GEMM (layers 1/2): Y[128 x 128] tile = X @ [Wl|Wr], 3-term bf16 split.
// Epilogue: cols<64 -> fp16 xl (half2), cols>=64 -> fp32 xr.
// ---------------------------------------------------------------------------
#define SMA_HI 0
#define SMA_LO 16384
#define SMB_HI 32768
#define SMB_LO 49152
#define SM_TOT 65536

__global__ void __launch_bounds__(256, 2) k_mma(const float* __restrict__ X,
                                                const unsigned char* __restrict__ Bhi,
                                                const unsigned char* __restrict__ Blo,
                                                __half2* __restrict__ Y0h,
                                                float* __restrict__ Y1, int N) {
    extern __shared__ char smem[];
    const uint32_t sb = smem_u32(smem);
    const int tid = threadIdx.x, wid = tid >> 5, lane = tid & 31;
    const int rowbase = blockIdx.x * 128;

    const uint4* bh = (const uint4*)Bhi;
    const uint4* bl = (const uint4*)Blo;
#pragma unroll
    for (int i = tid; i < 1024; i += 256) {
        ((uint4*)(smem + SMB_HI))[i] = bh[i];
        ((uint4*)(smem + SMB_LO))[i] = bl[i];
    }
#pragma unroll
    for (int i = tid; i < 4096; i += 256) {
        int r = i >> 5, kp = i & 31;
        int row = rowbase + r;
        float2 v = (row < N) ? *(const float2*)&X[row * 64 + 2 * kp] : make_float2(0.f, 0.f);
        uint16_t h0, l0, h1, l1;
        bf16_split(v.x, h0, l0);
        bf16_split(v.y, h1, l1);
        uint32_t off = swz_off(r, kp * 4);
        *(uint32_t*)(smem + SMA_HI + off) = (uint32_t)h0 | ((uint32_t)h1 << 16);
        *(uint32_t*)(smem + SMA_LO + off) = (uint32_t)l0 | ((uint32_t)l1 << 16);
    }
    __syncthreads();

    const int m0 = (wid & 3) * 32;
    const int n0 = (wid >> 2) * 64;
    const int rl  = lane & 7;
    const int grp = lane >> 3;

    float acc[2][8][4];
#pragma unroll
    for (int mt = 0; mt < 2; mt++)
#pragma unroll
        for (int nt = 0; nt < 8; nt++)
#pragma unroll
            for (int j = 0; j < 4; j++) acc[mt][nt][j] = 0.f;

#pragma unroll
    for (int ks = 0; ks < 4; ks++) {
        const int cb = ks * 32;
        uint32_t ahi[2][4], alo[2][4];
#pragma unroll
        for (int mt = 0; mt < 2; mt++) {
            int arow = m0 + mt * 16 + (grp & 1) * 8 + rl;
            int abyte = cb + (grp >> 1) * 16;
            ldm_x4(ahi[mt], sb + SMA_HI + swz_off(arow, abyte));
            ldm_x4(alo[mt], sb + SMA_LO + swz_off(arow, abyte));
        }
#pragma unroll
        for (int np = 0; np < 4; np++) {
            int brow = n0 + np * 16 + (grp >> 1) * 8 + rl;
            int bbyte = cb + (grp & 1) * 16;
            uint32_t bhi[4], blo[4];
            ldm_x4(bhi, sb + SMB_HI + swz_off(brow, bbyte));
            ldm_x4(blo, sb + SMB_LO + swz_off(brow, bbyte));
            mma_bf16(acc[0][2 * np],     ahi[0], bhi[0], bhi[1]);
            mma_bf16(acc[1][2 * np],     ahi[1], bhi[0], bhi[1]);
            mma_bf16(acc[0][2 * np + 1], ahi[0], bhi[2], bhi[3]);
            mma_bf16(acc[1][2 * np + 1], ahi[1], bhi[2], bhi[3]);
            mma_bf16(acc[0][2 * np],     alo[0], bhi[0], bhi[1]);
            mma_bf16(acc[1][2 * np],     alo[1], bhi[0], bhi[1]);
            mma_bf16(acc[0][2 * np + 1], alo[0], bhi[2], bhi[3]);
            mma_bf16(acc[1][2 * np + 1], alo[1], bhi[2], bhi[3]);
            mma_bf16(acc[0][2 * np],     ahi[0], blo[0], blo[1]);
            mma_bf16(acc[1][2 * np],     ahi[1], blo[0], blo[1]);
            mma_bf16(acc[0][2 * np + 1], ahi[0], blo[2], blo[3]);
            mma_bf16(acc[1][2 * np + 1], ahi[1], blo[2], blo[3]);
        }
    }

    const int qr = lane >> 2, qc = (lane & 3) * 2;
#pragma unroll
    for (int mt = 0; mt < 2; mt++) {
#pragma unroll
        for (int nt = 0; nt < 8; nt++) {
            int col = n0 + nt * 8 + qc;
            int row0 = rowbase + m0 + mt * 16 + qr;
#pragma unroll
            for (int h = 0; h < 2; h++) {
                int row = row0 + h * 8;
                if (row < N) {
                    float vx = acc[mt][nt][2 * h], vy = acc[mt][nt][2 * h + 1];
                    if (col < 64) Y0h[row * 32 + (col >> 1)] = __floats2half2_rn(vx, vy);
                    else          *(float2*)&Y1[row * 64 + col - 64] = make_float2(vx, vy);
                }
            }
        }
    }
}

// ---------------------------------------------------------------------------
// Layer-3 fused GEMM: Y[128 x 256] = X @ [W3l | W3r] in ONE pass (512 thr).
// ---------------------------------------------------------------------------
#define SM3_AHI 0
#define SM3_ALO 16384
#define SM3_BHI 32768
#define SM3_BLO 65536
#define SM3_TOT 98304

__global__ void __launch_bounds__(512) k_mma3(const float* __restrict__ X,
                                              const unsigned char* __restrict__ Bhi2,
                                              const unsigned char* __restrict__ Blo2,
                                              const unsigned char* __restrict__ Bhi3,
                                              const unsigned char* __restrict__ Blo3,
                                              __half2* __restrict__ Y0h,
                                              float* __restrict__ Y1, int N) {
    extern __shared__ char smem[];
    const uint32_t sb = smem_u32(smem);
    const int tid = threadIdx.x, wid = tid >> 5, lane = tid & 31;
    const int rowbase = blockIdx.x * 128;

#pragma unroll
    for (int i = tid; i < 2048; i += 512) {
        ((uint4*)(smem + SM3_BHI))[i] = (i < 1024) ? ((const uint4*)Bhi2)[i]
                                                   : ((const uint4*)Bhi3)[i - 1024];
        ((uint4*)(smem + SM3_BLO))[i] = (i < 1024) ? ((const uint4*)Blo2)[i]
                                                   : ((const uint4*)Blo3)[i - 1024];
    }
#pragma unroll
    for (int i = tid; i < 4096; i += 512) {
        int r = i >> 5, kp = i & 31;
        int row = rowbase + r;
        float2 v = (row < N) ? *(const float2*)&X[row * 64 + 2 * kp] : make_float2(0.f, 0.f);
        uint16_t h0, l0, h1, l1;
        bf16_split(v.x, h0, l0);
        bf16_split(v.y, h1, l1);
        uint32_t off = swz_off(r, kp * 4);
        *(uint32_t*)(smem + SM3_AHI + off) = (uint32_t)h0 | ((uint32_t)h1 << 16);
        *(uint32_t*)(smem + SM3_ALO + off) = (uint32_t)l0 | ((uint32_t)l1 << 16);
    }
    __syncthreads();

    const int m0 = (wid & 3) * 32;
    const int n0 = (wid >> 2) * 64;  // 0,64,128,192
    const int rl  = lane & 7;
    const int grp = lane >> 3;

    float acc[2][8][4];
#pragma unroll
    for (int mt = 0; mt < 2; mt++)
#pragma unroll
        for (int nt = 0; nt < 8; nt++)
#pragma unroll
            for (int j = 0; j < 4; j++) acc[mt][nt][j] = 0.f;

#pragma unroll
    for (int ks = 0; ks < 4; ks++) {
        const int cb = ks * 32;
        uint32_t ahi[2][4], alo[2][4];
#pragma unroll
        for (int mt = 0; mt < 2; mt++) {
            int arow = m0 + mt * 16 + (grp & 1) * 8 + rl;
            int abyte = cb + (grp >> 1) * 16;
            ldm_x4(ahi[mt], sb + SM3_AHI + swz_off(arow, abyte));
            ldm_x4(alo[mt], sb + SM3_ALO + swz_off(arow, abyte));
        }
#pragma unroll
        for (int np = 0; np < 4; np++) {
            int brow = n0 + np * 16 + (grp >> 1) * 8 + rl;
            int bbyte = cb + (grp & 1) * 16;
            uint32_t bhi[4], blo[4];
            ldm_x4(bhi, sb + SM3_BHI + swz_off(brow, bbyte));
            ldm_x4(blo, sb + SM3_BLO + swz_off(brow, bbyte));
            mma_bf16(acc[0][2 * np],     ahi[0], bhi[0], bhi[1]);
            mma_bf16(acc[1][2 * np],     ahi[1], bhi[0], bhi[1]);
            mma_bf16(acc[0][2 * np + 1], ahi[0], bhi[2], bhi[3]);
            mma_bf16(acc[1][2 * np + 1], ahi[1], bhi[2], bhi[3]);
            mma_bf16(acc[0][2 * np],     alo[0], bhi[0], bhi[1]);
            mma_bf16(acc[1][2 * np],     alo[1], bhi[0], bhi[1]);
            mma_bf16(acc[0][2 * np + 1], alo[0], bhi[2], bhi[3]);
            mma_bf16(acc[1][2 * np + 1], alo[1], bhi[2], bhi[3]);
            mma_bf16(acc[0][2 * np],     ahi[0], blo[0], blo[1]);
            mma_bf16(acc[1][2 * np],     ahi[1], blo[0], blo[1]);
            mma_bf16(acc[0][2 * np + 1], ahi[0], blo[2], blo[3]);
            mma_bf16(acc[1][2 * np + 1], ahi[1], blo[2], blo[3]);
        }
    }

    const int qr = lane >> 2, qc = (lane & 3) * 2;
#pragma unroll
    for (int mt = 0; mt < 2; mt++) {
#pragma unroll
        for (int nt = 0; nt < 8; nt++) {
            int col = n0 + nt * 8 + qc;
            int row0 = rowbase + m0 + mt * 16 + qr;
#pragma unroll
            for (int h = 0; h < 2; h++) {
                int row = row0 + h * 8;
                if (row < N) {
                    float vx = acc[mt][nt][2 * h], vy = acc[mt][nt][2 * h + 1];
                    if (col < 128) Y0h[row * 64 + (col >> 1)] = __floats2half2_rn(vx, vy);
                    else           *(float2*)&Y1[row * 128 + col - 128] = make_float2(vx, vy);
                }
            }
        }
    }
}

// ---------------------------------------------------------------------------
// Edge phase
// ---------------------------------------------------------------------------
__device__ __forceinline__ float leaky(float t) { return fmaxf(t, 0.2f * t); }

__device__ __forceinline__ float red8(float p) {
    p += __shfl_xor_sync(0xffffffffu, p, 4);
    p += __shfl_xor_sync(0xffffffffu, p, 2);
    p += __shfl_xor_sync(0xffffffffu, p, 1);
    return p;
}
__device__ __forceinline__ float red4(float p) {
    p += __shfl_xor_sync(0xffffffffu, p, 2);
    p += __shfl_xor_sync(0xffffffffu, p, 1);
    return p;
}
__device__ __forceinline__ float4 h2f4(uint2 u) {
    float2 lohalf = __half22float2(*(__half2*)&u.x);
    float2 hihalf = __half22float2(*(__half2*)&u.y);
    return make_float4(lohalf.x, lohalf.y, hihalf.x, hihalf.y);
}

// k_edge64: TWO nodes per warp (16 lanes each, 4 fp16 feats/lane),
// 4-edge pipeline, branchless lockstep (invalid slots -> p=-1e30 -> e=0),
// quad-merged online softmax. Head reduction = 2 shfl (4-lane groups).
__global__ void k_edge64(const __half2* __restrict__ XLH, const float* __restrict__ XR,
                         const float* __restrict__ att, const float* __restrict__ bias,
                         float* __restrict__ OUT, int N) {
    const int lane = threadIdx.x & 31;
    const int hl   = lane & 15;          // lane within half-warp
    const int wg   = (blockIdx.x * blockDim.x + threadIdx.x) >> 5;
    const int n    = wg * 2 + (lane >> 4);
    const bool valid = n < N;
    const int nc = valid ? n : N - 1;

    const uint2* XL2 = (const uint2*)XLH;   // 16 uint2 (= 4 fp16) per 64-feat row

    float4 a  = *(const float4*)&att[4 * hl];
    float4 xr = *(const float4*)&XR[nc * 64 + 4 * hl];
    float4 vs = h2f4(XL2[nc * 16 + hl]);

    auto score = [&](const float4& v) {
        return a.x * leaky(v.x + xr.x) + a.y * leaky(v.y + xr.y) +
               a.z * leaky(v.z + xr.z) + a.w * leaky(v.w + xr.w);
    };

    float m = red4(score(vs));
    float d = 1.f;
    float4 acc = vs;

    int beg = g_rowptr[nc];
    int end = valid ? g_rowptr[nc + 1] : beg;
    int cnt = end - beg;
    int ocnt = __shfl_xor_sync(0xffffffffu, cnt, 16);
    int nq = (max(cnt, ocnt) + 3) >> 2;

    int j = beg;
    int s0 = (j + 0 < end) ? g_adj[j + 0] : nc;
    int s1 = (j + 1 < end) ? g_adj[j + 1] : nc;
    int s2 = (j + 2 < end) ? g_adj[j + 2] : nc;
    int s3 = (j + 3 < end) ? g_adj[j + 3] : nc;

    for (int q = 0; q < nq; q++) {
        float4 v0 = h2f4(XL2[s0 * 16 + hl]);
        float4 v1 = h2f4(XL2[s1 * 16 + hl]);
        float4 v2 = h2f4(XL2[s2 * 16 + hl]);
        float4 v3 = h2f4(XL2[s3 * 16 + hl]);
        bool o0 = j + 0 < end, o1 = j + 1 < end, o2 = j + 2 < end, o3 = j + 3 < end;
        int jn = j + 4;
        s0 = (jn + 0 < end) ? g_adj[jn + 0] : nc;
        s1 = (jn + 1 < end) ? g_adj[jn + 1] : nc;
        s2 = (jn + 2 < end) ? g_adj[jn + 2] : nc;
        s3 = (jn + 3 < end) ? g_adj[jn + 3] : nc;
        j = jn;

        float p0 = red4(score(v0));
        float p1 = red4(score(v1));
        float p2 = red4(score(v2));
        float p3 = red4(score(v3));
        p0 = o0 ? p0 : -1e30f;
        p1 = o1 ? p1 : -1e30f;
        p2 = o2 ? p2 : -1e30f;
        p3 = o3 ? p3 : -1e30f;

        float mq = fmaxf(fmaxf(p0, p1), fmaxf(p2, p3));
        float mn = fmaxf(m, mq);
        float w  = __expf(m - mn);
        float e0 = __expf(p0 - mn), e1 = __expf(p1 - mn);
        float e2 = __expf(p2 - mn), e3 = __expf(p3 - mn);
        acc.x = acc.x * w + (e0 * v0.x + e1 * v1.x) + (e2 * v2.x + e3 * v3.x);
        acc.y = acc.y * w + (e0 * v0.y + e1 * v1.y) + (e2 * v2.y + e3 * v3.y);
        acc.z = acc.z * w + (e0 * v0.z + e1 * v1.z) + (e2 * v2.z + e3 * v3.z);
        acc.w = acc.w * w + (e0 * v0.w + e1 * v1.w) + (e2 * v2.w + e3 * v3.w);
        d = d * w + ((e0 + e1) + (e2 + e3));
        m = mn;
    }
    float inv = 1.f / d;
    float o0 = acc.x * inv + bias[4 * hl + 0];
    float o1 = acc.y * inv + bias[4 * hl + 1];
    float o2 = acc.z * inv + bias[4 * hl + 2];
    float o3 = acc.w * inv + bias[4 * hl + 3];
    o0 = o0 > 0.f ? o0 : (__expf(o0) - 1.f);
    o1 = o1 > 0.f ? o1 : (__expf(o1) - 1.f);
    o2 = o2 > 0.f ? o2 : (__expf(o2) - 1.f);
    o3 = o3 > 0.f ? o3 : (__expf(o3) - 1.f);
    if (valid) *(float4*)&OUT[n * 64 + 4 * hl] = make_float4(o0, o1, o2, o3);
}

__global__ void k_edge128_mean(const __half2* __restrict__ XLH, const float* __restrict__ XR,
                               const float* __restrict__ att, const float* __restrict__ bias,
                               float* __restrict__ OUT, int N) {
    int lane = threadIdx.x & 31;
    int n    = (blockIdx.x * blockDim.x + threadIdx.x) >> 5;
    if (n >= N) return;

    float4 a  = *(const float4*)&att[4 * lane];
    float4 xr = *(const float4*)&XR[n * 128 + 4 * lane];
    float4 vs = h2f4(*(const uint2*)&XLH[n * 64 + 2 * lane]);

    auto score = [&](const float4& v) {
        return a.x * leaky(v.x + xr.x) + a.y * leaky(v.y + xr.y) +
               a.z * leaky(v.z + xr.z) + a.w * leaky(v.w + xr.w);
    };

    float m = red8(score(vs));
    float d = 1.f;
    float4 acc = vs;

    int beg = g_rowptr[n], end = g_rowptr[n + 1];
    int i = beg;
    int s0 = 0, s1 = 0, s2 = 0, s3 = 0;
    if (i + 4 <= end) { s0 = g_adj[i]; s1 = g_adj[i+1]; s2 = g_adj[i+2]; s3 = g_adj[i+3]; }
    while (i + 4 <= end) {
        float4 v0 = h2f4(*(const uint2*)&XLH[s0 * 64 + 2 * lane]);
        float4 v1 = h2f4(*(const uint2*)&XLH[s1 * 64 + 2 * lane]);
        float4 v2 = h2f4(*(const uint2*)&XLH[s2 * 64 + 2 * lane]);
        float4 v3 = h2f4(*(const uint2*)&XLH[s3 * 64 + 2 * lane]);
        i += 4;
        if (i + 4 <= end) { s0 = g_adj[i]; s1 = g_adj[i+1]; s2 = g_adj[i+2]; s3 = g_adj[i+3]; }
        float p0 = score(v0), p1 = score(v1), p2 = score(v2), p3 = score(v3);
#pragma unroll
        for (int o = 4; o > 0; o >>= 1) {
            p0 += __shfl_xor_sync(0xffffffffu, p0, o);
            p1 += __shfl_xor_sync(0xffffffffu, p1, o);
            p2 += __shfl_xor_sync(0xffffffffu, p2, o);
            p3 += __shfl_xor_sync(0xffffffffu, p3, o);
        }
        float mq = fmaxf(fmaxf(p0, p1), fmaxf(p2, p3));
        float mn = fmaxf(m, mq);
        float w  = __expf(m - mn);
        float e0 = __expf(p0 - mn), e1 = __expf(p1 - mn);
        float e2 = __expf(p2 - mn), e3 = __expf(p3 - mn);
        acc.x = acc.x * w + (e0 * v0.x + e1 * v1.x) + (e2 * v2.x + e3 * v3.x);
        acc.y = acc.y * w + (e0 * v0.y + e1 * v1.y) + (e2 * v2.y + e3 * v3.y);
        acc.z = acc.z * w + (e0 * v0.z + e1 * v1.z) + (e2 * v2.z + e3 * v3.z);
        acc.w = acc.w * w + (e0 * v0.w + e1 * v1.w) + (e2 * v2.w + e3 * v3.w);
        d = d * w + ((e0 + e1) + (e2 + e3));
        m = mn;
    }
    for (; i < end; i++) {
        int s = g_adj[i];
        float4 v = h2f4(*(const uint2*)&XLH[s * 64 + 2 * lane]);
        float p = red8(score(v));
        float mn = fmaxf(m, p);
        float w  = __expf(m - mn);
        float e  = __expf(p - mn);
        acc.x = acc.x * w + e * v.x;
        acc.y = acc.y * w + e * v.y;
        acc.z = acc.z * w + e * v.z;
        acc.w = acc.w * w + e * v.w;
        d = d * w + e;
        m = mn;
    }
    float inv = 1.f / d;
    float o0 = acc.x * inv, o1 = acc.y * inv, o2 = acc.z * inv, o3 = acc.w * inv;
#pragma unroll
    for (int off = 8; off <= 16; off <<= 1) {
        o0 += __shfl_xor_sync(0xffffffffu, o0, off);
        o1 += __shfl_xor_sync(0xffffffffu, o1, off);
        o2 += __shfl_xor_sync(0xffffffffu, o2, off);
        o3 += __shfl_xor_sync(0xffffffffu, o3, off);
    }
    if (lane < 8) {
        int c = 4 * lane;
        float4 o = make_float4(0.25f * o0 + bias[c + 0],
                               0.25f * o1 + bias[c + 1],
                               0.25f * o2 + bias[c + 2],
                               0.25f * o3 + bias[c + 3]);
        *(float4*)&OUT[n * 32 + c] = o;
    }
}

// ---------------------------------------------------------------------------
// Launch (layer-1 GEMM at index 3 -> ncu capture target)
// ---------------------------------------------------------------------------
extern "C" void kernel_launch(void* const* d_in, const int* in_sizes, int n_in,
                              void* d_out, int out_size) {
    const float* x   = (const float*)d_in[0];
    const int*   ei  = (const int*)  d_in[1];
    const float* W1l = (const float*)d_in[2];
    const float* W1r = (const float*)d_in[3];
    const float* a1  = (const float*)d_in[4];
    const float* b1  = (const float*)d_in[5];
    const float* W2l = (const float*)d_in[6];
    const float* W2r = (const float*)d_in[7];
    const float* a2  = (const float*)d_in[8];
    const float* b2  = (const float*)d_in[9];
    const float* W3l = (const float*)d_in[10];
    const float* W3r = (const float*)d_in[11];
    const float* a3  = (const float*)d_in[12];
    const float* b3  = (const float*)d_in[13];
    float* out = (float*)d_out;

    const int N = in_sizes[0] / 64;
    const int E = in_sizes[1] / 2;
    const int NB = (N + 1023) / 1024;

    float *xlf, *xr, *h;
    unsigned char (*whi)[16384], (*wlo)[16384];
    cudaGetSymbolAddress((void**)&xlf, g_xl);
    cudaGetSymbolAddress((void**)&xr,  g_xr);
    cudaGetSymbolAddress((void**)&h,   g_h);
    cudaGetSymbolAddress((void**)&whi, g_wimg_hi);
    cudaGetSymbolAddress((void**)&wlo, g_wimg_lo);
    __half2* xlh = (__half2*)xlf;

    cudaFuncSetAttribute(k_mma,  cudaFuncAttributeMaxDynamicSharedMemorySize, SM_TOT);
    cudaFuncSetAttribute(k_mma3, cudaFuncAttributeMaxDynamicSharedMemorySize, SM3_TOT);

    const int GT  = (N + 127) / 128;
    const int EB  = (N + 15) / 16;    // edge64: 8 warps x 2 nodes per block
    const int EBM = (N + 7) / 8;      // edge128: 8 warps x 1 node per block
    const int ZB  = (N + 255) / 256;

    // 0: init (zero cnt + W images)
    k_init<<<64 + ZB, 256>>>(W1l, W1r, W2l, W2r, W3l, W3r, N);
    // 1-2: CSR part 1
    k_hist<<<1024, 256>>>(ei, E);
    k_scan1<<<NB, 1024>>>(N);
    // 3: layer-1 GEMM (ncu capture target)
    k_mma<<<GT, 256, SM_TOT>>>(x, whi[0], wlo[0], xlh, xr, N);
    // 4-5: CSR part 2
    k_scan3<<<NB, 1024>>>(N, E);
    k_scatter<<<1024, 256>>>(ei, E);
    // Layer 1 edge
    k_edge64<<<EB, 256>>>(xlh, xr, a1, b1, h, N);
    // Layer 2
    k_mma<<<GT, 256, SM_TOT>>>(h, whi[1], wlo[1], xlh, xr, N);
    k_edge64<<<EB, 256>>>(xlh, xr, a2, b2, h, N);
    // Layer 3 (fused dual-N GEMM)
    k_mma3<<<GT, 512, SM3_TOT>>>(h, whi[2], wlo[2], whi[3], wlo[3], xlh, xr, N);
    k_edge128_mean<<<EBM, 256>>>(xlh, xr, a3, b3, out, N);
}

// round 10
// speedup vs baseline: 1.8131x; 1.0148x over previous
#include <cuda_runtime.h>
#include <cuda_bf16.h>
#include <cuda_fp16.h>
#include <cstdint>

// Problem constants
#define NMAX 100000
#define EMAX 800000
#define HPAD 100096   // NMAX rounded up to 128 (tile padding)

// Scratch (no allocation allowed -> __device__ globals)
__device__ float g_xl[NMAX * 128];     // fp16 xl (half2) buffers
__device__ float g_xr[NMAX * 128];     // fp32 xr
__device__ __align__(16) unsigned char g_hhi[HPAD * 128];  // h bf16-hi image (swizzled)
__device__ __align__(16) unsigned char g_hlo[HPAD * 128];  // h bf16-lo image (swizzled)
__device__ int   g_cnt[NMAX];
__device__ int   g_rowptr[NMAX + 1];
__device__ int   g_fill[NMAX];
__device__ int   g_adj[EMAX];
__device__ int   g_bsum[128];
// bf16 [n=128][k=64] W images (XOR-swizzled): 0:[W1l|W1r] 1:[W2l|W2r] 2:W3l 3:W3r
__device__ __align__(16) unsigned char g_wimg_hi[4][16384];
__device__ __align__(16) unsigned char g_wimg_lo[4][16384];

// ---------------------------------------------------------------------------
// helpers
// ---------------------------------------------------------------------------
__device__ __forceinline__ uint32_t smem_u32(const void* p) {
    uint32_t a;
    asm("{ .reg .u64 t; cvta.to.shared.u64 t, %1; cvt.u32.u64 %0, t; }" : "=r"(a) : "l"(p));
    return a;
}
__device__ __forceinline__ void bf16_split(float v, uint16_t& hi, uint16_t& lo) {
    __nv_bfloat16 h = __float2bfloat16(v);
    float residual = v - __bfloat162float(h);
    __nv_bfloat16 l = __float2bfloat16(residual);
    hi = *(uint16_t*)&h;
    lo = *(uint16_t*)&l;
}
__device__ __forceinline__ void ldm_x4(uint32_t (&r)[4], uint32_t addr) {
    asm volatile("ldmatrix.sync.aligned.m8n8.x4.shared.b16 {%0,%1,%2,%3}, [%4];"
                 : "=r"(r[0]), "=r"(r[1]), "=r"(r[2]), "=r"(r[3]) : "r"(addr));
}
__device__ __forceinline__ void mma_bf16(float (&d)[4], const uint32_t (&a)[4],
                                         uint32_t b0, uint32_t b1) {
    asm volatile(
        "mma.sync.aligned.m16n8k16.row.col.f32.bf16.bf16.f32 "
        "{%0,%1,%2,%3}, {%4,%5,%6,%7}, {%8,%9}, {%0,%1,%2,%3};"
        : "+f"(d[0]), "+f"(d[1]), "+f"(d[2]), "+f"(d[3])
        : "r"(a[0]), "r"(a[1]), "r"(a[2]), "r"(a[3]), "r"(b0), "r"(b1));
}
// XOR swizzle inside a 128B row: 16B chunk index XORed with (row&7)
__device__ __forceinline__ uint32_t swz_off(int row, int byte_in_row) {
    return (uint32_t)(row * 128 + (byte_in_row ^ ((row & 7) << 4)));
}

// ---------------------------------------------------------------------------
// k_init: zero cnt + bsum, W -> bf16 hi/lo images
// ---------------------------------------------------------------------------
__global__ void k_init(const float* __restrict__ W1l, const float* __restrict__ W1r,
                       const float* __restrict__ W2l, const float* __restrict__ W2r,
                       const float* __restrict__ W3l, const float* __restrict__ W3r,
                       int N) {
    if (blockIdx.x >= 64) {
        int i = (blockIdx.x - 64) * 256 + threadIdx.x;
        if (i < N) g_cnt[i] = 0;
        if (blockIdx.x == 64 && threadIdx.x < 128) g_bsum[threadIdx.x] = 0;
        return;
    }
    int tid = blockIdx.x * 256 + threadIdx.x;   // 0..16383
    int img = tid >> 12, idx = tid & 4095;
    int n = idx >> 5, kp = idx & 31;
    int k0 = 2 * kp, k1 = k0 + 1;
    float v0, v1;
    if (img == 0) {
        v0 = (n < 64) ? W1l[k0 * 64 + n] : W1r[k0 * 64 + n - 64];
        v1 = (n < 64) ? W1l[k1 * 64 + n] : W1r[k1 * 64 + n - 64];
    } else if (img == 1) {
        v0 = (n < 64) ? W2l[k0 * 64 + n] : W2r[k0 * 64 + n - 64];
        v1 = (n < 64) ? W2l[k1 * 64 + n] : W2r[k1 * 64 + n - 64];
    } else if (img == 2) {
        v0 = W3l[k0 * 128 + n];
        v1 = W3l[k1 * 128 + n];
    } else {
        v0 = W3r[k0 * 128 + n];
        v1 = W3r[k1 * 128 + n];
    }
    uint16_t h0, l0, h1, l1;
    bf16_split(v0, h0, l0);
    bf16_split(v1, h1, l1);
    uint32_t off = swz_off(n, kp * 4);
    *(uint32_t*)(g_wimg_hi[img] + off) = (uint32_t)h0 | ((uint32_t)h1 << 16);
    *(uint32_t*)(g_wimg_lo[img] + off) = (uint32_t)l0 | ((uint32_t)l1 << 16);
}

// ---------------------------------------------------------------------------
// CSR: fused decoupled-lookback scan (NB <= 148 blocks, all co-resident)
// ---------------------------------------------------------------------------
__device__ __forceinline__ int block_scan_excl_1024(int val, int& total) {
    __shared__ int wsum[32];
    int lane = threadIdx.x & 31, w = threadIdx.x >> 5;
    int inc = val;
#pragma unroll
    for (int o = 1; o < 32; o <<= 1) {
        int u = __shfl_up_sync(0xffffffffu, inc, o);
        if (lane >= o) inc += u;
    }
    if (lane == 31) wsum[w] = inc;
    __syncthreads();
    if (w == 0) {
        int v = wsum[lane];
#pragma unroll
        for (int o = 1; o < 32; o <<= 1) {
            int u = __shfl_up_sync(0xffffffffu, v, o);
            if (lane >= o) v += u;
        }
        wsum[lane] = v;
    }
    __syncthreads();
    int off = (w > 0) ? wsum[w - 1] : 0;
    total = wsum[31];
    return off + inc - val;
}

__global__ void k_scan(int N, int E) {
    int b = blockIdx.x, t = threadIdx.x;
    int idx = b * 1024 + t;
    int val = (idx < N) ? g_cnt[idx] : 0;
    int total;
    int ex = block_scan_excl_1024(val, total);
    if (t == 0) atomicExch(&g_bsum[b], total + 1);   // publish (sentinel +1)
    // lookback: thread t (< b) waits for block t's total
    int my = 0;
    if (t < b) {
        int v;
        do { v = atomicAdd(&g_bsum[t], 0); } while (v == 0);
        my = v - 1;
    }
    __shared__ int red[32];
    int lane = t & 31, w = t >> 5;
#pragma unroll
    for (int o = 16; o > 0; o >>= 1) my += __shfl_xor_sync(0xffffffffu, my, o);
    if (lane == 0) red[w] = my;
    __syncthreads();
    if (t == 0) {
        int s = 0;
#pragma unroll
        for (int i = 0; i < 32; i++) s += red[i];
        red[0] = s;
    }
    __syncthreads();
    int off = red[0];
    if (idx < N) {
        g_rowptr[idx] = ex + off;
        g_fill[idx]   = ex + off;
    }
    if (b == 0 && t == 0) g_rowptr[N] = E;
}

__global__ void k_scatter(const int* __restrict__ ei, int E) {
    for (int i = blockIdx.x * blockDim.x + threadIdx.x; i < E; i += gridDim.x * blockDim.x) {
        int d = ei[E + i];
        int p = atomicAdd(&g_fill[d], 1);
        g_adj[p] = ei[i];
    }
}

// ---------------------------------------------------------------------------
// HMMA GEMM (layers 1/2): Y[128x128] = X @ [Wl|Wr], 3-term bf16 split.
// PRE=false: convert fp32 X in-kernel, and extra blocks run the edge histogram.
// PRE=true : A loaded from pre-split global bf16 hi/lo images (uint4 copy).
// Epilogue: cols<64 -> fp16 xl, cols>=64 -> fp32 xr.
// ---------------------------------------------------------------------------
#define SMA_HI 0
#define SMA_LO 16384
#define SMB_HI 32768
#define SMB_LO 49152
#define SM_TOT 65536

template <bool PRE>
__global__ void __launch_bounds__(256, 2) k_mma(const float* __restrict__ X,
                                                const unsigned char* __restrict__ Ahi,
                                                const unsigned char* __restrict__ Alo,
                                                const unsigned char* __restrict__ Bhi,
                                                const unsigned char* __restrict__ Blo,
                                                __half2* __restrict__ Y0h,
                                                float* __restrict__ Y1, int N,
                                                const int* __restrict__ ei, int E, int GB) {
    if (!PRE && blockIdx.x >= (unsigned)GB) {
        // histogram side-grid (independent of GEMM work)
        for (int i = (blockIdx.x - GB) * 256 + threadIdx.x; i < E; i += 1024 * 256)
            atomicAdd(&g_cnt[ei[E + i]], 1);
        return;
    }
    extern __shared__ char smem[];
    const uint32_t sb = smem_u32(smem);
    const int tid = threadIdx.x, wid = tid >> 5, lane = tid & 31;
    const int rowbase = blockIdx.x * 128;

    const uint4* bh = (const uint4*)Bhi;
    const uint4* bl = (const uint4*)Blo;
#pragma unroll
    for (int i = tid; i < 1024; i += 256) {
        ((uint4*)(smem + SMB_HI))[i] = bh[i];
        ((uint4*)(smem + SMB_LO))[i] = bl[i];
    }
    if (PRE) {
        const uint4* ah = (const uint4*)(Ahi + (size_t)rowbase * 128);
        const uint4* al = (const uint4*)(Alo + (size_t)rowbase * 128);
#pragma unroll
        for (int i = tid; i < 1024; i += 256) {
            ((uint4*)(smem + SMA_HI))[i] = ah[i];
            ((uint4*)(smem + SMA_LO))[i] = al[i];
        }
    } else {
#pragma unroll
        for (int i = tid; i < 4096; i += 256) {
            int r = i >> 5, kp = i & 31;
            int row = rowbase + r;
            float2 v = (row < N) ? *(const float2*)&X[row * 64 + 2 * kp]
                                 : make_float2(0.f, 0.f);
            uint16_t h0, l0, h1, l1;
            bf16_split(v.x, h0, l0);
            bf16_split(v.y, h1, l1);
            uint32_t off = swz_off(r, kp * 4);
            *(uint32_t*)(smem + SMA_HI + off) = (uint32_t)h0 | ((uint32_t)h1 << 16);
            *(uint32_t*)(smem + SMA_LO + off) = (uint32_t)l0 | ((uint32_t)l1 << 16);
        }
    }
    __syncthreads();

    const int m0 = (wid & 3) * 32;
    const int n0 = (wid >> 2) * 64;
    const int rl  = lane & 7;
    const int grp = lane >> 3;

    float acc[2][8][4];
#pragma unroll
    for (int mt = 0; mt < 2; mt++)
#pragma unroll
        for (int nt = 0; nt < 8; nt++)
#pragma unroll
            for (int j = 0; j < 4; j++) acc[mt][nt][j] = 0.f;

#pragma unroll
    for (int ks = 0; ks < 4; ks++) {
        const int cb = ks * 32;
        uint32_t ahi[2][4], alo[2][4];
#pragma unroll
        for (int mt = 0; mt < 2; mt++) {
            int arow = m0 + mt * 16 + (grp & 1) * 8 + rl;
            int abyte = cb + (grp >> 1) * 16;
            ldm_x4(ahi[mt], sb + SMA_HI + swz_off(arow, abyte));
            ldm_x4(alo[mt], sb + SMA_LO + swz_off(arow, abyte));
        }
#pragma unroll
        for (int np = 0; np < 4; np++) {
            int brow = n0 + np * 16 + (grp >> 1) * 8 + rl;
            int bbyte = cb + (grp & 1) * 16;
            uint32_t bhi[4], blo[4];
            ldm_x4(bhi, sb + SMB_HI + swz_off(brow, bbyte));
            ldm_x4(blo, sb + SMB_LO + swz_off(brow, bbyte));
            mma_bf16(acc[0][2 * np],     ahi[0], bhi[0], bhi[1]);
            mma_bf16(acc[1][2 * np],     ahi[1], bhi[0], bhi[1]);
            mma_bf16(acc[0][2 * np + 1], ahi[0], bhi[2], bhi[3]);
            mma_bf16(acc[1][2 * np + 1], ahi[1], bhi[2], bhi[3]);
            mma_bf16(acc[0][2 * np],     alo[0], bhi[0], bhi[1]);
            mma_bf16(acc[1][2 * np],     alo[1], bhi[0], bhi[1]);
            mma_bf16(acc[0][2 * np + 1], alo[0], bhi[2], bhi[3]);
            mma_bf16(acc[1][2 * np + 1], alo[1], bhi[2], bhi[3]);
            mma_bf16(acc[0][2 * np],     ahi[0], blo[0], blo[1]);
            mma_bf16(acc[1][2 * np],     ahi[1], blo[0], blo[1]);
            mma_bf16(acc[0][2 * np + 1], ahi[0], blo[2], blo[3]);
            mma_bf16(acc[1][2 * np + 1], ahi[1], blo[2], blo[3]);
        }
    }

    const int qr = lane >> 2, qc = (lane & 3) * 2;
#pragma unroll
    for (int mt = 0; mt < 2; mt++) {
#pragma unroll
        for (int nt = 0; nt < 8; nt++) {
            int col = n0 + nt * 8 + qc;
            int row0 = rowbase + m0 + mt * 16 + qr;
#pragma unroll
            for (int h = 0; h < 2; h++) {
                int row = row0 + h * 8;
                if (row < N) {
                    float vx = acc[mt][nt][2 * h], vy = acc[mt][nt][2 * h + 1];
                    if (col < 64) Y0h[row * 32 + (col >> 1)] = __floats2half2_rn(vx, vy);
                    else          *(float2*)&Y1[row * 64 + col - 64] = make_float2(vx, vy);
                }
            }
        }
    }
}

// ---------------------------------------------------------------------------
// Layer-3 fused GEMM: Y[128 x 256] = H @ [W3l | W3r], H from pre-split images.
// ---------------------------------------------------------------------------
#define SM3_AHI 0
#define SM3_ALO 16384
#define SM3_BHI 32768
#define SM3_BLO 65536
#define SM3_TOT 98304

__global__ void __launch_bounds__(512) k_mma3(const unsigned char* __restrict__ Ahi,
                                              const unsigned char* __restrict__ Alo,
                                              const unsigned char* __restrict__ Bhi2,
                                              const unsigned char* __restrict__ Blo2,
                                              const unsigned char* __restrict__ Bhi3,
                                              const unsigned char* __restrict__ Blo3,
                                              __half2* __restrict__ Y0h,
                                              float* __restrict__ Y1, int N) {
    extern __shared__ char smem[];
    const uint32_t sb = smem_u32(smem);
    const int tid = threadIdx.x, wid = tid >> 5, lane = tid & 31;
    const int rowbase = blockIdx.x * 128;

#pragma unroll
    for (int i = tid; i < 2048; i += 512) {
        ((uint4*)(smem + SM3_BHI))[i] = (i < 1024) ? ((const uint4*)Bhi2)[i]
                                                   : ((const uint4*)Bhi3)[i - 1024];
        ((uint4*)(smem + SM3_BLO))[i] = (i < 1024) ? ((const uint4*)Blo2)[i]
                                                   : ((const uint4*)Blo3)[i - 1024];
    }
    {
        const uint4* ah = (const uint4*)(Ahi + (size_t)rowbase * 128);
        const uint4* al = (const uint4*)(Alo + (size_t)rowbase * 128);
#pragma unroll
        for (int i = tid; i < 1024; i += 512) {
            ((uint4*)(smem + SM3_AHI))[i] = ah[i];
            ((uint4*)(smem + SM3_ALO))[i] = al[i];
        }
    }
    __syncthreads();

    const int m0 = (wid & 3) * 32;
    const int n0 = (wid >> 2) * 64;  // 0,64,128,192
    const int rl  = lane & 7;
    const int grp = lane >> 3;

    float acc[2][8][4];
#pragma unroll
    for (int mt = 0; mt < 2; mt++)
#pragma unroll
        for (int nt = 0; nt < 8; nt++)
#pragma unroll
            for (int j = 0; j < 4; j++) acc[mt][nt][j] = 0.f;

#pragma unroll
    for (int ks = 0; ks < 4; ks++) {
        const int cb = ks * 32;
        uint32_t ahi[2][4], alo[2][4];
#pragma unroll
        for (int mt = 0; mt < 2; mt++) {
            int arow = m0 + mt * 16 + (grp & 1) * 8 + rl;
            int abyte = cb + (grp >> 1) * 16;
            ldm_x4(ahi[mt], sb + SM3_AHI + swz_off(arow, abyte));
            ldm_x4(alo[mt], sb + SM3_ALO + swz_off(arow, abyte));
        }
#pragma unroll
        for (int np = 0; np < 4; np++) {
            int brow = n0 + np * 16 + (grp >> 1) * 8 + rl;
            int bbyte = cb + (grp & 1) * 16;
            uint32_t bhi[4], blo[4];
            ldm_x4(bhi, sb + SM3_BHI + swz_off(brow, bbyte));
            ldm_x4(blo, sb + SM3_BLO + swz_off(brow, bbyte));
            mma_bf16(acc[0][2 * np],     ahi[0], bhi[0], bhi[1]);
            mma_bf16(acc[1][2 * np],     ahi[1], bhi[0], bhi[1]);
            mma_bf16(acc[0][2 * np + 1], ahi[0], bhi[2], bhi[3]);
            mma_bf16(acc[1][2 * np + 1], ahi[1], bhi[2], bhi[3]);
            mma_bf16(acc[0][2 * np],     alo[0], bhi[0], bhi[1]);
            mma_bf16(acc[1][2 * np],     alo[1], bhi[0], bhi[1]);
            mma_bf16(acc[0][2 * np + 1], alo[0], bhi[2], bhi[3]);
            mma_bf16(acc[1][2 * np + 1], alo[1], bhi[2], bhi[3]);
            mma_bf16(acc[0][2 * np],     ahi[0], blo[0], blo[1]);
            mma_bf16(acc[1][2 * np],     ahi[1], blo[0], blo[1]);
            mma_bf16(acc[0][2 * np + 1], ahi[0], blo[2], blo[3]);
            mma_bf16(acc[1][2 * np + 1], ahi[1], blo[2], blo[3]);
        }
    }

    const int qr = lane >> 2, qc = (lane & 3) * 2;
#pragma unroll
    for (int mt = 0; mt < 2; mt++) {
#pragma unroll
        for (int nt = 0; nt < 8; nt++) {
            int col = n0 + nt * 8 + qc;
            int row0 = rowbase + m0 + mt * 16 + qr;
#pragma unroll
            for (int h = 0; h < 2; h++) {
                int row = row0 + h * 8;
                if (row < N) {
                    float vx = acc[mt][nt][2 * h], vy = acc[mt][nt][2 * h + 1];
                    if (col < 128) Y0h[row * 64 + (col >> 1)] = __floats2half2_rn(vx, vy);
                    else           *(float2*)&Y1[row * 128 + col - 128] = make_float2(vx, vy);
                }
            }
        }
    }
}

// ---------------------------------------------------------------------------
// Edge phase
// ---------------------------------------------------------------------------
__device__ __forceinline__ float leaky(float t) { return fmaxf(t, 0.2f * t); }

__device__ __forceinline__ float red8(float p) {
    p += __shfl_xor_sync(0xffffffffu, p, 4);
    p += __shfl_xor_sync(0xffffffffu, p, 2);
    p += __shfl_xor_sync(0xffffffffu, p, 1);
    return p;
}
__device__ __forceinline__ float red4(float p) {
    p += __shfl_xor_sync(0xffffffffu, p, 2);
    p += __shfl_xor_sync(0xffffffffu, p, 1);
    return p;
}
__device__ __forceinline__ float4 h2f4(uint2 u) {
    float2 lohalf = __half22float2(*(__half2*)&u.x);
    float2 hihalf = __half22float2(*(__half2*)&u.y);
    return make_float4(lohalf.x, lohalf.y, hihalf.x, hihalf.y);
}

// k_edge64: two nodes per warp (16 lanes each, 4 fp16 feats/lane), 4-edge
// pipeline, branchless lockstep, quad-merged online softmax. Output = ELU(..)
// written as pre-split bf16 hi/lo global images (swizzled GEMM layout).
__global__ void k_edge64(const __half2* __restrict__ XLH, const float* __restrict__ XR,
                         const float* __restrict__ att, const float* __restrict__ bias,
                         uint2* __restrict__ OHI, uint2* __restrict__ OLO, int N) {
    const int lane = threadIdx.x & 31;
    const int hl   = lane & 15;
    const int wg   = (blockIdx.x * blockDim.x + threadIdx.x) >> 5;
    const int n    = wg * 2 + (lane >> 4);
    const bool valid = n < N;
    const int nc = valid ? n : N - 1;

    const uint2* XL2 = (const uint2*)XLH;

    float4 a  = *(const float4*)&att[4 * hl];
    float4 xr = *(const float4*)&XR[nc * 64 + 4 * hl];
    float4 vs = h2f4(XL2[nc * 16 + hl]);

    auto score = [&](const float4& v) {
        return a.x * leaky(v.x + xr.x) + a.y * leaky(v.y + xr.y) +
               a.z * leaky(v.z + xr.z) + a.w * leaky(v.w + xr.w);
    };

    float m = red4(score(vs));
    float d = 1.f;
    float4 acc = vs;

    int beg = g_rowptr[nc];
    int end = valid ? g_rowptr[nc + 1] : beg;
    int cnt = end - beg;
    int ocnt = __shfl_xor_sync(0xffffffffu, cnt, 16);
    int nq = (max(cnt, ocnt) + 3) >> 2;

    int j = beg;
    int s0 = (j + 0 < end) ? g_adj[j + 0] : nc;
    int s1 = (j + 1 < end) ? g_adj[j + 1] : nc;
    int s2 = (j + 2 < end) ? g_adj[j + 2] : nc;
    int s3 = (j + 3 < end) ? g_adj[j + 3] : nc;

    for (int q = 0; q < nq; q++) {
        float4 v0 = h2f4(XL2[s0 * 16 + hl]);
        float4 v1 = h2f4(XL2[s1 * 16 + hl]);
        float4 v2 = h2f4(XL2[s2 * 16 + hl]);
        float4 v3 = h2f4(XL2[s3 * 16 + hl]);
        bool o0 = j + 0 < end, o1 = j + 1 < end, o2 = j + 2 < end, o3 = j + 3 < end;
        int jn = j + 4;
        s0 = (jn + 0 < end) ? g_adj[jn + 0] : nc;
        s1 = (jn + 1 < end) ? g_adj[jn + 1] : nc;
        s2 = (jn + 2 < end) ? g_adj[jn + 2] : nc;
        s3 = (jn + 3 < end) ? g_adj[jn + 3] : nc;
        j = jn;

        float p0 = red4(score(v0));
        float p1 = red4(score(v1));
        float p2 = red4(score(v2));
        float p3 = red4(score(v3));
        p0 = o0 ? p0 : -1e30f;
        p1 = o1 ? p1 : -1e30f;
        p2 = o2 ? p2 : -1e30f;
        p3 = o3 ? p3 : -1e30f;

        float mq = fmaxf(fmaxf(p0, p1), fmaxf(p2, p3));
        float mn = fmaxf(m, mq);
        float w  = __expf(m - mn);
        float e0 = __expf(p0 - mn), e1 = __expf(p1 - mn);
        float e2 = __expf(p2 - mn), e3 = __expf(p3 - mn);
        acc.x = acc.x * w + (e0 * v0.x + e1 * v1.x) + (e2 * v2.x + e3 * v3.x);
        acc.y = acc.y * w + (e0 * v0.y + e1 * v1.y) + (e2 * v2.y + e3 * v3.y);
        acc.z = acc.z * w + (e0 * v0.z + e1 * v1.z) + (e2 * v2.z + e3 * v3.z);
        acc.w = acc.w * w + (e0 * v0.w + e1 * v1.w) + (e2 * v2.w + e3 * v3.w);
        d = d * w + ((e0 + e1) + (e2 + e3));
        m = mn;
    }
    float inv = 1.f / d;
    float o0 = acc.x * inv + bias[4 * hl + 0];
    float o1 = acc.y * inv + bias[4 * hl + 1];
    float o2 = acc.z * inv + bias[4 * hl + 2];
    float o3 = acc.w * inv + bias[4 * hl + 3];
    o0 = o0 > 0.f ? o0 : (__expf(o0) - 1.f);
    o1 = o1 > 0.f ? o1 : (__expf(o1) - 1.f);
    o2 = o2 > 0.f ? o2 : (__expf(o2) - 1.f);
    o3 = o3 > 0.f ? o3 : (__expf(o3) - 1.f);
    if (valid) {
        uint16_t h0, l0, h1, l1, h2, l2, h3, l3;
        bf16_split(o0, h0, l0);
        bf16_split(o1, h1, l1);
        bf16_split(o2, h2, l2);
        bf16_split(o3, h3, l3);
        int idx = n * 16 + (hl ^ ((n & 7) << 1));   // swizzled 8B-unit offset
        OHI[idx] = make_uint2((uint32_t)h0 | ((uint32_t)h1 << 16),
                              (uint32_t)h2 | ((uint32_t)h3 << 16));
        OLO[idx] = make_uint2((uint32_t)l0 | ((uint32_t)l1 << 16),
                              (uint32_t)l2 | ((uint32_t)l3 << 16));
    }
}

__global__ void k_edge128_mean(const __half2* __restrict__ XLH, const float* __restrict__ XR,
                               const float* __restrict__ att, const float* __restrict__ bias,
                               float* __restrict__ OUT, int N) {
    int lane = threadIdx.x & 31;
    int n    = (blockIdx.x * blockDim.x + threadIdx.x) >> 5;
    if (n >= N) return;

    float4 a  = *(const float4*)&att[4 * lane];
    float4 xr = *(const float4*)&XR[n * 128 + 4 * lane];
    float4 vs = h2f4(*(const uint2*)&XLH[n * 64 + 2 * lane]);

    auto score = [&](const float4& v) {
        return a.x * leaky(v.x + xr.x) + a.y * leaky(v.y + xr.y) +
               a.z * leaky(v.z + xr.z) + a.w * leaky(v.w + xr.w);
    };

    float m = red8(score(vs));
    float d = 1.f;
    float4 acc = vs;

    int beg = g_rowptr[n], end = g_rowptr[n + 1];
    int i = beg;
    int s0 = 0, s1 = 0, s2 = 0, s3 = 0;
    if (i + 4 <= end) { s0 = g_adj[i]; s1 = g_adj[i+1]; s2 = g_adj[i+2]; s3 = g_adj[i+3]; }
    while (i + 4 <= end) {
        float4 v0 = h2f4(*(const uint2*)&XLH[s0 * 64 + 2 * lane]);
        float4 v1 = h2f4(*(const uint2*)&XLH[s1 * 64 + 2 * lane]);
        float4 v2 = h2f4(*(const uint2*)&XLH[s2 * 64 + 2 * lane]);
        float4 v3 = h2f4(*(const uint2*)&XLH[s3 * 64 + 2 * lane]);
        i += 4;
        if (i + 4 <= end) { s0 = g_adj[i]; s1 = g_adj[i+1]; s2 = g_adj[i+2]; s3 = g_adj[i+3]; }
        float p0 = score(v0), p1 = score(v1), p2 = score(v2), p3 = score(v3);
#pragma unroll
        for (int o = 4; o > 0; o >>= 1) {
            p0 += __shfl_xor_sync(0xffffffffu, p0, o);
            p1 += __shfl_xor_sync(0xffffffffu, p1, o);
            p2 += __shfl_xor_sync(0xffffffffu, p2, o);
            p3 += __shfl_xor_sync(0xffffffffu, p3, o);
        }
        float mq = fmaxf(fmaxf(p0, p1), fmaxf(p2, p3));
        float mn = fmaxf(m, mq);
        float w  = __expf(m - mn);
        float e0 = __expf(p0 - mn), e1 = __expf(p1 - mn);
        float e2 = __expf(p2 - mn), e3 = __expf(p3 - mn);
        acc.x = acc.x * w + (e0 * v0.x + e1 * v1.x) + (e2 * v2.x + e3 * v3.x);
        acc.y = acc.y * w + (e0 * v0.y + e1 * v1.y) + (e2 * v2.y + e3 * v3.y);
        acc.z = acc.z * w + (e0 * v0.z + e1 * v1.z) + (e2 * v2.z + e3 * v3.z);
        acc.w = acc.w * w + (e0 * v0.w + e1 * v1.w) + (e2 * v2.w + e3 * v3.w);
        d = d * w + ((e0 + e1) + (e2 + e3));
        m = mn;
    }
    for (; i < end; i++) {
        int s = g_adj[i];
        float4 v = h2f4(*(const uint2*)&XLH[s * 64 + 2 * lane]);
        float p = red8(score(v));
        float mn = fmaxf(m, p);
        float w  = __expf(m - mn);
        float e  = __expf(p - mn);
        acc.x = acc.x * w + e * v.x;
        acc.y = acc.y * w + e * v.y;
        acc.z = acc.z * w + e * v.z;
        acc.w = acc.w * w + e * v.w;
        d = d * w + e;
        m = mn;
    }
    float inv = 1.f / d;
    float o0 = acc.x * inv, o1 = acc.y * inv, o2 = acc.z * inv, o3 = acc.w * inv;
#pragma unroll
    for (int off = 8; off <= 16; off <<= 1) {
        o0 += __shfl_xor_sync(0xffffffffu, o0, off);
        o1 += __shfl_xor_sync(0xffffffffu, o1, off);
        o2 += __shfl_xor_sync(0xffffffffu, o2, off);
        o3 += __shfl_xor_sync(0xffffffffu, o3, off);
    }
    if (lane < 8) {
        int c = 4 * lane;
        float4 o = make_float4(0.25f * o0 + bias[c + 0],
                               0.25f * o1 + bias[c + 1],
                               0.25f * o2 + bias[c + 2],
                               0.25f * o3 + bias[c + 3]);
        *(float4*)&OUT[n * 32 + c] = o;
    }
}

// ---------------------------------------------------------------------------
// Launch (k_scatter at index 3 -> ncu capture target)
// ---------------------------------------------------------------------------
extern "C" void kernel_launch(void* const* d_in, const int* in_sizes, int n_in,
                              void* d_out, int out_size) {
    const float* x   = (const float*)d_in[0];
    const int*   ei  = (const int*)  d_in[1];
    const float* W1l = (const float*)d_in[2];
    const float* W1r = (const float*)d_in[3];
    const float* a1  = (const float*)d_in[4];
    const float* b1  = (const float*)d_in[5];
    const float* W2l = (const float*)d_in[6];
    const float* W2r = (const float*)d_in[7];
    const float* a2  = (const float*)d_in[8];
    const float* b2  = (const float*)d_in[9];
    const float* W3l = (const float*)d_in[10];
    const float* W3r = (const float*)d_in[11];
    const float* a3  = (const float*)d_in[12];
    const float* b3  = (const float*)d_in[13];
    float* out = (float*)d_out;

    const int N = in_sizes[0] / 64;
    const int E = in_sizes[1] / 2;
    const int NB = (N + 1023) / 1024;

    float *xlf, *xr;
    unsigned char *hhi, *hlo;
    unsigned char (*whi)[16384], (*wlo)[16384];
    cudaGetSymbolAddress((void**)&xlf, g_xl);
    cudaGetSymbolAddress((void**)&xr,  g_xr);
    cudaGetSymbolAddress((void**)&hhi, g_hhi);
    cudaGetSymbolAddress((void**)&hlo, g_hlo);
    cudaGetSymbolAddress((void**)&whi, g_wimg_hi);
    cudaGetSymbolAddress((void**)&wlo, g_wimg_lo);
    __half2* xlh = (__half2*)xlf;

    cudaFuncSetAttribute(k_mma<false>, cudaFuncAttributeMaxDynamicSharedMemorySize, SM_TOT);
    cudaFuncSetAttribute(k_mma<true>,  cudaFuncAttributeMaxDynamicSharedMemorySize, SM_TOT);
    cudaFuncSetAttribute(k_mma3, cudaFuncAttributeMaxDynamicSharedMemorySize, SM3_TOT);

    const int GT  = (N + 127) / 128;
    const int EB  = (N + 15) / 16;    // edge64: 8 warps x 2 nodes per block
    const int EBM = (N + 7) / 8;      // edge128: 8 warps x 1 node per block
    const int ZB  = (N + 255) / 256;

    // 0: init (zero cnt/bsum + W images)
    k_init<<<64 + ZB, 256>>>(W1l, W1r, W2l, W2r, W3l, W3r, N);
    // 1: layer-1 GEMM + histogram side-grid
    k_mma<false><<<GT + 1024, 256, SM_TOT>>>(x, nullptr, nullptr, whi[0], wlo[0],
                                             xlh, xr, N, ei, E, GT);
    // 2: fused decoupled-lookback scan
    k_scan<<<NB, 1024>>>(N, E);
    // 3: scatter (ncu capture target)
    k_scatter<<<1024, 256>>>(ei, E);
    // 4: layer-1 edge -> pre-split h images
    k_edge64<<<EB, 256>>>(xlh, xr, a1, b1, (uint2*)hhi, (uint2*)hlo, N);
    // 5: layer-2 GEMM (pre-split A)
    k_mma<true><<<GT, 256, SM_TOT>>>(nullptr, hhi, hlo, whi[1], wlo[1],
                                     xlh, xr, N, nullptr, 0, GT);
    // 6: layer-2 edge
    k_edge64<<<EB, 256>>>(xlh, xr, a2, b2, (uint2*)hhi, (uint2*)hlo, N);
    // 7: layer-3 fused dual-N GEMM (pre-split A)
    k_mma3<<<GT, 512, SM3_TOT>>>(hhi, hlo, whi[2], wlo[2], whi[3], wlo[3], xlh, xr, N);
    // 8: layer-3 edge (mean over heads) -> final output
    k_edge128_mean<<<EBM, 256>>>(xlh, xr, a3, b3, out, N);
}